// round 3
// baseline (speedup 1.0000x reference)
#include <cuda_runtime.h>
#include <cstdint>

// ---------------- problem constants ----------------
#define B32   32
#define NN    325      // s1 (GRU sequence length after reshape)
#define TT    12       // s2 (attention length)
#define DD    128
#define G3    384      // 3*D gates
#define BATCH 384      // B32*TT  (GRU batch)
#define MTOT  124800   // BATCH*NN rows
#define HH    8
#define HD    16

typedef unsigned long long u64;

// ---------------- scratch (device globals; no allocation allowed) ----------
__device__ float g_xw[(size_t)3 * MTOT * G3];  // input projections (incl. bih)
__device__ float g_ys[(size_t)3 * MTOT * DD];  // GRU outputs  [gru][i=b*12+t][j=n][d]
__device__ float g_ao[(size_t)MTOT * DD];      // attention out [b][n][t][d]

// ---------------- packed fp32x2 helpers (sm_100+) ----------------
__device__ __forceinline__ void fma2(u64& d, u64 a, u64 b) {
    asm("fma.rn.f32x2 %0, %1, %2, %0;" : "+l"(d) : "l"(a), "l"(b));
}
__device__ __forceinline__ u64 pk(float lo, float hi) {
    u64 r; asm("mov.b64 %0, {%1, %2};" : "=l"(r) : "f"(lo), "f"(hi)); return r;
}
__device__ __forceinline__ void upk(u64 v, float& lo, float& hi) {
    asm("mov.b64 {%0, %1}, %2;" : "=f"(lo), "=f"(hi) : "l"(v));
}
// 16B shared load -> two u64 packed-pair registers (no pack ALU ops)
__device__ __forceinline__ void lds_v2u64(u64& a, u64& b, unsigned addr) {
    asm volatile("ld.shared.v2.u64 {%0, %1}, [%2];" : "=l"(a), "=l"(b) : "r"(addr));
}
__device__ __forceinline__ unsigned smem_u32(const void* p) {
    return (unsigned)__cvta_generic_to_shared(p);
}

// ---------------- small helpers ----------------
__device__ __forceinline__ float sigmoidf_(float x) {
    return __fdividef(1.f, 1.f + __expf(-x));
}
__device__ __forceinline__ float tanhf_(float x) {
    return __fdividef(2.f, 1.f + __expf(-2.f * x)) - 1.f;
}

__device__ __forceinline__ void cp_async16(void* dst_smem, const void* src_gmem) {
    unsigned d = smem_u32(dst_smem);
    asm volatile("cp.async.cg.shared.global [%0], [%1], 16;" :: "r"(d), "l"(src_gmem) : "memory");
}
__device__ __forceinline__ void cp_commit() {
    asm volatile("cp.async.commit_group;" ::: "memory");
}

// ========================================================================
// GEMM: C[M, N] = A[M,128] @ W[N,128]^T + bias   (fp32, FFMA2)
// BM=128, BN=128, K=128 in smem (k-major), 256 threads, 8x8 per thread.
// acc packed over m-pairs; a-pairs via ld.shared.v2.u64; b dup'd via pk.
// asel: 0 -> A = Aext, 1 -> A = g_ao
// cslot: >=0 -> C = g_xw + slot*MTOT*G3 (ldc=384), -1 -> C = Cext (ldc=N)
// ========================================================================
#define TST 132   // smem tile stride (multiple of 4 -> 16B-aligned vec reads)

__global__ void __launch_bounds__(256)
gemm128(const float* __restrict__ Aext, int asel,
        const float* __restrict__ W, const float* __restrict__ bias,
        float* __restrict__ Cext, int cslot, int N)
{
    extern __shared__ float sm[];
    float* As = sm;                 // [k][m]  stride TST
    float* Bs = sm + 128 * TST;     // [k][n]  stride TST

    const float* A = asel ? g_ao : Aext;
    float* C = (cslot >= 0) ? (g_xw + (size_t)cslot * MTOT * G3) : Cext;

    int tid = threadIdx.x;
    int m0 = blockIdx.x * 128;
    int n0 = blockIdx.y * 128;

    // load A tile (128x128) transposed to k-major (coalesced gmem over k)
    for (int u = tid; u < 128 * 128; u += 256) {
        int r = u >> 7, c = u & 127;
        As[c * TST + r] = A[(size_t)(m0 + r) * 128 + c];
    }
    // load W tile (128 rows x 128) transposed to k-major
    for (int u = tid; u < 128 * 128; u += 256) {
        int g = u >> 7, c = u & 127;
        Bs[c * TST + g] = W[(size_t)(n0 + g) * 128 + c];
    }
    __syncthreads();

    int mt = (tid >> 4) * 8;     // 8 consecutive m per thread
    int nt = (tid & 15) * 4;     // cols nt..nt+3 and nt+64..nt+67

    u64 acc[4][8];               // [m-pair][col j]  j<4 -> nt+j, j>=4 -> nt+64+(j-4)
#pragma unroll
    for (int i = 0; i < 4; i++)
#pragma unroll
        for (int j = 0; j < 8; j++) acc[i][j] = 0ull;

    unsigned abase = smem_u32(As + mt);
    const float* Bp0 = Bs + nt;
    const float* Bp1 = Bs + nt + 64;

#pragma unroll 4
    for (int k = 0; k < 128; k++) {
        u64 a01, a23, a45, a67;
        lds_v2u64(a01, a23, abase + k * (TST * 4));
        lds_v2u64(a45, a67, abase + k * (TST * 4) + 16);
        float4 b0 = *(const float4*)(Bp0 + k * TST);
        float4 b1 = *(const float4*)(Bp1 + k * TST);
        float bv[8] = {b0.x, b0.y, b0.z, b0.w, b1.x, b1.y, b1.z, b1.w};
#pragma unroll
        for (int j = 0; j < 8; j++) {
            u64 bd = pk(bv[j], bv[j]);
            fma2(acc[0][j], a01, bd);
            fma2(acc[1][j], a23, bd);
            fma2(acc[2][j], a45, bd);
            fma2(acc[3][j], a67, bd);
        }
    }

    float4 bs0 = *(const float4*)(bias + n0 + nt);
    float4 bs1 = *(const float4*)(bias + n0 + 64 + nt);

#pragma unroll
    for (int mp = 0; mp < 4; mp++) {
        float lo[8], hi[8];
#pragma unroll
        for (int j = 0; j < 8; j++) upk(acc[mp][j], lo[j], hi[j]);
        size_t r0 = (size_t)(m0 + mt + 2 * mp) * N;
        float4 v;
        v.x = lo[0] + bs0.x; v.y = lo[1] + bs0.y; v.z = lo[2] + bs0.z; v.w = lo[3] + bs0.w;
        *(float4*)(C + r0 + n0 + nt) = v;
        v.x = lo[4] + bs1.x; v.y = lo[5] + bs1.y; v.z = lo[6] + bs1.z; v.w = lo[7] + bs1.w;
        *(float4*)(C + r0 + n0 + 64 + nt) = v;
        v.x = hi[0] + bs0.x; v.y = hi[1] + bs0.y; v.z = hi[2] + bs0.z; v.w = hi[3] + bs0.w;
        *(float4*)(C + r0 + N + n0 + nt) = v;
        v.x = hi[4] + bs1.x; v.y = hi[5] + bs1.y; v.z = hi[6] + bs1.z; v.w = hi[7] + bs1.w;
        *(float4*)(C + r0 + N + n0 + 64 + nt) = v;
    }
}

// ========================================================================
// GRU scan. One CTA = (gru, block of 8 batches), 325 sequential steps.
// 384 threads: thread g owns gate g. Inner matvec 4-d-wide: LDS.128 for
// both W (per-lane) and H (broadcast) via ld.shared.v2.u64, zero pack ops.
// ========================================================================
#define WST 132
#define WS_FLOATS (G3 * WST)          // 50688
#define HS_OFF    WS_FLOATS
#define XS_OFF    (WS_FLOATS + 1024)

__global__ void __launch_bounds__(384, 1)
gru_scan(const float* __restrict__ Whh_q, const float* __restrict__ Whh_k,
         const float* __restrict__ Whh_v,
         const float* __restrict__ bhh_q, const float* __restrict__ bhh_k,
         const float* __restrict__ bhh_v)
{
    extern __shared__ float sm[];
    float* Ws = sm;             // [g][d] stride WST
    float* Hs = sm + HS_OFF;    // [b][d]: 8*128
    float* Xs = sm + XS_OFF;    // 2*8*384 double buffer [stage][b][g]

    int gru = blockIdx.x / 48;
    int bb  = blockIdx.x % 48;
    int i0  = bb * 8;

    const float* Whh = (gru == 0) ? Whh_q : (gru == 1) ? Whh_k : Whh_v;
    const float* bhh = (gru == 0) ? bhh_q : (gru == 1) ? bhh_k : bhh_v;

    int g = threadIdx.x;

    // Whh -> Ws[g*WST + d] (coalesced gmem; conflict-free smem stores)
    for (int idx = g; idx < G3 * DD; idx += 384)
        Ws[(idx >> 7) * WST + (idx & 127)] = Whh[idx];
    for (int idx = g; idx < DD * 8; idx += 384) Hs[idx] = 0.f;

    float bhh_g = bhh[g];
    const size_t xwbase = (size_t)(gru * BATCH + i0) * NN * G3;

    // prefetch step 0 into stage 0
    {
#pragma unroll
        for (int w = 0; w < 2; w++) {
            int c = g + w * 384;           // 768 x 16B chunks
            int b = c / 96, q = c % 96;
            cp_async16(Xs + b * 384 + q * 4,
                       g_xw + xwbase + (size_t)b * (NN * G3) + q * 4);
        }
        cp_commit();
    }
    __syncthreads();

    int gate = g >> 7;       // 0=r 1=z 2=n
    int e    = g & 127;
    float xn[8], ghn[8];

    unsigned wbase = smem_u32(Ws + (size_t)g * WST);
    unsigned hbase = smem_u32(Hs);

    for (int j = 0; j < NN; j++) {
        int cur = j & 1;
        bool has_next = (j + 1 < NN);
        if (has_next) {
            float* dstb = Xs + ((j + 1) & 1) * 3072;
#pragma unroll
            for (int w = 0; w < 2; w++) {
                int c = g + w * 384;
                int b = c / 96, q = c % 96;
                cp_async16(dstb + b * 384 + q * 4,
                           g_xw + xwbase + (size_t)b * (NN * G3) + (size_t)(j + 1) * G3 + q * 4);
            }
            cp_commit();
        }

        // gh[g][b] = sum_d Whh[g][d] * h[b][d]   (4-d-wide, packed pairs)
        u64 acc2[8];
#pragma unroll
        for (int b = 0; b < 8; b++) acc2[b] = 0ull;
#pragma unroll 4
        for (int dq = 0; dq < 32; dq++) {
            u64 wlo, whi;
            lds_v2u64(wlo, whi, wbase + dq * 16);
#pragma unroll
            for (int b = 0; b < 8; b++) {
                u64 hlo, hhi;
                lds_v2u64(hlo, hhi, hbase + b * 512 + dq * 16);
                fma2(acc2[b], wlo, hlo);
                fma2(acc2[b], whi, hhi);
            }
        }
        float acc[8];
#pragma unroll
        for (int b = 0; b < 8; b++) {
            float lo, hi; upk(acc2[b], lo, hi);
            acc[b] = lo + hi;
        }

        if (has_next) asm volatile("cp.async.wait_group 1;" ::: "memory");
        else          asm volatile("cp.async.wait_group 0;" ::: "memory");
        __syncthreads();

        float* Xc = Xs + cur * 3072;
        if (gate < 2) {
            // r/z: overwrite consumed xw slot with activated gate value
#pragma unroll
            for (int b = 0; b < 8; b++) {
                float pre = Xc[b * 384 + g] + acc[b] + bhh_g;
                Xc[b * 384 + g] = sigmoidf_(pre);
            }
        } else {
#pragma unroll
            for (int b = 0; b < 8; b++) {
                xn[b]  = Xc[b * 384 + g];
                ghn[b] = acc[b] + bhh_g;
            }
        }
        __syncthreads();

        if (gate == 2) {
            float* yout = g_ys + ((size_t)(gru * BATCH + i0) * NN + j) * DD + e;
#pragma unroll
            for (int b = 0; b < 8; b++) {
                float r  = Xc[b * 384 + e];
                float z  = Xc[b * 384 + 128 + e];
                float nn = tanhf_(xn[b] + r * ghn[b]);
                float hp = Hs[b * 128 + e];
                float hnew = (1.f - z) * nn + z * hp;
                Hs[b * 128 + e] = hnew;
                yout[(size_t)b * (NN * DD)] = hnew;
            }
        }
        __syncthreads();
    }
}

// ========================================================================
// Attention: one block per (b, n); 96 threads = 8 heads x 12 t.
// Bias head index = (5*b + n) mod 8  (replica of scrambled reshape).
// ========================================================================
__global__ void __launch_bounds__(96)
attn_kernel(const float* __restrict__ rel)
{
    __shared__ float ks[TT * DD];
    __shared__ float vs[TT * DD];

    int b = blockIdx.x / NN;
    int n = blockIdx.x % NN;
    int tid = threadIdx.x;
    const size_t GS = (size_t)MTOT * DD;

    for (int u = tid; u < TT * DD / 4; u += 96) {
        int s = u >> 5, c4 = u & 31;
        size_t base = ((size_t)(b * TT + s) * NN + n) * DD + c4 * 4;
        ((float4*)ks)[u] = *(const float4*)(g_ys + GS + base);
        ((float4*)vs)[u] = *(const float4*)(g_ys + 2 * GS + base);
    }
    __syncthreads();

    int h = tid / TT, t = tid % TT;

    float q[HD];
    size_t qb = ((size_t)(b * TT + t) * NN + n) * DD + h * HD;
#pragma unroll
    for (int i = 0; i < 4; i++) ((float4*)q)[i] = *(const float4*)(g_ys + qb + i * 4);

    int hb = (5 * b + n) & 7;
    const float* rp = rel + hb * TT * TT + t * TT;

    float srow[TT];
#pragma unroll
    for (int s = 0; s < TT; s++) {
        float a = 0.f;
#pragma unroll
        for (int d = 0; d < HD; d++) a += q[d] * ks[s * DD + h * HD + d];
        srow[s] = a * 0.25f + __ldg(&rp[s]);
    }

    float m = srow[0];
#pragma unroll
    for (int s = 1; s < TT; s++) m = fmaxf(m, srow[s]);
    float sum = 0.f;
#pragma unroll
    for (int s = 0; s < TT; s++) { srow[s] = __expf(srow[s] - m); sum += srow[s]; }
    float inv = __fdividef(1.f, sum);

    float o[HD];
#pragma unroll
    for (int d = 0; d < HD; d++) o[d] = 0.f;
#pragma unroll
    for (int s = 0; s < TT; s++) {
        float p = srow[s] * inv;
#pragma unroll
        for (int d = 0; d < HD; d++) o[d] += p * vs[s * DD + h * HD + d];
    }

    size_t ob = ((size_t)(b * NN + n) * TT + t) * DD + h * HD;
#pragma unroll
    for (int i = 0; i < 4; i++) *(float4*)(g_ao + ob + i * 4) = ((float4*)o)[i];
}

// ========================================================================
extern "C" void kernel_launch(void* const* d_in, const int* in_sizes, int n_in,
                              void* d_out, int out_size)
{
    const float* query = (const float*)d_in[0];
    const float* key   = (const float*)d_in[1];
    const float* value = (const float*)d_in[2];
    const float* Wih_q = (const float*)d_in[3];
    const float* Whh_q = (const float*)d_in[4];
    const float* bih_q = (const float*)d_in[5];
    const float* bhh_q = (const float*)d_in[6];
    const float* Wih_k = (const float*)d_in[7];
    const float* Whh_k = (const float*)d_in[8];
    const float* bih_k = (const float*)d_in[9];
    const float* bhh_k = (const float*)d_in[10];
    const float* Wih_v = (const float*)d_in[11];
    const float* Whh_v = (const float*)d_in[12];
    const float* bih_v = (const float*)d_in[13];
    const float* bhh_v = (const float*)d_in[14];
    const float* rel   = (const float*)d_in[15];
    const float* Wout  = (const float*)d_in[16];
    const float* bout  = (const float*)d_in[17];

    const int gemm_smem = 2 * 128 * TST * 4;                           // 135,168 B
    const int scan_smem = (WS_FLOATS + 1024 + 2 * 8 * 384) * 4;        // 231,424 B
    cudaFuncSetAttribute(gemm128, cudaFuncAttributeMaxDynamicSharedMemorySize, gemm_smem);
    cudaFuncSetAttribute(gru_scan, cudaFuncAttributeMaxDynamicSharedMemorySize, scan_smem);

    // 1) input projections xw = X @ Wih^T + bih  (3 GRUs)
    gemm128<<<dim3(MTOT / 128, 3), 256, gemm_smem>>>(query, 0, Wih_q, bih_q, nullptr, 0, G3);
    gemm128<<<dim3(MTOT / 128, 3), 256, gemm_smem>>>(key,   0, Wih_k, bih_k, nullptr, 1, G3);
    gemm128<<<dim3(MTOT / 128, 3), 256, gemm_smem>>>(value, 0, Wih_v, bih_v, nullptr, 2, G3);

    // 2) sequential GRU scans (3 GRUs x 48 batch-blocks, independent)
    gru_scan<<<144, 384, scan_smem>>>(Whh_q, Whh_k, Whh_v, bhh_q, bhh_k, bhh_v);

    // 3) tiny attentions
    attn_kernel<<<B32 * NN, 96>>>(rel);

    // 4) output projection
    gemm128<<<dim3(MTOT / 128, 1), 256, gemm_smem>>>(nullptr, 1, Wout, bout,
                                                     (float*)d_out, -1, DD);
}

// round 4
// speedup vs baseline: 1.1408x; 1.1408x over previous
#include <cuda_runtime.h>
#include <cstdint>

// ---------------- problem constants ----------------
#define B32   32
#define NN    325      // s1 (GRU sequence length after reshape)
#define TT    12       // s2 (attention length)
#define DD    128
#define G3    384      // 3*D gates
#define BATCH 384      // B32*TT  (GRU batch)
#define MTOT  124800   // BATCH*NN rows
#define HH    8
#define HD    16

typedef unsigned long long u64;

// ---------------- scratch (device globals; no allocation allowed) ----------
__device__ float g_xw[(size_t)3 * MTOT * G3];  // input projections (incl. bih)
__device__ float g_ys[(size_t)3 * MTOT * DD];  // GRU outputs  [gru][i=b*12+t][j=n][d]
__device__ float g_ao[(size_t)MTOT * DD];      // attention out [b][n][t][d]

// ---------------- packed fp32x2 helpers (sm_100+) ----------------
__device__ __forceinline__ void fma2(u64& d, u64 a, u64 b) {
    asm("fma.rn.f32x2 %0, %1, %2, %0;" : "+l"(d) : "l"(a), "l"(b));
}
__device__ __forceinline__ u64 pk(float lo, float hi) {
    u64 r; asm("mov.b64 %0, {%1, %2};" : "=l"(r) : "f"(lo), "f"(hi)); return r;
}
__device__ __forceinline__ void upk(u64 v, float& lo, float& hi) {
    asm("mov.b64 {%0, %1}, %2;" : "=f"(lo), "=f"(hi) : "l"(v));
}
__device__ __forceinline__ void lds_v2u64(u64& a, u64& b, unsigned addr) {
    asm volatile("ld.shared.v2.u64 {%0, %1}, [%2];" : "=l"(a), "=l"(b) : "r"(addr));
}
__device__ __forceinline__ unsigned smem_u32(const void* p) {
    return (unsigned)__cvta_generic_to_shared(p);
}

// ---------------- small helpers ----------------
__device__ __forceinline__ float sigmoidf_(float x) {
    return __fdividef(1.f, 1.f + __expf(-x));
}
__device__ __forceinline__ float tanhf_(float x) {
    return __fdividef(2.f, 1.f + __expf(-2.f * x)) - 1.f;
}

__device__ __forceinline__ void cp_async16(void* dst_smem, const void* src_gmem) {
    unsigned d = smem_u32(dst_smem);
    asm volatile("cp.async.cg.shared.global [%0], [%1], 16;" :: "r"(d), "l"(src_gmem) : "memory");
}
__device__ __forceinline__ void cp_commit() {
    asm volatile("cp.async.commit_group;" ::: "memory");
}

// ========================================================================
// GEMM (R2 config — best measured): C[M,N] = A[M,128] @ W[N,128]^T + bias
// BM=64, BN=128, full K=128 in smem (k-major, padded strides), 256 thr.
// asel: 0 -> A = Aext, 1 -> A = g_ao
// cslot: >=0 -> C = g_xw + slot*MTOT*G3 (ldc=384), -1 -> C = Cext (ldc=N)
// ========================================================================
#define AST 66
#define BST 129

__global__ void __launch_bounds__(256)
gemm128(const float* __restrict__ Aext, int asel,
        const float* __restrict__ W, const float* __restrict__ bias,
        float* __restrict__ Cext, int cslot, int N)
{
    extern __shared__ float sm[];
    float* As = sm;                 // [128][AST]  k-major
    float* Bs = sm + 128 * AST;     // [128][BST]  k-major

    const float* A = asel ? g_ao : Aext;
    float* C = (cslot >= 0) ? (g_xw + (size_t)cslot * MTOT * G3) : Cext;

    int tid = threadIdx.x;
    int m0 = blockIdx.x * 64;
    int n0 = blockIdx.y * 128;

    for (int u = tid; u < 64 * 128; u += 256) {
        int r = u >> 7, c = u & 127;
        As[c * AST + r] = A[(size_t)(m0 + r) * 128 + c];
    }
    for (int u = tid; u < 128 * 128; u += 256) {
        int g = u >> 7, c = u & 127;
        Bs[c * BST + g] = W[(size_t)(n0 + g) * 128 + c];
    }
    __syncthreads();

    int nsub = tid & 15;
    int msub = tid >> 4;

    u64 acc[2][8];
#pragma unroll
    for (int i = 0; i < 2; i++)
#pragma unroll
        for (int j = 0; j < 8; j++) acc[i][j] = 0ull;

#pragma unroll 4
    for (int k = 0; k < 128; k++) {
        const u64* Ak = (const u64*)(As + k * AST + msub * 4);
        u64 ap0 = Ak[0];
        u64 ap1 = Ak[1];
        float b[8];
#pragma unroll
        for (int j = 0; j < 8; j++) b[j] = Bs[k * BST + nsub + 16 * j];
#pragma unroll
        for (int j = 0; j < 8; j++) {
            u64 bd = pk(b[j], b[j]);
            fma2(acc[0][j], ap0, bd);
            fma2(acc[1][j], ap1, bd);
        }
    }

#pragma unroll
    for (int i = 0; i < 2; i++) {
        size_t r0 = (size_t)(m0 + msub * 4 + 2 * i) * N;
#pragma unroll
        for (int j = 0; j < 8; j++) {
            int col = n0 + nsub + 16 * j;
            float lo, hi;
            upk(acc[i][j], lo, hi);
            float bv = __ldg(&bias[col]);
            C[r0 + col] = lo + bv;
            C[r0 + N + col] = hi + bv;
        }
    }
}

// ========================================================================
// GRU scan v4: 768 threads/CTA (24 warps for latency hiding).
// Lane pair (l, l^16) splits the 128-d dot of gate g = w*16 + (l&15):
//   hf = l>>4 owns d in [hf*64, hf*64+64). Reduce via shfl.xor 16.
// W: smem [g][d] stride 132 (per-lane LDS.128 hits 32 distinct 16B groups).
//   First 32 d of each half cached in 16 u64 REGISTERS (halves W traffic).
// H: smem [b][hf*68 + dd] (the two half-addresses of each broadcast LDS
//   land on disjoint bank quads -> 1 wavefront).
// ========================================================================
#define GST 132
#define WS_FLOATS (G3 * GST)          // 50688
#define HST 136                       // H batch stride (floats)
#define HS_OFF WS_FLOATS
#define XS_OFF (WS_FLOATS + 8 * HST)  // +1088

__global__ void __launch_bounds__(768, 1)
gru_scan(const float* __restrict__ Whh_q, const float* __restrict__ Whh_k,
         const float* __restrict__ Whh_v,
         const float* __restrict__ bhh_q, const float* __restrict__ bhh_k,
         const float* __restrict__ bhh_v)
{
    extern __shared__ float sm[];
    float* Ws = sm;             // [g][d] stride GST
    float* Hs = sm + HS_OFF;    // [b][hf*68+dd]: 8*HST
    float* Xs = sm + XS_OFF;    // 2*8*384 double buffer [stage][b][g]

    int gru = blockIdx.x / 48;
    int bb  = blockIdx.x % 48;
    int i0  = bb * 8;

    const float* Whh = (gru == 0) ? Whh_q : (gru == 1) ? Whh_k : Whh_v;
    const float* bhh = (gru == 0) ? bhh_q : (gru == 1) ? bhh_k : bhh_v;

    int tid = threadIdx.x;
    int w   = tid >> 5;
    int l   = tid & 31;
    int g   = w * 16 + (l & 15);   // gate 0..383
    int hf  = l >> 4;              // d-half
    int gate = g >> 7;             // 0=r 1=z 2=n
    int e    = g & 127;

    // Whh -> Ws[g*GST + d]
    for (int idx = tid; idx < G3 * DD; idx += 768)
        Ws[(idx >> 7) * GST + (idx & 127)] = Whh[idx];
    for (int idx = tid; idx < 8 * HST; idx += 768) Hs[idx] = 0.f;

    float bhh_g = bhh[g];
    const size_t xwbase = (size_t)(gru * BATCH + i0) * NN * G3;

    // prefetch step 0 into stage 0 (one 16B chunk per thread)
    {
        int b = tid / 96, q = tid % 96;
        cp_async16(Xs + b * 384 + q * 4,
                   g_xw + xwbase + (size_t)b * (NN * G3) + q * 4);
        cp_commit();
    }
    __syncthreads();

    // cache first 32 d of this thread's half in registers
    unsigned wbase = smem_u32(Ws + g * GST + hf * 64);
    u64 wreg[16];
#pragma unroll
    for (int dq = 0; dq < 8; dq++)
        lds_v2u64(wreg[2 * dq], wreg[2 * dq + 1], wbase + dq * 16);

    unsigned hbase = smem_u32(Hs) + hf * (68 * 4);

    for (int j = 0; j < NN; j++) {
        int cur = j & 1;
        bool has_next = (j + 1 < NN);
        if (has_next) {
            float* dstb = Xs + ((j + 1) & 1) * 3072;
            int b = tid / 96, q = tid % 96;
            cp_async16(dstb + b * 384 + q * 4,
                       g_xw + xwbase + (size_t)b * (NN * G3) + (size_t)(j + 1) * G3 + q * 4);
            cp_commit();
        }

        // partial gh over this thread's 64-d half
        u64 acc2[8];
#pragma unroll
        for (int b = 0; b < 8; b++) acc2[b] = 0ull;
#pragma unroll
        for (int dq = 0; dq < 8; dq++) {        // register W
            u64 wlo = wreg[2 * dq], whi = wreg[2 * dq + 1];
#pragma unroll
            for (int b = 0; b < 8; b++) {
                u64 hlo, hhi;
                lds_v2u64(hlo, hhi, hbase + b * (HST * 4) + dq * 16);
                fma2(acc2[b], wlo, hlo);
                fma2(acc2[b], whi, hhi);
            }
        }
#pragma unroll
        for (int dq = 8; dq < 16; dq++) {       // smem W
            u64 wlo, whi;
            lds_v2u64(wlo, whi, wbase + dq * 16);
#pragma unroll
            for (int b = 0; b < 8; b++) {
                u64 hlo, hhi;
                lds_v2u64(hlo, hhi, hbase + b * (HST * 4) + dq * 16);
                fma2(acc2[b], wlo, hlo);
                fma2(acc2[b], whi, hhi);
            }
        }

        // pair-sum + cross-half reduce (both halves end with the full gh)
        float full[8];
#pragma unroll
        for (int b = 0; b < 8; b++) {
            float lo, hi; upk(acc2[b], lo, hi);
            float s = lo + hi;
            full[b] = s + __shfl_xor_sync(0xffffffffu, s, 16);
        }

        if (has_next) asm volatile("cp.async.wait_group 1;" ::: "memory");
        else          asm volatile("cp.async.wait_group 0;" ::: "memory");
        __syncthreads();

        float* Xc = Xs + cur * 3072;
        if (gate < 2) {
            if (hf == 0) {
#pragma unroll
                for (int b = 0; b < 8; b++) {
                    float pre = Xc[b * 384 + g] + full[b] + bhh_g;
                    Xc[b * 384 + g] = sigmoidf_(pre);
                }
            }
        } else {
#pragma unroll
            for (int b = 0; b < 8; b++) full[b] += bhh_g;   // ghn, keep in regs
        }
        __syncthreads();

        if (gate == 2 && hf == 0) {
            float* yout = g_ys + ((size_t)(gru * BATCH + i0) * NN + j) * DD + e;
            int eoff = (e >> 6) * 68 + (e & 63);
#pragma unroll
            for (int b = 0; b < 8; b++) {
                float r  = Xc[b * 384 + e];
                float z  = Xc[b * 384 + 128 + e];
                float xn = Xc[b * 384 + 256 + e];
                float nn = tanhf_(xn + r * full[b]);
                float hp = Hs[b * HST + eoff];
                float hnew = (1.f - z) * nn + z * hp;
                Hs[b * HST + eoff] = hnew;
                yout[(size_t)b * (NN * DD)] = hnew;
            }
        }
        __syncthreads();
    }
}

// ========================================================================
// Attention: one block per (b, n); 96 threads = 8 heads x 12 t.
// Bias head index = (5*b + n) mod 8  (replica of scrambled reshape).
// ========================================================================
__global__ void __launch_bounds__(96)
attn_kernel(const float* __restrict__ rel)
{
    __shared__ float ks[TT * DD];
    __shared__ float vs[TT * DD];

    int b = blockIdx.x / NN;
    int n = blockIdx.x % NN;
    int tid = threadIdx.x;
    const size_t GS = (size_t)MTOT * DD;

    for (int u = tid; u < TT * DD / 4; u += 96) {
        int s = u >> 5, c4 = u & 31;
        size_t base = ((size_t)(b * TT + s) * NN + n) * DD + c4 * 4;
        ((float4*)ks)[u] = *(const float4*)(g_ys + GS + base);
        ((float4*)vs)[u] = *(const float4*)(g_ys + 2 * GS + base);
    }
    __syncthreads();

    int h = tid / TT, t = tid % TT;

    float q[HD];
    size_t qb = ((size_t)(b * TT + t) * NN + n) * DD + h * HD;
#pragma unroll
    for (int i = 0; i < 4; i++) ((float4*)q)[i] = *(const float4*)(g_ys + qb + i * 4);

    int hb = (5 * b + n) & 7;
    const float* rp = rel + hb * TT * TT + t * TT;

    float srow[TT];
#pragma unroll
    for (int s = 0; s < TT; s++) {
        float a = 0.f;
#pragma unroll
        for (int d = 0; d < HD; d++) a += q[d] * ks[s * DD + h * HD + d];
        srow[s] = a * 0.25f + __ldg(&rp[s]);
    }

    float m = srow[0];
#pragma unroll
    for (int s = 1; s < TT; s++) m = fmaxf(m, srow[s]);
    float sum = 0.f;
#pragma unroll
    for (int s = 0; s < TT; s++) { srow[s] = __expf(srow[s] - m); sum += srow[s]; }
    float inv = __fdividef(1.f, sum);

    float o[HD];
#pragma unroll
    for (int d = 0; d < HD; d++) o[d] = 0.f;
#pragma unroll
    for (int s = 0; s < TT; s++) {
        float p = srow[s] * inv;
#pragma unroll
        for (int d = 0; d < HD; d++) o[d] += p * vs[s * DD + h * HD + d];
    }

    size_t ob = ((size_t)(b * NN + n) * TT + t) * DD + h * HD;
#pragma unroll
    for (int i = 0; i < 4; i++) *(float4*)(g_ao + ob + i * 4) = ((float4*)o)[i];
}

// ========================================================================
extern "C" void kernel_launch(void* const* d_in, const int* in_sizes, int n_in,
                              void* d_out, int out_size)
{
    const float* query = (const float*)d_in[0];
    const float* key   = (const float*)d_in[1];
    const float* value = (const float*)d_in[2];
    const float* Wih_q = (const float*)d_in[3];
    const float* Whh_q = (const float*)d_in[4];
    const float* bih_q = (const float*)d_in[5];
    const float* bhh_q = (const float*)d_in[6];
    const float* Wih_k = (const float*)d_in[7];
    const float* Whh_k = (const float*)d_in[8];
    const float* bih_k = (const float*)d_in[9];
    const float* bhh_k = (const float*)d_in[10];
    const float* Wih_v = (const float*)d_in[11];
    const float* Whh_v = (const float*)d_in[12];
    const float* bih_v = (const float*)d_in[13];
    const float* bhh_v = (const float*)d_in[14];
    const float* rel   = (const float*)d_in[15];
    const float* Wout  = (const float*)d_in[16];
    const float* bout  = (const float*)d_in[17];

    const int gemm_smem = (128 * AST + 128 * BST) * 4;                 //  99,840 B
    const int scan_smem = (WS_FLOATS + 8 * HST + 2 * 8 * 384) * 4;     // 231,680 B
    cudaFuncSetAttribute(gemm128, cudaFuncAttributeMaxDynamicSharedMemorySize, gemm_smem);
    cudaFuncSetAttribute(gru_scan, cudaFuncAttributeMaxDynamicSharedMemorySize, scan_smem);

    // 1) input projections xw = X @ Wih^T + bih  (3 GRUs)
    gemm128<<<dim3(MTOT / 64, 3), 256, gemm_smem>>>(query, 0, Wih_q, bih_q, nullptr, 0, G3);
    gemm128<<<dim3(MTOT / 64, 3), 256, gemm_smem>>>(key,   0, Wih_k, bih_k, nullptr, 1, G3);
    gemm128<<<dim3(MTOT / 64, 3), 256, gemm_smem>>>(value, 0, Wih_v, bih_v, nullptr, 2, G3);

    // 2) sequential GRU scans (3 GRUs x 48 batch-blocks, independent)
    gru_scan<<<144, 768, scan_smem>>>(Whh_q, Whh_k, Whh_v, bhh_q, bhh_k, bhh_v);

    // 3) tiny attentions
    attn_kernel<<<B32 * NN, 96>>>(rel);

    // 4) output projection
    gemm128<<<dim3(MTOT / 64, 1), 256, gemm_smem>>>(nullptr, 1, Wout, bout,
                                                    (float*)d_out, -1, DD);
}

// round 6
// speedup vs baseline: 1.3813x; 1.2108x over previous
#include <cuda_runtime.h>
#include <cuda_bf16.h>
#include <cstdint>

// ---------------- problem constants ----------------
#define B32   32
#define NN    325
#define TT    12
#define DD    128
#define G3    384
#define BATCH 384
#define MTOT  124800
#define HH    8
#define HD    16

typedef unsigned long long u64;

// ---------------- scratch ----------
__device__ float g_xw[(size_t)3 * MTOT * G3];
__device__ float g_ys[(size_t)3 * MTOT * DD];
__device__ float g_ao[(size_t)MTOT * DD];

// ---------------- packed fp32x2 helpers ----------------
__device__ __forceinline__ void fma2(u64& d, u64 a, u64 b) {
    asm("fma.rn.f32x2 %0, %1, %2, %0;" : "+l"(d) : "l"(a), "l"(b));
}
__device__ __forceinline__ u64 pk(float lo, float hi) {
    u64 r; asm("mov.b64 %0, {%1, %2};" : "=l"(r) : "f"(lo), "f"(hi)); return r;
}
__device__ __forceinline__ void upk(u64 v, float& lo, float& hi) {
    asm("mov.b64 {%0, %1}, %2;" : "=f"(lo), "=f"(hi) : "l"(v));
}
__device__ __forceinline__ void lds_v2u64(u64& a, u64& b, unsigned addr) {
    asm volatile("ld.shared.v2.u64 {%0, %1}, [%2];" : "=l"(a), "=l"(b) : "r"(addr));
}
__device__ __forceinline__ unsigned smem_u32(const void* p) {
    return (unsigned)__cvta_generic_to_shared(p);
}

__device__ __forceinline__ float sigmoidf_(float x) {
    return __fdividef(1.f, 1.f + __expf(-x));
}
__device__ __forceinline__ float tanhf_(float x) {
    return __fdividef(2.f, 1.f + __expf(-2.f * x)) - 1.f;
}
__device__ __forceinline__ void cp_async16(void* dst_smem, const void* src_gmem) {
    unsigned d = smem_u32(dst_smem);
    asm volatile("cp.async.cg.shared.global [%0], [%1], 16;" :: "r"(d), "l"(src_gmem) : "memory");
}
__device__ __forceinline__ void cp_commit() {
    asm volatile("cp.async.commit_group;" ::: "memory");
}

// ---------------- warp-level tensor core helpers (sm_80+ path) ----------
__device__ __forceinline__ void ldsm4(uint32_t* r, unsigned a) {
    asm volatile("ldmatrix.sync.aligned.m8n8.x4.shared.b16 {%0,%1,%2,%3}, [%4];"
        : "=r"(r[0]), "=r"(r[1]), "=r"(r[2]), "=r"(r[3]) : "r"(a));
}
__device__ __forceinline__ void mma_bf16(float* c, const uint32_t* a, const uint32_t* b) {
    asm volatile("mma.sync.aligned.m16n8k16.row.col.f32.bf16.bf16.f32 "
        "{%0,%1,%2,%3}, {%4,%5,%6,%7}, {%8,%9}, {%0,%1,%2,%3};"
        : "+f"(c[0]), "+f"(c[1]), "+f"(c[2]), "+f"(c[3])
        : "r"(a[0]), "r"(a[1]), "r"(a[2]), "r"(a[3]), "r"(b[0]), "r"(b[1]));
}
// pack two fp32 -> bf16x2 (lower 16 = first arg)
__device__ __forceinline__ uint32_t bf16x2_pack(float lo, float hi) {
    uint32_t r;
    asm("cvt.rn.bf16x2.f32 %0, %2, %1;" : "=r"(r) : "f"(lo), "f"(hi));
    return r;
}

// ========================================================================
// Tensor-core input projection via mma.sync (bf16 3-pass float-split):
//   xw[gru] = X @ Wih^T + bih,  per block: 128 rows x 128 gates x K=128.
// smem: Ah/Al/Bh/Bl bf16 tiles, row stride 136 (272B, ldmatrix conflict-free).
// grid: (nblk=3, mblk=975, gru=3), 512 threads (16 warps, 32x32 each).
// ========================================================================
#define BSTRD 136                       // bf16 row stride
#define TILE_B (128 * BSTRD * 2)        // 34816 bytes per tile
#define GBF_SMEM (4 * TILE_B)           // 139264

__global__ void __launch_bounds__(512)
gemm_bf16(const float* __restrict__ Xq, const float* __restrict__ Xk, const float* __restrict__ Xv,
          const float* __restrict__ Wq, const float* __restrict__ Wk, const float* __restrict__ Wv,
          const float* __restrict__ bq, const float* __restrict__ bk, const float* __restrict__ bv)
{
    extern __shared__ char smc[];
    unsigned sAh = smem_u32(smc);
    unsigned sAl = sAh + TILE_B;
    unsigned sBh = sAh + 2 * TILE_B;
    unsigned sBl = sAh + 3 * TILE_B;
    uint32_t* Ah32 = (uint32_t*)smc;
    uint32_t* Al32 = (uint32_t*)(smc + TILE_B);
    uint32_t* Bh32 = (uint32_t*)(smc + 2 * TILE_B);
    uint32_t* Bl32 = (uint32_t*)(smc + 3 * TILE_B);

    int tid = threadIdx.x;
    int gru  = blockIdx.z;
    int nblk = blockIdx.x;
    int m0   = blockIdx.y * 128;
    int n0   = nblk * 128;

    const float* X = (gru == 0) ? Xq : (gru == 1) ? Xk : Xv;
    const float* W = (gru == 0) ? Wq : (gru == 1) ? Wk : Wv;
    const float* bias = (gru == 0) ? bq : (gru == 1) ? bk : bv;
    float* C = g_xw + (size_t)gru * MTOT * G3;

    // ---- load + split A (X rows) and B (W rows) into bf16 hi/lo tiles
    for (int u = tid; u < 128 * 32; u += 512) {
        int r = u >> 5, c4 = (u & 31) << 2;      // row, k0 (4 floats)
        int o = r * 68 + (c4 >> 1);              // u32 index (stride 136 bf16 = 68 u32)
        float4 f = *(const float4*)(X + (size_t)(m0 + r) * 128 + c4);
        float h0 = __bfloat162float(__float2bfloat16(f.x));
        float h1 = __bfloat162float(__float2bfloat16(f.y));
        float h2 = __bfloat162float(__float2bfloat16(f.z));
        float h3 = __bfloat162float(__float2bfloat16(f.w));
        Ah32[o]     = bf16x2_pack(h0, h1);
        Ah32[o + 1] = bf16x2_pack(h2, h3);
        Al32[o]     = bf16x2_pack(f.x - h0, f.y - h1);
        Al32[o + 1] = bf16x2_pack(f.z - h2, f.w - h3);

        float4 g = *(const float4*)(W + (size_t)(n0 + r) * 128 + c4);
        float g0 = __bfloat162float(__float2bfloat16(g.x));
        float g1 = __bfloat162float(__float2bfloat16(g.y));
        float g2 = __bfloat162float(__float2bfloat16(g.z));
        float g3 = __bfloat162float(__float2bfloat16(g.w));
        Bh32[o]     = bf16x2_pack(g0, g1);
        Bh32[o + 1] = bf16x2_pack(g2, g3);
        Bl32[o]     = bf16x2_pack(g.x - g0, g.y - g1);
        Bl32[o + 1] = bf16x2_pack(g.z - g2, g.w - g3);
    }
    __syncthreads();

    int wid = tid >> 5, lane = tid & 31;
    int m0w = (wid & 3) * 32;       // warp row base within tile
    int n0w = (wid >> 2) * 32;      // warp col base within tile

    // ldmatrix lane offsets (bytes)
    unsigned aoff[2], boff[2];
#pragma unroll
    for (int mt = 0; mt < 2; mt++)
        aoff[mt] = (m0w + mt * 16 + (lane & 15)) * 272 + ((lane >> 4) << 4);
#pragma unroll
    for (int np = 0; np < 2; np++)
        boff[np] = (n0w + np * 16 + ((lane >> 4) << 3) + (lane & 7)) * 272
                 + (((lane >> 3) & 1) << 4);

    float acc[2][4][4];
#pragma unroll
    for (int mt = 0; mt < 2; mt++)
#pragma unroll
        for (int nt = 0; nt < 4; nt++)
#pragma unroll
            for (int i = 0; i < 4; i++) acc[mt][nt][i] = 0.f;

#pragma unroll
    for (int pass = 0; pass < 3; pass++) {
        unsigned ab = (pass == 2) ? sAl : sAh;
        unsigned bb = (pass == 1) ? sBl : sBh;
#pragma unroll
        for (int ks = 0; ks < 8; ks++) {
            uint32_t a[2][4], b[2][4];
            ldsm4(a[0], ab + aoff[0] + ks * 32);
            ldsm4(a[1], ab + aoff[1] + ks * 32);
            ldsm4(b[0], bb + boff[0] + ks * 32);
            ldsm4(b[1], bb + boff[1] + ks * 32);
#pragma unroll
            for (int mt = 0; mt < 2; mt++) {
                mma_bf16(acc[mt][0], a[mt], &b[0][0]);
                mma_bf16(acc[mt][1], a[mt], &b[0][2]);
                mma_bf16(acc[mt][2], a[mt], &b[1][0]);
                mma_bf16(acc[mt][3], a[mt], &b[1][2]);
            }
        }
    }

    // ---- epilogue: c-frag rows l/4 (+8), cols 2*(l&3)
    int crow = lane >> 2;
    int ccol = (lane & 3) * 2;
#pragma unroll
    for (int mt = 0; mt < 2; mt++) {
        int row = m0 + m0w + mt * 16 + crow;
#pragma unroll
        for (int nt = 0; nt < 4; nt++) {
            int col = n0 + n0w + nt * 8 + ccol;
            float2 bv = *(const float2*)(bias + col);
            float2 v0 = make_float2(acc[mt][nt][0] + bv.x, acc[mt][nt][1] + bv.y);
            float2 v1 = make_float2(acc[mt][nt][2] + bv.x, acc[mt][nt][3] + bv.y);
            *(float2*)(C + (size_t)row * G3 + col) = v0;
            *(float2*)(C + (size_t)(row + 8) * G3 + col) = v1;
        }
    }
}

// ========================================================================
// fp32 FFMA2 GEMM (exact) — output projection only.
// ========================================================================
#define AST 66
#define BST 129

__global__ void __launch_bounds__(256)
gemm128(const float* __restrict__ W, const float* __restrict__ bias,
        float* __restrict__ Cext, int N)
{
    extern __shared__ float sm[];
    float* As = sm;
    float* Bs = sm + 128 * AST;

    const float* A = g_ao;
    float* C = Cext;

    int tid = threadIdx.x;
    int m0 = blockIdx.x * 64;
    int n0 = blockIdx.y * 128;

    for (int u = tid; u < 64 * 128; u += 256) {
        int r = u >> 7, c = u & 127;
        As[c * AST + r] = A[(size_t)(m0 + r) * 128 + c];
    }
    for (int u = tid; u < 128 * 128; u += 256) {
        int g = u >> 7, c = u & 127;
        Bs[c * BST + g] = W[(size_t)(n0 + g) * 128 + c];
    }
    __syncthreads();

    int nsub = tid & 15;
    int msub = tid >> 4;

    u64 acc[2][8];
#pragma unroll
    for (int i = 0; i < 2; i++)
#pragma unroll
        for (int j = 0; j < 8; j++) acc[i][j] = 0ull;

#pragma unroll 4
    for (int k = 0; k < 128; k++) {
        const u64* Ak = (const u64*)(As + k * AST + msub * 4);
        u64 ap0 = Ak[0];
        u64 ap1 = Ak[1];
        float b[8];
#pragma unroll
        for (int j = 0; j < 8; j++) b[j] = Bs[k * BST + nsub + 16 * j];
#pragma unroll
        for (int j = 0; j < 8; j++) {
            u64 bd = pk(b[j], b[j]);
            fma2(acc[0][j], ap0, bd);
            fma2(acc[1][j], ap1, bd);
        }
    }

#pragma unroll
    for (int i = 0; i < 2; i++) {
        size_t r0 = (size_t)(m0 + msub * 4 + 2 * i) * N;
#pragma unroll
        for (int j = 0; j < 8; j++) {
            int col = n0 + nsub + 16 * j;
            float lo, hi;
            upk(acc[i][j], lo, hi);
            float bv = __ldg(&bias[col]);
            C[r0 + col] = lo + bv;
            C[r0 + N + col] = hi + bv;
        }
    }
}

// ========================================================================
// GRU scan (R4 best): 768 threads, lane-pair d-split, W quarter in regs.
// ========================================================================
#define GST 132
#define WS_FLOATS (G3 * GST)
#define HST 136
#define HS_OFF WS_FLOATS
#define XS_OFF (WS_FLOATS + 8 * HST)

__global__ void __launch_bounds__(768, 1)
gru_scan(const float* __restrict__ Whh_q, const float* __restrict__ Whh_k,
         const float* __restrict__ Whh_v,
         const float* __restrict__ bhh_q, const float* __restrict__ bhh_k,
         const float* __restrict__ bhh_v)
{
    extern __shared__ float sm[];
    float* Ws = sm;
    float* Hs = sm + HS_OFF;
    float* Xs = sm + XS_OFF;

    int gru = blockIdx.x / 48;
    int bb  = blockIdx.x % 48;
    int i0  = bb * 8;

    const float* Whh = (gru == 0) ? Whh_q : (gru == 1) ? Whh_k : Whh_v;
    const float* bhh = (gru == 0) ? bhh_q : (gru == 1) ? bhh_k : bhh_v;

    int tid = threadIdx.x;
    int w   = tid >> 5;
    int l   = tid & 31;
    int g   = w * 16 + (l & 15);
    int hf  = l >> 4;
    int gate = g >> 7;
    int e    = g & 127;

    for (int idx = tid; idx < G3 * DD; idx += 768)
        Ws[(idx >> 7) * GST + (idx & 127)] = Whh[idx];
    for (int idx = tid; idx < 8 * HST; idx += 768) Hs[idx] = 0.f;

    float bhh_g = bhh[g];
    const size_t xwbase = (size_t)(gru * BATCH + i0) * NN * G3;

    {
        int b = tid / 96, q = tid % 96;
        cp_async16(Xs + b * 384 + q * 4,
                   g_xw + xwbase + (size_t)b * (NN * G3) + q * 4);
        cp_commit();
    }
    __syncthreads();

    unsigned wbase = smem_u32(Ws + g * GST + hf * 64);
    u64 wreg[16];
#pragma unroll
    for (int dq = 0; dq < 8; dq++)
        lds_v2u64(wreg[2 * dq], wreg[2 * dq + 1], wbase + dq * 16);

    unsigned hbase = smem_u32(Hs) + hf * (68 * 4);

    for (int j = 0; j < NN; j++) {
        int cur = j & 1;
        bool has_next = (j + 1 < NN);
        if (has_next) {
            float* dstb = Xs + ((j + 1) & 1) * 3072;
            int b = tid / 96, q = tid % 96;
            cp_async16(dstb + b * 384 + q * 4,
                       g_xw + xwbase + (size_t)b * (NN * G3) + (size_t)(j + 1) * G3 + q * 4);
            cp_commit();
        }

        u64 acc2[8];
#pragma unroll
        for (int b = 0; b < 8; b++) acc2[b] = 0ull;
#pragma unroll
        for (int dq = 0; dq < 8; dq++) {
            u64 wlo = wreg[2 * dq], whi = wreg[2 * dq + 1];
#pragma unroll
            for (int b = 0; b < 8; b++) {
                u64 hlo, hhi;
                lds_v2u64(hlo, hhi, hbase + b * (HST * 4) + dq * 16);
                fma2(acc2[b], wlo, hlo);
                fma2(acc2[b], whi, hhi);
            }
        }
#pragma unroll
        for (int dq = 8; dq < 16; dq++) {
            u64 wlo, whi;
            lds_v2u64(wlo, whi, wbase + dq * 16);
#pragma unroll
            for (int b = 0; b < 8; b++) {
                u64 hlo, hhi;
                lds_v2u64(hlo, hhi, hbase + b * (HST * 4) + dq * 16);
                fma2(acc2[b], wlo, hlo);
                fma2(acc2[b], whi, hhi);
            }
        }

        float full[8];
#pragma unroll
        for (int b = 0; b < 8; b++) {
            float lo, hi; upk(acc2[b], lo, hi);
            float s = lo + hi;
            full[b] = s + __shfl_xor_sync(0xffffffffu, s, 16);
        }

        if (has_next) asm volatile("cp.async.wait_group 1;" ::: "memory");
        else          asm volatile("cp.async.wait_group 0;" ::: "memory");
        __syncthreads();

        float* Xc = Xs + cur * 3072;
        if (gate < 2) {
            if (hf == 0) {
#pragma unroll
                for (int b = 0; b < 8; b++) {
                    float pre = Xc[b * 384 + g] + full[b] + bhh_g;
                    Xc[b * 384 + g] = sigmoidf_(pre);
                }
            }
        } else {
#pragma unroll
            for (int b = 0; b < 8; b++) full[b] += bhh_g;
        }
        __syncthreads();

        if (gate == 2 && hf == 0) {
            float* yout = g_ys + ((size_t)(gru * BATCH + i0) * NN + j) * DD + e;
            int eoff = (e >> 6) * 68 + (e & 63);
#pragma unroll
            for (int b = 0; b < 8; b++) {
                float r  = Xc[b * 384 + e];
                float z  = Xc[b * 384 + 128 + e];
                float xn = Xc[b * 384 + 256 + e];
                float nn = tanhf_(xn + r * full[b]);
                float hp = Hs[b * HST + eoff];
                float hnew = (1.f - z) * nn + z * hp;
                Hs[b * HST + eoff] = hnew;
                yout[(size_t)b * (NN * DD)] = hnew;
            }
        }
        __syncthreads();
    }
}

// ========================================================================
// Attention (unchanged)
// ========================================================================
__global__ void __launch_bounds__(96)
attn_kernel(const float* __restrict__ rel)
{
    __shared__ float ks[TT * DD];
    __shared__ float vs[TT * DD];

    int b = blockIdx.x / NN;
    int n = blockIdx.x % NN;
    int tid = threadIdx.x;
    const size_t GS = (size_t)MTOT * DD;

    for (int u = tid; u < TT * DD / 4; u += 96) {
        int s = u >> 5, c4 = u & 31;
        size_t base = ((size_t)(b * TT + s) * NN + n) * DD + c4 * 4;
        ((float4*)ks)[u] = *(const float4*)(g_ys + GS + base);
        ((float4*)vs)[u] = *(const float4*)(g_ys + 2 * GS + base);
    }
    __syncthreads();

    int h = tid / TT, t = tid % TT;

    float q[HD];
    size_t qb = ((size_t)(b * TT + t) * NN + n) * DD + h * HD;
#pragma unroll
    for (int i = 0; i < 4; i++) ((float4*)q)[i] = *(const float4*)(g_ys + qb + i * 4);

    int hb = (5 * b + n) & 7;
    const float* rp = rel + hb * TT * TT + t * TT;

    float srow[TT];
#pragma unroll
    for (int s = 0; s < TT; s++) {
        float a = 0.f;
#pragma unroll
        for (int d = 0; d < HD; d++) a += q[d] * ks[s * DD + h * HD + d];
        srow[s] = a * 0.25f + __ldg(&rp[s]);
    }

    float m = srow[0];
#pragma unroll
    for (int s = 1; s < TT; s++) m = fmaxf(m, srow[s]);
    float sum = 0.f;
#pragma unroll
    for (int s = 0; s < TT; s++) { srow[s] = __expf(srow[s] - m); sum += srow[s]; }
    float inv = __fdividef(1.f, sum);

    float o[HD];
#pragma unroll
    for (int d = 0; d < HD; d++) o[d] = 0.f;
#pragma unroll
    for (int s = 0; s < TT; s++) {
        float p = srow[s] * inv;
#pragma unroll
        for (int d = 0; d < HD; d++) o[d] += p * vs[s * DD + h * HD + d];
    }

    size_t ob = ((size_t)(b * NN + n) * TT + t) * DD + h * HD;
#pragma unroll
    for (int i = 0; i < 4; i++) *(float4*)(g_ao + ob + i * 4) = ((float4*)o)[i];
}

// ========================================================================
extern "C" void kernel_launch(void* const* d_in, const int* in_sizes, int n_in,
                              void* d_out, int out_size)
{
    const float* query = (const float*)d_in[0];
    const float* key   = (const float*)d_in[1];
    const float* value = (const float*)d_in[2];
    const float* Wih_q = (const float*)d_in[3];
    const float* Whh_q = (const float*)d_in[4];
    const float* bih_q = (const float*)d_in[5];
    const float* bhh_q = (const float*)d_in[6];
    const float* Wih_k = (const float*)d_in[7];
    const float* Whh_k = (const float*)d_in[8];
    const float* bih_k = (const float*)d_in[9];
    const float* bhh_k = (const float*)d_in[10];
    const float* Wih_v = (const float*)d_in[11];
    const float* Whh_v = (const float*)d_in[12];
    const float* bih_v = (const float*)d_in[13];
    const float* bhh_v = (const float*)d_in[14];
    const float* rel   = (const float*)d_in[15];
    const float* Wout  = (const float*)d_in[16];
    const float* bout  = (const float*)d_in[17];

    const int gemm_smem = (128 * AST + 128 * BST) * 4;
    const int scan_smem = (WS_FLOATS + 8 * HST + 2 * 8 * 384) * 4;
    cudaFuncSetAttribute(gemm_bf16, cudaFuncAttributeMaxDynamicSharedMemorySize, GBF_SMEM);
    cudaFuncSetAttribute(gemm128,   cudaFuncAttributeMaxDynamicSharedMemorySize, gemm_smem);
    cudaFuncSetAttribute(gru_scan,  cudaFuncAttributeMaxDynamicSharedMemorySize, scan_smem);

    // 1) input projections on tensor cores (mma.sync bf16, 3-pass split)
    gemm_bf16<<<dim3(3, MTOT / 128, 3), 512, GBF_SMEM>>>(query, key, value,
                                                         Wih_q, Wih_k, Wih_v,
                                                         bih_q, bih_k, bih_v);

    // 2) sequential GRU scans
    gru_scan<<<144, 768, scan_smem>>>(Whh_q, Whh_k, Whh_v, bhh_q, bhh_k, bhh_v);

    // 3) tiny attentions
    attn_kernel<<<B32 * NN, 96>>>(rel);

    // 4) output projection (fp32, exact)
    gemm128<<<dim3(MTOT / 64, 1), 256, gemm_smem>>>(Wout, bout, (float*)d_out, DD);
}

// round 7
// speedup vs baseline: 2.1952x; 1.5892x over previous
#include <cuda_runtime.h>
#include <cuda_bf16.h>
#include <cstdint>

// ---------------- problem constants ----------------
#define B32   32
#define NN    325
#define TT    12
#define DD    128
#define G3    384
#define BATCH 384
#define MTOT  124800
#define HH    8
#define HD    16

typedef unsigned long long u64;

// ---------------- scratch ----------
__device__ float g_xw[(size_t)3 * MTOT * G3];
__device__ float g_ys[(size_t)3 * MTOT * DD];
__device__ float g_ao[(size_t)MTOT * DD];

// ---------------- packed fp32x2 helpers ----------------
__device__ __forceinline__ void fma2(u64& d, u64 a, u64 b) {
    asm("fma.rn.f32x2 %0, %1, %2, %0;" : "+l"(d) : "l"(a), "l"(b));
}
__device__ __forceinline__ u64 pk(float lo, float hi) {
    u64 r; asm("mov.b64 %0, {%1, %2};" : "=l"(r) : "f"(lo), "f"(hi)); return r;
}
__device__ __forceinline__ void upk(u64 v, float& lo, float& hi) {
    asm("mov.b64 {%0, %1}, %2;" : "=f"(lo), "=f"(hi) : "l"(v));
}
__device__ __forceinline__ unsigned smem_u32(const void* p) {
    return (unsigned)__cvta_generic_to_shared(p);
}

__device__ __forceinline__ float sigmoidf_(float x) {
    return __fdividef(1.f, 1.f + __expf(-x));
}
__device__ __forceinline__ float tanhf_(float x) {
    return __fdividef(2.f, 1.f + __expf(-2.f * x)) - 1.f;
}
__device__ __forceinline__ void cp_async16(void* dst_smem, const void* src_gmem) {
    unsigned d = smem_u32(dst_smem);
    asm volatile("cp.async.cg.shared.global [%0], [%1], 16;" :: "r"(d), "l"(src_gmem) : "memory");
}
__device__ __forceinline__ void cp_commit() {
    asm volatile("cp.async.commit_group;" ::: "memory");
}

// ---------------- warp-level tensor core helpers ----------
__device__ __forceinline__ void ldsm4(uint32_t* r, unsigned a) {
    asm volatile("ldmatrix.sync.aligned.m8n8.x4.shared.b16 {%0,%1,%2,%3}, [%4];"
        : "=r"(r[0]), "=r"(r[1]), "=r"(r[2]), "=r"(r[3]) : "r"(a));
}
__device__ __forceinline__ void mma_bf16(float* c, const uint32_t* a, const uint32_t* b) {
    asm volatile("mma.sync.aligned.m16n8k16.row.col.f32.bf16.bf16.f32 "
        "{%0,%1,%2,%3}, {%4,%5,%6,%7}, {%8,%9}, {%0,%1,%2,%3};"
        : "+f"(c[0]), "+f"(c[1]), "+f"(c[2]), "+f"(c[3])
        : "r"(a[0]), "r"(a[1]), "r"(a[2]), "r"(a[3]), "r"(b[0]), "r"(b[1]));
}
__device__ __forceinline__ uint32_t bf16x2_pack(float lo, float hi) {
    uint32_t r;
    asm("cvt.rn.bf16x2.f32 %0, %2, %1;" : "=r"(r) : "f"(lo), "f"(hi));
    return r;
}

// ========================================================================
// Tensor-core input projection via mma.sync (R6, unchanged)
// ========================================================================
#define BSTRD 136
#define TILE_B (128 * BSTRD * 2)
#define GBF_SMEM (4 * TILE_B)

__global__ void __launch_bounds__(512)
gemm_bf16(const float* __restrict__ Xq, const float* __restrict__ Xk, const float* __restrict__ Xv,
          const float* __restrict__ Wq, const float* __restrict__ Wk, const float* __restrict__ Wv,
          const float* __restrict__ bq, const float* __restrict__ bk, const float* __restrict__ bv)
{
    extern __shared__ char smc[];
    unsigned sAh = smem_u32(smc);
    unsigned sAl = sAh + TILE_B;
    unsigned sBh = sAh + 2 * TILE_B;
    unsigned sBl = sAh + 3 * TILE_B;
    uint32_t* Ah32 = (uint32_t*)smc;
    uint32_t* Al32 = (uint32_t*)(smc + TILE_B);
    uint32_t* Bh32 = (uint32_t*)(smc + 2 * TILE_B);
    uint32_t* Bl32 = (uint32_t*)(smc + 3 * TILE_B);

    int tid = threadIdx.x;
    int gru  = blockIdx.z;
    int m0   = blockIdx.y * 128;
    int n0   = blockIdx.x * 128;

    const float* X = (gru == 0) ? Xq : (gru == 1) ? Xk : Xv;
    const float* W = (gru == 0) ? Wq : (gru == 1) ? Wk : Wv;
    const float* bias = (gru == 0) ? bq : (gru == 1) ? bk : bv;
    float* C = g_xw + (size_t)gru * MTOT * G3;

    for (int u = tid; u < 128 * 32; u += 512) {
        int r = u >> 5, c4 = (u & 31) << 2;
        int o = r * 68 + (c4 >> 1);
        float4 f = *(const float4*)(X + (size_t)(m0 + r) * 128 + c4);
        float h0 = __bfloat162float(__float2bfloat16(f.x));
        float h1 = __bfloat162float(__float2bfloat16(f.y));
        float h2 = __bfloat162float(__float2bfloat16(f.z));
        float h3 = __bfloat162float(__float2bfloat16(f.w));
        Ah32[o]     = bf16x2_pack(h0, h1);
        Ah32[o + 1] = bf16x2_pack(h2, h3);
        Al32[o]     = bf16x2_pack(f.x - h0, f.y - h1);
        Al32[o + 1] = bf16x2_pack(f.z - h2, f.w - h3);

        float4 g = *(const float4*)(W + (size_t)(n0 + r) * 128 + c4);
        float g0 = __bfloat162float(__float2bfloat16(g.x));
        float g1 = __bfloat162float(__float2bfloat16(g.y));
        float g2 = __bfloat162float(__float2bfloat16(g.z));
        float g3 = __bfloat162float(__float2bfloat16(g.w));
        Bh32[o]     = bf16x2_pack(g0, g1);
        Bh32[o + 1] = bf16x2_pack(g2, g3);
        Bl32[o]     = bf16x2_pack(g.x - g0, g.y - g1);
        Bl32[o + 1] = bf16x2_pack(g.z - g2, g.w - g3);
    }
    __syncthreads();

    int wid = tid >> 5, lane = tid & 31;
    int m0w = (wid & 3) * 32;
    int n0w = (wid >> 2) * 32;

    unsigned aoff[2], boff[2];
#pragma unroll
    for (int mt = 0; mt < 2; mt++)
        aoff[mt] = (m0w + mt * 16 + (lane & 15)) * 272 + ((lane >> 4) << 4);
#pragma unroll
    for (int np = 0; np < 2; np++)
        boff[np] = (n0w + np * 16 + ((lane >> 4) << 3) + (lane & 7)) * 272
                 + (((lane >> 3) & 1) << 4);

    float acc[2][4][4];
#pragma unroll
    for (int mt = 0; mt < 2; mt++)
#pragma unroll
        for (int nt = 0; nt < 4; nt++)
#pragma unroll
            for (int i = 0; i < 4; i++) acc[mt][nt][i] = 0.f;

#pragma unroll
    for (int pass = 0; pass < 3; pass++) {
        unsigned ab = (pass == 2) ? sAl : sAh;
        unsigned bb = (pass == 1) ? sBl : sBh;
#pragma unroll
        for (int ks = 0; ks < 8; ks++) {
            uint32_t a[2][4], b[2][4];
            ldsm4(a[0], ab + aoff[0] + ks * 32);
            ldsm4(a[1], ab + aoff[1] + ks * 32);
            ldsm4(b[0], bb + boff[0] + ks * 32);
            ldsm4(b[1], bb + boff[1] + ks * 32);
#pragma unroll
            for (int mt = 0; mt < 2; mt++) {
                mma_bf16(acc[mt][0], a[mt], &b[0][0]);
                mma_bf16(acc[mt][1], a[mt], &b[0][2]);
                mma_bf16(acc[mt][2], a[mt], &b[1][0]);
                mma_bf16(acc[mt][3], a[mt], &b[1][2]);
            }
        }
    }

    int crow = lane >> 2;
    int ccol = (lane & 3) * 2;
#pragma unroll
    for (int mt = 0; mt < 2; mt++) {
        int row = m0 + m0w + mt * 16 + crow;
#pragma unroll
        for (int nt = 0; nt < 4; nt++) {
            int col = n0 + n0w + nt * 8 + ccol;
            float2 bv = *(const float2*)(bias + col);
            float2 v0 = make_float2(acc[mt][nt][0] + bv.x, acc[mt][nt][1] + bv.y);
            float2 v1 = make_float2(acc[mt][nt][2] + bv.x, acc[mt][nt][3] + bv.y);
            *(float2*)(C + (size_t)row * G3 + col) = v0;
            *(float2*)(C + (size_t)(row + 8) * G3 + col) = v1;
        }
    }
}

// ========================================================================
// fp32 FFMA2 GEMM (exact) — output projection only.
// ========================================================================
#define AST 66
#define BST 129

__global__ void __launch_bounds__(256)
gemm128(const float* __restrict__ W, const float* __restrict__ bias,
        float* __restrict__ Cext, int N)
{
    extern __shared__ float sm[];
    float* As = sm;
    float* Bs = sm + 128 * AST;

    const float* A = g_ao;
    float* C = Cext;

    int tid = threadIdx.x;
    int m0 = blockIdx.x * 64;
    int n0 = blockIdx.y * 128;

    for (int u = tid; u < 64 * 128; u += 256) {
        int r = u >> 7, c = u & 127;
        As[c * AST + r] = A[(size_t)(m0 + r) * 128 + c];
    }
    for (int u = tid; u < 128 * 128; u += 256) {
        int g = u >> 7, c = u & 127;
        Bs[c * BST + g] = W[(size_t)(n0 + g) * 128 + c];
    }
    __syncthreads();

    int nsub = tid & 15;
    int msub = tid >> 4;

    u64 acc[2][8];
#pragma unroll
    for (int i = 0; i < 2; i++)
#pragma unroll
        for (int j = 0; j < 8; j++) acc[i][j] = 0ull;

#pragma unroll 4
    for (int k = 0; k < 128; k++) {
        const u64* Ak = (const u64*)(As + k * AST + msub * 4);
        u64 ap0 = Ak[0];
        u64 ap1 = Ak[1];
        float b[8];
#pragma unroll
        for (int j = 0; j < 8; j++) b[j] = Bs[k * BST + nsub + 16 * j];
#pragma unroll
        for (int j = 0; j < 8; j++) {
            u64 bd = pk(b[j], b[j]);
            fma2(acc[0][j], ap0, bd);
            fma2(acc[1][j], ap1, bd);
        }
    }

#pragma unroll
    for (int i = 0; i < 2; i++) {
        size_t r0 = (size_t)(m0 + msub * 4 + 2 * i) * N;
#pragma unroll
        for (int j = 0; j < 8; j++) {
            int col = n0 + nsub + 16 * j;
            float lo, hi;
            upk(acc[i][j], lo, hi);
            float bv = __ldg(&bias[col]);
            C[r0 + col] = lo + bv;
            C[r0 + N + col] = hi + bv;
        }
    }
}

// ========================================================================
// GRU scan v7 — tensor-core recurrence.
// gh[384 x 8] = Whh[384 x 128] @ h[8 x 128]^T  via mma.m16n8k16 bf16,
// 3-pass float split (Wh*hh + Wh*hl + Wl*hh).  12 warps: warp w owns
// gates [32w, 32w+32) as two m16 tiles; Wh a-frags pinned in registers.
// Epilogue: thread g (384 threads) computes gate g for 8 batches.
// ========================================================================
#define SC_WLB   (G3 * 136 * 2)            // 104448  Wl bf16 [384][136]
#define SC_HH    SC_WLB                    // hh bf16 [8][136]
#define SC_HL    (SC_HH + 8 * 136 * 2)     // hl bf16 [8][136]
#define SC_HS    (SC_HL + 8 * 136 * 2)     // h fp32  [8][136]
#define SC_GH    (SC_HS + 8 * 136 * 4)     // gh fp32 [384][8]
#define SC_XS    (SC_GH + G3 * 8 * 4)      // xw double buffer 2*8*384 fp32
#define SC_SMEM  (SC_XS + 2 * 8 * G3 * 4)  // 150016

__global__ void __launch_bounds__(384, 1)
gru_scan_tc(const float* __restrict__ Whh_q, const float* __restrict__ Whh_k,
            const float* __restrict__ Whh_v,
            const float* __restrict__ bhh_q, const float* __restrict__ bhh_k,
            const float* __restrict__ bhh_v)
{
    extern __shared__ char smc[];
    __nv_bfloat16* Wl  = (__nv_bfloat16*)smc;
    uint32_t*      Wl32 = (uint32_t*)smc;
    __nv_bfloat16* HHb = (__nv_bfloat16*)(smc + SC_HH);
    __nv_bfloat16* HLb = (__nv_bfloat16*)(smc + SC_HL);
    uint32_t*      HH32 = (uint32_t*)(smc + SC_HH);
    uint32_t*      HL32 = (uint32_t*)(smc + SC_HL);
    float*         Hs  = (float*)(smc + SC_HS);
    float*         gh_s = (float*)(smc + SC_GH);
    float*         Xs  = (float*)(smc + SC_XS);

    int gru = blockIdx.x / 48;
    int bb  = blockIdx.x % 48;
    int i0  = bb * 8;

    const float* Whh = (gru == 0) ? Whh_q : (gru == 1) ? Whh_k : Whh_v;
    const float* bhh = (gru == 0) ? bhh_q : (gru == 1) ? bhh_k : bhh_v;

    int tid = threadIdx.x;
    int wid = tid >> 5;
    int lane = tid & 31;
    int gate = tid >> 7;      // epilogue role: 0=r 1=z 2=n
    int e    = tid & 127;

    // ---- build Wl (bf16 residual) in smem, coalesced
    for (int idx = tid; idx < G3 * DD; idx += 384) {
        int g = idx >> 7, k = idx & 127;
        float w = Whh[idx];
        float wh = __bfloat162float(__float2bfloat16(w));
        Wl[g * 136 + k] = __float2bfloat16(w - wh);
    }
    for (int idx = tid; idx < 8 * 136; idx += 384) {
        HHb[idx] = __float2bfloat16(0.f);
        HLb[idx] = __float2bfloat16(0.f);
        Hs[idx] = 0.f;
    }

    // ---- Wh a-frags pinned in registers (gates [32*wid, +32), 8 k-tiles)
    uint32_t wh[2][8][4];
    {
        const float2* W2 = (const float2*)Whh;
        int rb = wid * 32 + (lane >> 2);
#pragma unroll
        for (int mt = 0; mt < 2; mt++) {
            int r0 = rb + mt * 16;
#pragma unroll
            for (int kt = 0; kt < 8; kt++) {
                int c = kt * 16 + (lane & 3) * 2;
                float2 w00 = W2[(r0 * 128 + c) >> 1];
                float2 w10 = W2[((r0 + 8) * 128 + c) >> 1];
                float2 w01 = W2[(r0 * 128 + c + 8) >> 1];
                float2 w11 = W2[((r0 + 8) * 128 + c + 8) >> 1];
                wh[mt][kt][0] = bf16x2_pack(w00.x, w00.y);
                wh[mt][kt][1] = bf16x2_pack(w10.x, w10.y);
                wh[mt][kt][2] = bf16x2_pack(w01.x, w01.y);
                wh[mt][kt][3] = bf16x2_pack(w11.x, w11.y);
            }
        }
    }

    float bhh_g = bhh[tid];
    const size_t xwbase = (size_t)(gru * BATCH + i0) * NN * G3;

    // prefetch step 0 (768 x 16B chunks, 2 per thread)
#pragma unroll
    for (int w2 = 0; w2 < 2; w2++) {
        int c = tid + w2 * 384;
        int b = c / 96, q = c % 96;
        cp_async16(Xs + b * 384 + q * 4,
                   g_xw + xwbase + (size_t)b * (NN * G3) + q * 4);
    }
    cp_commit();
    __syncthreads();

    float xn[8];

    for (int j = 0; j < NN; j++) {
        int cur = j & 1;
        bool has_next = (j + 1 < NN);
        if (has_next) {
            float* dstb = Xs + ((j + 1) & 1) * 3072;
#pragma unroll
            for (int w2 = 0; w2 < 2; w2++) {
                int c = tid + w2 * 384;
                int b = c / 96, q = c % 96;
                cp_async16(dstb + b * 384 + q * 4,
                           g_xw + xwbase + (size_t)b * (NN * G3) + (size_t)(j + 1) * G3 + q * 4);
            }
            cp_commit();
        }

        // ---- h b-frags (conflict-free LDS.32: banks 4b + c)
        int hb = (lane >> 2) * 68 + (lane & 3);
        uint32_t bh[8][2], bl[8][2];
#pragma unroll
        for (int kt = 0; kt < 8; kt++) {
            bh[kt][0] = HH32[hb + kt * 8];
            bh[kt][1] = HH32[hb + kt * 8 + 4];
            bl[kt][0] = HL32[hb + kt * 8];
            bl[kt][1] = HL32[hb + kt * 8 + 4];
        }

        float c_[2][4];
#pragma unroll
        for (int mt = 0; mt < 2; mt++)
#pragma unroll
            for (int i = 0; i < 4; i++) c_[mt][i] = 0.f;

        // pass 0: Wh * hh
#pragma unroll
        for (int kt = 0; kt < 8; kt++) {
            mma_bf16(c_[0], wh[0][kt], bh[kt]);
            mma_bf16(c_[1], wh[1][kt], bh[kt]);
        }
        // pass 1: Wh * hl
#pragma unroll
        for (int kt = 0; kt < 8; kt++) {
            mma_bf16(c_[0], wh[0][kt], bl[kt]);
            mma_bf16(c_[1], wh[1][kt], bl[kt]);
        }
        // pass 2: Wl * hh (a-frags from smem, conflict-free)
#pragma unroll
        for (int mt = 0; mt < 2; mt++) {
            int r0 = wid * 32 + mt * 16 + (lane >> 2);
#pragma unroll
            for (int kt = 0; kt < 8; kt++) {
                uint32_t wl[4];
                int base = r0 * 68 + kt * 8 + (lane & 3);
                wl[0] = Wl32[base];
                wl[1] = Wl32[base + 8 * 68];
                wl[2] = Wl32[base + 4];
                wl[3] = Wl32[base + 8 * 68 + 4];
                mma_bf16(c_[mt], wl, bh[kt]);
            }
        }

        // ---- store gh to smem [g][b] (stride 8)
#pragma unroll
        for (int mt = 0; mt < 2; mt++) {
            int gg = wid * 32 + mt * 16 + (lane >> 2);
            *(float2*)(gh_s + gg * 8 + (lane & 3) * 2) = make_float2(c_[mt][0], c_[mt][1]);
            *(float2*)(gh_s + (gg + 8) * 8 + (lane & 3) * 2) = make_float2(c_[mt][2], c_[mt][3]);
        }

        if (has_next) asm volatile("cp.async.wait_group 1;" ::: "memory");
        else          asm volatile("cp.async.wait_group 0;" ::: "memory");
        __syncthreads();

        // ---- gate epilogue: thread g = tid
        float4 ga = *(const float4*)(gh_s + tid * 8);
        float4 gb = *(const float4*)(gh_s + tid * 8 + 4);
        float ghv[8] = {ga.x + bhh_g, ga.y + bhh_g, ga.z + bhh_g, ga.w + bhh_g,
                        gb.x + bhh_g, gb.y + bhh_g, gb.z + bhh_g, gb.w + bhh_g};

        float* Xc = Xs + cur * 3072;
        if (gate < 2) {
#pragma unroll
            for (int b = 0; b < 8; b++) {
                float pre = Xc[b * 384 + tid] + ghv[b];
                Xc[b * 384 + tid] = sigmoidf_(pre);
            }
        } else {
#pragma unroll
            for (int b = 0; b < 8; b++) xn[b] = Xc[b * 384 + tid];
        }
        __syncthreads();

        if (gate == 2) {
            float* yout = g_ys + ((size_t)(gru * BATCH + i0) * NN + j) * DD + e;
#pragma unroll
            for (int b = 0; b < 8; b++) {
                float r  = Xc[b * 384 + e];
                float z  = Xc[b * 384 + 128 + e];
                float nn = tanhf_(xn[b] + r * ghv[b]);
                float hp = Hs[b * 136 + e];
                float hnew = (1.f - z) * nn + z * hp;
                Hs[b * 136 + e] = hnew;
                float hh = __bfloat162float(__float2bfloat16(hnew));
                HHb[b * 136 + e] = __float2bfloat16(hnew);
                HLb[b * 136 + e] = __float2bfloat16(hnew - hh);
                yout[(size_t)b * (NN * DD)] = hnew;
            }
        }
        __syncthreads();
    }
}

// ========================================================================
// Attention (unchanged)
// ========================================================================
__global__ void __launch_bounds__(96)
attn_kernel(const float* __restrict__ rel)
{
    __shared__ float ks[TT * DD];
    __shared__ float vs[TT * DD];

    int b = blockIdx.x / NN;
    int n = blockIdx.x % NN;
    int tid = threadIdx.x;
    const size_t GS = (size_t)MTOT * DD;

    for (int u = tid; u < TT * DD / 4; u += 96) {
        int s = u >> 5, c4 = u & 31;
        size_t base = ((size_t)(b * TT + s) * NN + n) * DD + c4 * 4;
        ((float4*)ks)[u] = *(const float4*)(g_ys + GS + base);
        ((float4*)vs)[u] = *(const float4*)(g_ys + 2 * GS + base);
    }
    __syncthreads();

    int h = tid / TT, t = tid % TT;

    float q[HD];
    size_t qb = ((size_t)(b * TT + t) * NN + n) * DD + h * HD;
#pragma unroll
    for (int i = 0; i < 4; i++) ((float4*)q)[i] = *(const float4*)(g_ys + qb + i * 4);

    int hb = (5 * b + n) & 7;
    const float* rp = rel + hb * TT * TT + t * TT;

    float srow[TT];
#pragma unroll
    for (int s = 0; s < TT; s++) {
        float a = 0.f;
#pragma unroll
        for (int d = 0; d < HD; d++) a += q[d] * ks[s * DD + h * HD + d];
        srow[s] = a * 0.25f + __ldg(&rp[s]);
    }

    float m = srow[0];
#pragma unroll
    for (int s = 1; s < TT; s++) m = fmaxf(m, srow[s]);
    float sum = 0.f;
#pragma unroll
    for (int s = 0; s < TT; s++) { srow[s] = __expf(srow[s] - m); sum += srow[s]; }
    float inv = __fdividef(1.f, sum);

    float o[HD];
#pragma unroll
    for (int d = 0; d < HD; d++) o[d] = 0.f;
#pragma unroll
    for (int s = 0; s < TT; s++) {
        float p = srow[s] * inv;
#pragma unroll
        for (int d = 0; d < HD; d++) o[d] += p * vs[s * DD + h * HD + d];
    }

    size_t ob = ((size_t)(b * NN + n) * TT + t) * DD + h * HD;
#pragma unroll
    for (int i = 0; i < 4; i++) *(float4*)(g_ao + ob + i * 4) = ((float4*)o)[i];
}

// ========================================================================
extern "C" void kernel_launch(void* const* d_in, const int* in_sizes, int n_in,
                              void* d_out, int out_size)
{
    const float* query = (const float*)d_in[0];
    const float* key   = (const float*)d_in[1];
    const float* value = (const float*)d_in[2];
    const float* Wih_q = (const float*)d_in[3];
    const float* Whh_q = (const float*)d_in[4];
    const float* bih_q = (const float*)d_in[5];
    const float* bhh_q = (const float*)d_in[6];
    const float* Wih_k = (const float*)d_in[7];
    const float* Whh_k = (const float*)d_in[8];
    const float* bih_k = (const float*)d_in[9];
    const float* bhh_k = (const float*)d_in[10];
    const float* Wih_v = (const float*)d_in[11];
    const float* Whh_v = (const float*)d_in[12];
    const float* bih_v = (const float*)d_in[13];
    const float* bhh_v = (const float*)d_in[14];
    const float* rel   = (const float*)d_in[15];
    const float* Wout  = (const float*)d_in[16];
    const float* bout  = (const float*)d_in[17];

    const int gemm_smem = (128 * AST + 128 * BST) * 4;
    cudaFuncSetAttribute(gemm_bf16,   cudaFuncAttributeMaxDynamicSharedMemorySize, GBF_SMEM);
    cudaFuncSetAttribute(gemm128,     cudaFuncAttributeMaxDynamicSharedMemorySize, gemm_smem);
    cudaFuncSetAttribute(gru_scan_tc, cudaFuncAttributeMaxDynamicSharedMemorySize, SC_SMEM);

    // 1) input projections on tensor cores (mma.sync bf16, 3-pass split)
    gemm_bf16<<<dim3(3, MTOT / 128, 3), 512, GBF_SMEM>>>(query, key, value,
                                                         Wih_q, Wih_k, Wih_v,
                                                         bih_q, bih_k, bih_v);

    // 2) sequential GRU scans — recurrence on tensor cores
    gru_scan_tc<<<144, 384, SC_SMEM>>>(Whh_q, Whh_k, Whh_v, bhh_q, bhh_k, bhh_v);

    // 3) tiny attentions
    attn_kernel<<<B32 * NN, 96>>>(rel);

    // 4) output projection (fp32, exact)
    gemm128<<<dim3(MTOT / 64, 1), 256, gemm_smem>>>(Wout, bout, (float*)d_out, DD);
}

// round 8
// speedup vs baseline: 2.3316x; 1.0622x over previous
#include <cuda_runtime.h>
#include <cuda_bf16.h>
#include <cstdint>

// ---------------- problem constants ----------------
#define B32   32
#define NN    325
#define TT    12
#define DD    128
#define G3    384
#define BATCH 384
#define MTOT  124800
#define HH    8
#define HD    16

// ---------------- scratch ----------
__device__ float g_xw[(size_t)3 * MTOT * G3];
__device__ float g_ys[(size_t)3 * MTOT * DD];
__device__ float g_ao[(size_t)MTOT * DD];

__device__ __forceinline__ unsigned smem_u32(const void* p) {
    return (unsigned)__cvta_generic_to_shared(p);
}
__device__ __forceinline__ float sigmoidf_(float x) {
    return __fdividef(1.f, 1.f + __expf(-x));
}
__device__ __forceinline__ float tanhf_(float x) {
    return __fdividef(2.f, 1.f + __expf(-2.f * x)) - 1.f;
}

// ---------------- warp-level tensor core helpers ----------
__device__ __forceinline__ void ldsm4(uint32_t* r, unsigned a) {
    asm volatile("ldmatrix.sync.aligned.m8n8.x4.shared.b16 {%0,%1,%2,%3}, [%4];"
        : "=r"(r[0]), "=r"(r[1]), "=r"(r[2]), "=r"(r[3]) : "r"(a));
}
__device__ __forceinline__ void mma_bf16(float* c, const uint32_t* a, const uint32_t* b) {
    asm volatile("mma.sync.aligned.m16n8k16.row.col.f32.bf16.bf16.f32 "
        "{%0,%1,%2,%3}, {%4,%5,%6,%7}, {%8,%9}, {%0,%1,%2,%3};"
        : "+f"(c[0]), "+f"(c[1]), "+f"(c[2]), "+f"(c[3])
        : "r"(a[0]), "r"(a[1]), "r"(a[2]), "r"(a[3]), "r"(b[0]), "r"(b[1]));
}
__device__ __forceinline__ uint32_t bf16x2_pack(float lo, float hi) {
    uint32_t r;
    asm("cvt.rn.bf16x2.f32 %0, %2, %1;" : "=r"(r) : "f"(lo), "f"(hi));
    return r;
}

// ========================================================================
// Tensor-core GEMM body (bf16 3-pass float-split), BM=128 x BN=128 x K=128.
// Used for the 3 input projections and the output projection.
// ========================================================================
#define BSTRD 136
#define TILE_B (128 * BSTRD * 2)
#define GBF_SMEM (4 * TILE_B)

__device__ __forceinline__ void gemm_tile_body(
    const float* __restrict__ A, size_t lda, int m0,
    const float* __restrict__ W, int n0,
    const float* __restrict__ bias,
    float* __restrict__ C, int ldc,
    char* smc)
{
    unsigned sAh = smem_u32(smc);
    unsigned sAl = sAh + TILE_B;
    unsigned sBh = sAh + 2 * TILE_B;
    unsigned sBl = sAh + 3 * TILE_B;
    uint32_t* Ah32 = (uint32_t*)smc;
    uint32_t* Al32 = (uint32_t*)(smc + TILE_B);
    uint32_t* Bh32 = (uint32_t*)(smc + 2 * TILE_B);
    uint32_t* Bl32 = (uint32_t*)(smc + 3 * TILE_B);

    int tid = threadIdx.x;

    for (int u = tid; u < 128 * 32; u += 512) {
        int r = u >> 5, c4 = (u & 31) << 2;
        int o = r * 68 + (c4 >> 1);
        float4 f = *(const float4*)(A + (size_t)(m0 + r) * lda + c4);
        float h0 = __bfloat162float(__float2bfloat16(f.x));
        float h1 = __bfloat162float(__float2bfloat16(f.y));
        float h2 = __bfloat162float(__float2bfloat16(f.z));
        float h3 = __bfloat162float(__float2bfloat16(f.w));
        Ah32[o]     = bf16x2_pack(h0, h1);
        Ah32[o + 1] = bf16x2_pack(h2, h3);
        Al32[o]     = bf16x2_pack(f.x - h0, f.y - h1);
        Al32[o + 1] = bf16x2_pack(f.z - h2, f.w - h3);

        float4 g = *(const float4*)(W + (size_t)(n0 + r) * 128 + c4);
        float g0 = __bfloat162float(__float2bfloat16(g.x));
        float g1 = __bfloat162float(__float2bfloat16(g.y));
        float g2 = __bfloat162float(__float2bfloat16(g.z));
        float g3 = __bfloat162float(__float2bfloat16(g.w));
        Bh32[o]     = bf16x2_pack(g0, g1);
        Bh32[o + 1] = bf16x2_pack(g2, g3);
        Bl32[o]     = bf16x2_pack(g.x - g0, g.y - g1);
        Bl32[o + 1] = bf16x2_pack(g.z - g2, g.w - g3);
    }
    __syncthreads();

    int wid = tid >> 5, lane = tid & 31;
    int m0w = (wid & 3) * 32;
    int n0w = (wid >> 2) * 32;

    unsigned aoff[2], boff[2];
#pragma unroll
    for (int mt = 0; mt < 2; mt++)
        aoff[mt] = (m0w + mt * 16 + (lane & 15)) * 272 + ((lane >> 4) << 4);
#pragma unroll
    for (int np = 0; np < 2; np++)
        boff[np] = (n0w + np * 16 + ((lane >> 4) << 3) + (lane & 7)) * 272
                 + (((lane >> 3) & 1) << 4);

    float acc[2][4][4];
#pragma unroll
    for (int mt = 0; mt < 2; mt++)
#pragma unroll
        for (int nt = 0; nt < 4; nt++)
#pragma unroll
            for (int i = 0; i < 4; i++) acc[mt][nt][i] = 0.f;

#pragma unroll
    for (int pass = 0; pass < 3; pass++) {
        unsigned ab = (pass == 2) ? sAl : sAh;
        unsigned bb = (pass == 1) ? sBl : sBh;
#pragma unroll
        for (int ks = 0; ks < 8; ks++) {
            uint32_t a[2][4], b[2][4];
            ldsm4(a[0], ab + aoff[0] + ks * 32);
            ldsm4(a[1], ab + aoff[1] + ks * 32);
            ldsm4(b[0], bb + boff[0] + ks * 32);
            ldsm4(b[1], bb + boff[1] + ks * 32);
#pragma unroll
            for (int mt = 0; mt < 2; mt++) {
                mma_bf16(acc[mt][0], a[mt], &b[0][0]);
                mma_bf16(acc[mt][1], a[mt], &b[0][2]);
                mma_bf16(acc[mt][2], a[mt], &b[1][0]);
                mma_bf16(acc[mt][3], a[mt], &b[1][2]);
            }
        }
    }

    int crow = lane >> 2;
    int ccol = (lane & 3) * 2;
#pragma unroll
    for (int mt = 0; mt < 2; mt++) {
        int row = m0 + m0w + mt * 16 + crow;
#pragma unroll
        for (int nt = 0; nt < 4; nt++) {
            int col = n0 + n0w + nt * 8 + ccol;
            float2 bv = *(const float2*)(bias + col);
            float2 v0 = make_float2(acc[mt][nt][0] + bv.x, acc[mt][nt][1] + bv.y);
            float2 v1 = make_float2(acc[mt][nt][2] + bv.x, acc[mt][nt][3] + bv.y);
            *(float2*)(C + (size_t)row * ldc + col) = v0;
            *(float2*)(C + (size_t)(row + 8) * ldc + col) = v1;
        }
    }
}

// input projections: grid (3 nblk, 975 mblk, 3 gru)
__global__ void __launch_bounds__(512)
gemm_bf16(const float* __restrict__ Xq, const float* __restrict__ Xk, const float* __restrict__ Xv,
          const float* __restrict__ Wq, const float* __restrict__ Wk, const float* __restrict__ Wv,
          const float* __restrict__ bq, const float* __restrict__ bk, const float* __restrict__ bv)
{
    extern __shared__ char smc[];
    int gru = blockIdx.z;
    const float* X = (gru == 0) ? Xq : (gru == 1) ? Xk : Xv;
    const float* W = (gru == 0) ? Wq : (gru == 1) ? Wk : Wv;
    const float* bias = (gru == 0) ? bq : (gru == 1) ? bk : bv;
    float* C = g_xw + (size_t)gru * MTOT * G3;
    gemm_tile_body(X, 128, blockIdx.y * 128, W, blockIdx.x * 128, bias, C, G3, smc);
}

// output projection: grid (975)
__global__ void __launch_bounds__(512)
gemm_out(const float* __restrict__ Wout, const float* __restrict__ bout,
         float* __restrict__ out)
{
    extern __shared__ char smc[];
    gemm_tile_body(g_ao, 128, blockIdx.x * 128, Wout, 0, bout, out, 128, smc);
}

// ========================================================================
// GRU scan v8 — tensor-core recurrence, register-streamed xw,
// 2 block syncs + 1 warpsync per step.
// ========================================================================
#define SC_WLB   (G3 * 136 * 2)            // Wl bf16 [384][136]
#define SC_HH    SC_WLB
#define SC_HL    (SC_HH + 8 * 136 * 2)
#define SC_HS    (SC_HL + 8 * 136 * 2)     // h fp32 [8][136]
#define SC_GH    (SC_HS + 8 * 136 * 4)     // gh fp32 [384][8]
#define SC_RZ    (SC_GH + G3 * 8 * 4)      // rz fp32 [8][264]
#define SC_SMEM  (SC_RZ + 8 * 264 * 4)     // 133,888 B

__global__ void __launch_bounds__(384, 1)
gru_scan_tc(const float* __restrict__ Whh_q, const float* __restrict__ Whh_k,
            const float* __restrict__ Whh_v,
            const float* __restrict__ bhh_q, const float* __restrict__ bhh_k,
            const float* __restrict__ bhh_v)
{
    extern __shared__ char smc[];
    __nv_bfloat16* Wl  = (__nv_bfloat16*)smc;
    uint32_t*      Wl32 = (uint32_t*)smc;
    __nv_bfloat16* HHb = (__nv_bfloat16*)(smc + SC_HH);
    __nv_bfloat16* HLb = (__nv_bfloat16*)(smc + SC_HL);
    uint32_t*      HH32 = (uint32_t*)(smc + SC_HH);
    uint32_t*      HL32 = (uint32_t*)(smc + SC_HL);
    float*         Hs  = (float*)(smc + SC_HS);
    float*         gh_s = (float*)(smc + SC_GH);
    float*         rz_s = (float*)(smc + SC_RZ);

    int gru = blockIdx.x / 48;
    int bb  = blockIdx.x % 48;
    int i0  = bb * 8;

    const float* Whh = (gru == 0) ? Whh_q : (gru == 1) ? Whh_k : Whh_v;
    const float* bhh = (gru == 0) ? bhh_q : (gru == 1) ? bhh_k : bhh_v;

    int tid = threadIdx.x;
    int wid = tid >> 5;
    int lane = tid & 31;
    int gate = tid >> 7;      // 0=r 1=z 2=n
    int e    = tid & 127;

    // Wl residual in smem
    for (int idx = tid; idx < G3 * DD; idx += 384) {
        int g = idx >> 7, k = idx & 127;
        float w = Whh[idx];
        float wh = __bfloat162float(__float2bfloat16(w));
        Wl[g * 136 + k] = __float2bfloat16(w - wh);
    }
    for (int idx = tid; idx < 8 * 136; idx += 384) {
        HHb[idx] = __float2bfloat16(0.f);
        HLb[idx] = __float2bfloat16(0.f);
        Hs[idx] = 0.f;
    }

    // Wh a-frags pinned in registers
    uint32_t wh[2][8][4];
    {
        const float2* W2 = (const float2*)Whh;
        int rb = wid * 32 + (lane >> 2);
#pragma unroll
        for (int mt = 0; mt < 2; mt++) {
            int r0 = rb + mt * 16;
#pragma unroll
            for (int kt = 0; kt < 8; kt++) {
                int c = kt * 16 + (lane & 3) * 2;
                float2 w00 = W2[(r0 * 128 + c) >> 1];
                float2 w10 = W2[((r0 + 8) * 128 + c) >> 1];
                float2 w01 = W2[(r0 * 128 + c + 8) >> 1];
                float2 w11 = W2[((r0 + 8) * 128 + c + 8) >> 1];
                wh[mt][kt][0] = bf16x2_pack(w00.x, w00.y);
                wh[mt][kt][1] = bf16x2_pack(w10.x, w10.y);
                wh[mt][kt][2] = bf16x2_pack(w01.x, w01.y);
                wh[mt][kt][3] = bf16x2_pack(w11.x, w11.y);
            }
        }
    }

    float bhh_g = bhh[tid];
    // xw column for this thread's gate: g_xw[gru][i0+b][j][tid]
    const float* xwp = g_xw + (size_t)(gru * BATCH + i0) * NN * G3 + tid;
    const size_t bstride = (size_t)NN * G3;

    // prefetch step 0 into registers (coalesced: consecutive tid -> consecutive addr)
    float xw_cur[8], xw_nxt[8];
#pragma unroll
    for (int b = 0; b < 8; b++) xw_cur[b] = __ldg(xwp + (size_t)b * bstride);

    __syncthreads();

    for (int j = 0; j < NN; j++) {
        bool has_next = (j + 1 < NN);
        if (has_next) {
            const float* xp = xwp + (size_t)(j + 1) * G3;
#pragma unroll
            for (int b = 0; b < 8; b++) xw_nxt[b] = __ldg(xp + (size_t)b * bstride);
        }

        // ---- h b-frags (conflict-free LDS.32)
        int hb = (lane >> 2) * 68 + (lane & 3);
        uint32_t bh[8][2], bl[8][2];
#pragma unroll
        for (int kt = 0; kt < 8; kt++) {
            bh[kt][0] = HH32[hb + kt * 8];
            bh[kt][1] = HH32[hb + kt * 8 + 4];
            bl[kt][0] = HL32[hb + kt * 8];
            bl[kt][1] = HL32[hb + kt * 8 + 4];
        }

        float c_[2][4];
#pragma unroll
        for (int mt = 0; mt < 2; mt++)
#pragma unroll
            for (int i = 0; i < 4; i++) c_[mt][i] = 0.f;

#pragma unroll
        for (int kt = 0; kt < 8; kt++) {      // pass 0: Wh * hh
            mma_bf16(c_[0], wh[0][kt], bh[kt]);
            mma_bf16(c_[1], wh[1][kt], bh[kt]);
        }
#pragma unroll
        for (int kt = 0; kt < 8; kt++) {      // pass 1: Wh * hl
            mma_bf16(c_[0], wh[0][kt], bl[kt]);
            mma_bf16(c_[1], wh[1][kt], bl[kt]);
        }
#pragma unroll
        for (int mt = 0; mt < 2; mt++) {      // pass 2: Wl * hh
            int r0 = wid * 32 + mt * 16 + (lane >> 2);
#pragma unroll
            for (int kt = 0; kt < 8; kt++) {
                uint32_t wl[4];
                int base = r0 * 68 + kt * 8 + (lane & 3);
                wl[0] = Wl32[base];
                wl[1] = Wl32[base + 8 * 68];
                wl[2] = Wl32[base + 4];
                wl[3] = Wl32[base + 8 * 68 + 4];
                mma_bf16(c_[mt], wl, bh[kt]);
            }
        }

        // ---- gh to warp-local smem (consumed by same warp)
#pragma unroll
        for (int mt = 0; mt < 2; mt++) {
            int gg = wid * 32 + mt * 16 + (lane >> 2);
            *(float2*)(gh_s + gg * 8 + (lane & 3) * 2) = make_float2(c_[mt][0], c_[mt][1]);
            *(float2*)(gh_s + (gg + 8) * 8 + (lane & 3) * 2) = make_float2(c_[mt][2], c_[mt][3]);
        }
        __syncwarp();

        float4 ga = *(const float4*)(gh_s + tid * 8);
        float4 gb = *(const float4*)(gh_s + tid * 8 + 4);
        float ghv[8] = {ga.x + bhh_g, ga.y + bhh_g, ga.z + bhh_g, ga.w + bhh_g,
                        gb.x + bhh_g, gb.y + bhh_g, gb.z + bhh_g, gb.w + bhh_g};

        if (gate < 2) {
#pragma unroll
            for (int b = 0; b < 8; b++)
                rz_s[b * 264 + gate * 132 + e] = sigmoidf_(xw_cur[b] + ghv[b]);
        }
        __syncthreads();

        if (gate == 2) {
            float* yout = g_ys + ((size_t)(gru * BATCH + i0) * NN + j) * DD + e;
#pragma unroll
            for (int b = 0; b < 8; b++) {
                float r  = rz_s[b * 264 + e];
                float z  = rz_s[b * 264 + 132 + e];
                float nn = tanhf_(xw_cur[b] + r * ghv[b]);
                float hp = Hs[b * 136 + e];
                float hnew = (1.f - z) * nn + z * hp;
                Hs[b * 136 + e] = hnew;
                float hhv = __bfloat162float(__float2bfloat16(hnew));
                HHb[b * 136 + e] = __float2bfloat16(hnew);
                HLb[b * 136 + e] = __float2bfloat16(hnew - hhv);
                yout[(size_t)b * (NN * DD)] = hnew;
            }
        }
        __syncthreads();

#pragma unroll
        for (int b = 0; b < 8; b++) xw_cur[b] = xw_nxt[b];
    }
}

// ========================================================================
// Attention (unchanged)
// ========================================================================
__global__ void __launch_bounds__(96)
attn_kernel(const float* __restrict__ rel)
{
    __shared__ float ks[TT * DD];
    __shared__ float vs[TT * DD];

    int b = blockIdx.x / NN;
    int n = blockIdx.x % NN;
    int tid = threadIdx.x;
    const size_t GS = (size_t)MTOT * DD;

    for (int u = tid; u < TT * DD / 4; u += 96) {
        int s = u >> 5, c4 = u & 31;
        size_t base = ((size_t)(b * TT + s) * NN + n) * DD + c4 * 4;
        ((float4*)ks)[u] = *(const float4*)(g_ys + GS + base);
        ((float4*)vs)[u] = *(const float4*)(g_ys + 2 * GS + base);
    }
    __syncthreads();

    int h = tid / TT, t = tid % TT;

    float q[HD];
    size_t qb = ((size_t)(b * TT + t) * NN + n) * DD + h * HD;
#pragma unroll
    for (int i = 0; i < 4; i++) ((float4*)q)[i] = *(const float4*)(g_ys + qb + i * 4);

    int hb = (5 * b + n) & 7;
    const float* rp = rel + hb * TT * TT + t * TT;

    float srow[TT];
#pragma unroll
    for (int s = 0; s < TT; s++) {
        float a = 0.f;
#pragma unroll
        for (int d = 0; d < HD; d++) a += q[d] * ks[s * DD + h * HD + d];
        srow[s] = a * 0.25f + __ldg(&rp[s]);
    }

    float m = srow[0];
#pragma unroll
    for (int s = 1; s < TT; s++) m = fmaxf(m, srow[s]);
    float sum = 0.f;
#pragma unroll
    for (int s = 0; s < TT; s++) { srow[s] = __expf(srow[s] - m); sum += srow[s]; }
    float inv = __fdividef(1.f, sum);

    float o[HD];
#pragma unroll
    for (int d = 0; d < HD; d++) o[d] = 0.f;
#pragma unroll
    for (int s = 0; s < TT; s++) {
        float p = srow[s] * inv;
#pragma unroll
        for (int d = 0; d < HD; d++) o[d] += p * vs[s * DD + h * HD + d];
    }

    size_t ob = ((size_t)(b * NN + n) * TT + t) * DD + h * HD;
#pragma unroll
    for (int i = 0; i < 4; i++) *(float4*)(g_ao + ob + i * 4) = ((float4*)o)[i];
}

// ========================================================================
extern "C" void kernel_launch(void* const* d_in, const int* in_sizes, int n_in,
                              void* d_out, int out_size)
{
    const float* query = (const float*)d_in[0];
    const float* key   = (const float*)d_in[1];
    const float* value = (const float*)d_in[2];
    const float* Wih_q = (const float*)d_in[3];
    const float* Whh_q = (const float*)d_in[4];
    const float* bih_q = (const float*)d_in[5];
    const float* bhh_q = (const float*)d_in[6];
    const float* Wih_k = (const float*)d_in[7];
    const float* Whh_k = (const float*)d_in[8];
    const float* bih_k = (const float*)d_in[9];
    const float* bhh_k = (const float*)d_in[10];
    const float* Wih_v = (const float*)d_in[11];
    const float* Whh_v = (const float*)d_in[12];
    const float* bih_v = (const float*)d_in[13];
    const float* bhh_v = (const float*)d_in[14];
    const float* rel   = (const float*)d_in[15];
    const float* Wout  = (const float*)d_in[16];
    const float* bout  = (const float*)d_in[17];

    cudaFuncSetAttribute(gemm_bf16,   cudaFuncAttributeMaxDynamicSharedMemorySize, GBF_SMEM);
    cudaFuncSetAttribute(gemm_out,    cudaFuncAttributeMaxDynamicSharedMemorySize, GBF_SMEM);
    cudaFuncSetAttribute(gru_scan_tc, cudaFuncAttributeMaxDynamicSharedMemorySize, SC_SMEM);

    // 1) input projections on tensor cores
    gemm_bf16<<<dim3(3, MTOT / 128, 3), 512, GBF_SMEM>>>(query, key, value,
                                                         Wih_q, Wih_k, Wih_v,
                                                         bih_q, bih_k, bih_v);

    // 2) GRU scans — recurrence on tensor cores
    gru_scan_tc<<<144, 384, SC_SMEM>>>(Whh_q, Whh_k, Whh_v, bhh_q, bhh_k, bhh_v);

    // 3) tiny attentions
    attn_kernel<<<B32 * NN, 96>>>(rel);

    // 4) output projection on tensor cores
    gemm_out<<<MTOT / 128, 512, GBF_SMEM>>>(Wout, bout, (float*)d_out);
}

// round 9
// speedup vs baseline: 2.4925x; 1.0690x over previous
#include <cuda_runtime.h>
#include <cuda_bf16.h>
#include <cstdint>

// ---------------- problem constants ----------------
#define B32   32
#define NN    325
#define TT    12
#define DD    128
#define G3    384
#define BATCH 384
#define MTOT  124800
#define HH    8
#define HD    16

// ---------------- scratch ----------
__device__ float g_xw[(size_t)3 * MTOT * G3];
__device__ float g_ys[(size_t)3 * MTOT * DD];
__device__ float g_ao[(size_t)MTOT * DD];

__device__ __forceinline__ unsigned smem_u32(const void* p) {
    return (unsigned)__cvta_generic_to_shared(p);
}
__device__ __forceinline__ float sigmoidf_(float x) {
    return __fdividef(1.f, 1.f + __expf(-x));
}
__device__ __forceinline__ float tanhf_(float x) {
    return __fdividef(2.f, 1.f + __expf(-2.f * x)) - 1.f;
}

// ---------------- warp-level tensor core helpers ----------
__device__ __forceinline__ void ldsm4(uint32_t* r, unsigned a) {
    asm volatile("ldmatrix.sync.aligned.m8n8.x4.shared.b16 {%0,%1,%2,%3}, [%4];"
        : "=r"(r[0]), "=r"(r[1]), "=r"(r[2]), "=r"(r[3]) : "r"(a));
}
__device__ __forceinline__ void mma_bf16(float* c, const uint32_t* a, const uint32_t* b) {
    asm volatile("mma.sync.aligned.m16n8k16.row.col.f32.bf16.bf16.f32 "
        "{%0,%1,%2,%3}, {%4,%5,%6,%7}, {%8,%9}, {%0,%1,%2,%3};"
        : "+f"(c[0]), "+f"(c[1]), "+f"(c[2]), "+f"(c[3])
        : "r"(a[0]), "r"(a[1]), "r"(a[2]), "r"(a[3]), "r"(b[0]), "r"(b[1]));
}
__device__ __forceinline__ uint32_t bf16x2_pack(float lo, float hi) {
    uint32_t r;
    asm("cvt.rn.bf16x2.f32 %0, %2, %1;" : "=r"(r) : "f"(lo), "f"(hi));
    return r;
}

#define BSTRD 136
#define TILE_B (128 * BSTRD * 2)       // 34816 bytes

// convert one 128x128 fp32 block into bf16 hi/lo tiles (stride 136)
__device__ __forceinline__ void convert_blk(const float* __restrict__ S, size_t lds,
                                            int r0, uint32_t* H32, uint32_t* L32,
                                            int nthr)
{
    int tid = threadIdx.x;
    for (int u = tid; u < 128 * 32; u += nthr) {
        int r = u >> 5, c4 = (u & 31) << 2;
        int o = r * 68 + (c4 >> 1);
        float4 f = *(const float4*)(S + (size_t)(r0 + r) * lds + c4);
        float h0 = __bfloat162float(__float2bfloat16(f.x));
        float h1 = __bfloat162float(__float2bfloat16(f.y));
        float h2 = __bfloat162float(__float2bfloat16(f.z));
        float h3 = __bfloat162float(__float2bfloat16(f.w));
        H32[o]     = bf16x2_pack(h0, h1);
        H32[o + 1] = bf16x2_pack(h2, h3);
        L32[o]     = bf16x2_pack(f.x - h0, f.y - h1);
        L32[o + 1] = bf16x2_pack(f.z - h2, f.w - h3);
    }
}

// ========================================================================
// Input projections: one CTA = 128 rows x FULL N=384, K=128.
// A converted once; B double-buffered across the 3 n-tiles.
// smem: A hi/lo + B hi/lo x2 stages = 6 tiles = 208,896 B.
// ========================================================================
#define GIN_SMEM (6 * TILE_B)

__global__ void __launch_bounds__(512)
gemm_in(const float* __restrict__ Xq, const float* __restrict__ Xk, const float* __restrict__ Xv,
        const float* __restrict__ Wq, const float* __restrict__ Wk, const float* __restrict__ Wv,
        const float* __restrict__ bq, const float* __restrict__ bk, const float* __restrict__ bv)
{
    extern __shared__ char smc[];
    unsigned sA = smem_u32(smc);
    int gru = blockIdx.y;
    int m0  = blockIdx.x * 128;

    const float* X = (gru == 0) ? Xq : (gru == 1) ? Xk : Xv;
    const float* W = (gru == 0) ? Wq : (gru == 1) ? Wk : Wv;
    const float* bias = (gru == 0) ? bq : (gru == 1) ? bk : bv;
    float* C = g_xw + (size_t)gru * MTOT * G3;

    // A -> tiles 0(hi),1(lo);  B stage s -> tiles 2+2s(hi), 3+2s(lo)
    convert_blk(X, 128, m0, (uint32_t*)smc, (uint32_t*)(smc + TILE_B), 512);
    convert_blk(W, 128, 0, (uint32_t*)(smc + 2 * TILE_B), (uint32_t*)(smc + 3 * TILE_B), 512);
    __syncthreads();

    int tid = threadIdx.x;
    int wid = tid >> 5, lane = tid & 31;
    int m0w = (wid & 3) * 32;
    int n0w = (wid >> 2) * 32;

    unsigned aoffr[2], boffr[2];
#pragma unroll
    for (int mt = 0; mt < 2; mt++)
        aoffr[mt] = (m0w + mt * 16 + (lane & 15)) * 272 + ((lane >> 4) << 4);
#pragma unroll
    for (int np = 0; np < 2; np++)
        boffr[np] = (n0w + np * 16 + ((lane >> 4) << 3) + (lane & 7)) * 272
                  + (((lane >> 3) & 1) << 4);

    int crow = lane >> 2;
    int ccol = (lane & 3) * 2;

    for (int nt = 0; nt < 3; nt++) {
        unsigned sBh = sA + (2 + 2 * (nt & 1)) * TILE_B;
        unsigned sBl = sBh + TILE_B;

        float acc[2][4][4];
#pragma unroll
        for (int mt = 0; mt < 2; mt++)
#pragma unroll
            for (int q = 0; q < 4; q++)
#pragma unroll
                for (int i = 0; i < 4; i++) acc[mt][q][i] = 0.f;

#pragma unroll
        for (int pass = 0; pass < 3; pass++) {
            unsigned ab = (pass == 2) ? (sA + TILE_B) : sA;
            unsigned bb = (pass == 1) ? sBl : sBh;
#pragma unroll
            for (int ks = 0; ks < 8; ks++) {
                uint32_t a[2][4], b[2][4];
                ldsm4(a[0], ab + aoffr[0] + ks * 32);
                ldsm4(a[1], ab + aoffr[1] + ks * 32);
                ldsm4(b[0], bb + boffr[0] + ks * 32);
                ldsm4(b[1], bb + boffr[1] + ks * 32);
#pragma unroll
                for (int mt = 0; mt < 2; mt++) {
                    mma_bf16(acc[mt][0], a[mt], &b[0][0]);
                    mma_bf16(acc[mt][1], a[mt], &b[0][2]);
                    mma_bf16(acc[mt][2], a[mt], &b[1][0]);
                    mma_bf16(acc[mt][3], a[mt], &b[1][2]);
                }
            }
        }

        // epilogue for this n-tile
#pragma unroll
        for (int mt = 0; mt < 2; mt++) {
            int row = m0 + m0w + mt * 16 + crow;
#pragma unroll
            for (int q = 0; q < 4; q++) {
                int col = nt * 128 + n0w + q * 8 + ccol;
                float2 bv = *(const float2*)(bias + col);
                float2 v0 = make_float2(acc[mt][q][0] + bv.x, acc[mt][q][1] + bv.y);
                float2 v1 = make_float2(acc[mt][q][2] + bv.x, acc[mt][q][3] + bv.y);
                *(float2*)(C + (size_t)row * G3 + col) = v0;
                *(float2*)(C + (size_t)(row + 8) * G3 + col) = v1;
            }
        }

        // convert next B into the other stage
        if (nt < 2) {
            unsigned st = 2 + 2 * ((nt + 1) & 1);
            convert_blk(W, 128, (nt + 1) * 128,
                        (uint32_t*)(smc + st * TILE_B),
                        (uint32_t*)(smc + (st + 1) * TILE_B), 512);
        }
        __syncthreads();
    }
}

// ========================================================================
// Output projection (R8 single-tile body, measured 84us)
// ========================================================================
#define GBF_SMEM (4 * TILE_B)

__global__ void __launch_bounds__(512)
gemm_out(const float* __restrict__ Wout, const float* __restrict__ bout,
         float* __restrict__ out)
{
    extern __shared__ char smc[];
    unsigned sAh = smem_u32(smc);
    unsigned sAl = sAh + TILE_B;
    unsigned sBh = sAh + 2 * TILE_B;
    unsigned sBl = sAh + 3 * TILE_B;
    int m0 = blockIdx.x * 128;

    convert_blk(g_ao, 128, m0, (uint32_t*)smc, (uint32_t*)(smc + TILE_B), 512);
    convert_blk(Wout, 128, 0, (uint32_t*)(smc + 2 * TILE_B), (uint32_t*)(smc + 3 * TILE_B), 512);
    __syncthreads();

    int tid = threadIdx.x;
    int wid = tid >> 5, lane = tid & 31;
    int m0w = (wid & 3) * 32;
    int n0w = (wid >> 2) * 32;

    unsigned aoff[2], boff[2];
#pragma unroll
    for (int mt = 0; mt < 2; mt++)
        aoff[mt] = (m0w + mt * 16 + (lane & 15)) * 272 + ((lane >> 4) << 4);
#pragma unroll
    for (int np = 0; np < 2; np++)
        boff[np] = (n0w + np * 16 + ((lane >> 4) << 3) + (lane & 7)) * 272
                 + (((lane >> 3) & 1) << 4);

    float acc[2][4][4];
#pragma unroll
    for (int mt = 0; mt < 2; mt++)
#pragma unroll
        for (int q = 0; q < 4; q++)
#pragma unroll
            for (int i = 0; i < 4; i++) acc[mt][q][i] = 0.f;

#pragma unroll
    for (int pass = 0; pass < 3; pass++) {
        unsigned ab = (pass == 2) ? sAl : sAh;
        unsigned bb = (pass == 1) ? sBl : sBh;
#pragma unroll
        for (int ks = 0; ks < 8; ks++) {
            uint32_t a[2][4], b[2][4];
            ldsm4(a[0], ab + aoff[0] + ks * 32);
            ldsm4(a[1], ab + aoff[1] + ks * 32);
            ldsm4(b[0], bb + boff[0] + ks * 32);
            ldsm4(b[1], bb + boff[1] + ks * 32);
#pragma unroll
            for (int mt = 0; mt < 2; mt++) {
                mma_bf16(acc[mt][0], a[mt], &b[0][0]);
                mma_bf16(acc[mt][1], a[mt], &b[0][2]);
                mma_bf16(acc[mt][2], a[mt], &b[1][0]);
                mma_bf16(acc[mt][3], a[mt], &b[1][2]);
            }
        }
    }

    int crow = lane >> 2;
    int ccol = (lane & 3) * 2;
#pragma unroll
    for (int mt = 0; mt < 2; mt++) {
        int row = m0 + m0w + mt * 16 + crow;
#pragma unroll
        for (int q = 0; q < 4; q++) {
            int col = n0w + q * 8 + ccol;
            float2 bv = *(const float2*)(bout + col);
            float2 v0 = make_float2(acc[mt][q][0] + bv.x, acc[mt][q][1] + bv.y);
            float2 v1 = make_float2(acc[mt][q][2] + bv.x, acc[mt][q][3] + bv.y);
            *(float2*)(out + (size_t)row * 128 + col) = v0;
            *(float2*)(out + (size_t)(row + 8) * 128 + col) = v1;
        }
    }
}

// ========================================================================
// GRU scan v9 — tensor-core recurrence + balanced epilogue.
// ========================================================================
#define SC_WLB   (G3 * 136 * 2)
#define SC_HH    SC_WLB
#define SC_HL    (SC_HH + 8 * 136 * 2)
#define SC_HS    (SC_HL + 8 * 136 * 2)     // h fp32 [8][136]
#define SC_GH    (SC_HS + 8 * 136 * 4)     // gh fp32 [384][8]
#define SC_RZ    (SC_GH + G3 * 8 * 4)      // r,z fp32 [8][264]
#define SC_XN    (SC_RZ + 8 * 264 * 4)     // xn fp32 [8][132]
#define SC_GN    (SC_XN + 8 * 132 * 4)     // ghn fp32 [8][132]
#define SC_SMEM  (SC_GN + 8 * 132 * 4)     // 142,336 B

__global__ void __launch_bounds__(384, 1)
gru_scan_tc(const float* __restrict__ Whh_q, const float* __restrict__ Whh_k,
            const float* __restrict__ Whh_v,
            const float* __restrict__ bhh_q, const float* __restrict__ bhh_k,
            const float* __restrict__ bhh_v)
{
    extern __shared__ char smc[];
    __nv_bfloat16* Wl  = (__nv_bfloat16*)smc;
    uint32_t*      Wl32 = (uint32_t*)smc;
    __nv_bfloat16* HHb = (__nv_bfloat16*)(smc + SC_HH);
    __nv_bfloat16* HLb = (__nv_bfloat16*)(smc + SC_HL);
    uint32_t*      HH32 = (uint32_t*)(smc + SC_HH);
    uint32_t*      HL32 = (uint32_t*)(smc + SC_HL);
    float*         Hs   = (float*)(smc + SC_HS);
    float*         gh_s = (float*)(smc + SC_GH);
    float*         rz_s = (float*)(smc + SC_RZ);
    float*         xn_s = (float*)(smc + SC_XN);
    float*         gn_s = (float*)(smc + SC_GN);

    int gru = blockIdx.x / 48;
    int bb  = blockIdx.x % 48;
    int i0  = bb * 8;

    const float* Whh = (gru == 0) ? Whh_q : (gru == 1) ? Whh_k : Whh_v;
    const float* bhh = (gru == 0) ? bhh_q : (gru == 1) ? bhh_k : bhh_v;

    int tid = threadIdx.x;
    int wid = tid >> 5;
    int lane = tid & 31;
    int gate = tid >> 7;      // 0=r 1=z 2=n
    int e    = tid & 127;

    for (int idx = tid; idx < G3 * DD; idx += 384) {
        int g = idx >> 7, k = idx & 127;
        float w = Whh[idx];
        float wh = __bfloat162float(__float2bfloat16(w));
        Wl[g * 136 + k] = __float2bfloat16(w - wh);
    }
    for (int idx = tid; idx < 8 * 136; idx += 384) {
        HHb[idx] = __float2bfloat16(0.f);
        HLb[idx] = __float2bfloat16(0.f);
        Hs[idx] = 0.f;
    }

    // Wh a-frags pinned in registers
    uint32_t wh[2][8][4];
    {
        const float2* W2 = (const float2*)Whh;
        int rb = wid * 32 + (lane >> 2);
#pragma unroll
        for (int mt = 0; mt < 2; mt++) {
            int r0 = rb + mt * 16;
#pragma unroll
            for (int kt = 0; kt < 8; kt++) {
                int c = kt * 16 + (lane & 3) * 2;
                float2 w00 = W2[(r0 * 128 + c) >> 1];
                float2 w10 = W2[((r0 + 8) * 128 + c) >> 1];
                float2 w01 = W2[(r0 * 128 + c + 8) >> 1];
                float2 w11 = W2[((r0 + 8) * 128 + c + 8) >> 1];
                wh[mt][kt][0] = bf16x2_pack(w00.x, w00.y);
                wh[mt][kt][1] = bf16x2_pack(w10.x, w10.y);
                wh[mt][kt][2] = bf16x2_pack(w01.x, w01.y);
                wh[mt][kt][3] = bf16x2_pack(w11.x, w11.y);
            }
        }
    }

    float bhh_g = bhh[tid];
    const float* xwp = g_xw + (size_t)(gru * BATCH + i0) * NN * G3 + tid;
    const size_t bstride = (size_t)NN * G3;

    float xw_cur[8], xw_nxt[8];
#pragma unroll
    for (int b = 0; b < 8; b++) xw_cur[b] = __ldg(xwp + (size_t)b * bstride);

    __syncthreads();

    for (int j = 0; j < NN; j++) {
        bool has_next = (j + 1 < NN);
        if (has_next) {
            const float* xp = xwp + (size_t)(j + 1) * G3;
#pragma unroll
            for (int b = 0; b < 8; b++) xw_nxt[b] = __ldg(xp + (size_t)b * bstride);
        }

        int hb = (lane >> 2) * 68 + (lane & 3);
        uint32_t bh[8][2], bl[8][2];
#pragma unroll
        for (int kt = 0; kt < 8; kt++) {
            bh[kt][0] = HH32[hb + kt * 8];
            bh[kt][1] = HH32[hb + kt * 8 + 4];
            bl[kt][0] = HL32[hb + kt * 8];
            bl[kt][1] = HL32[hb + kt * 8 + 4];
        }

        float c_[2][4];
#pragma unroll
        for (int mt = 0; mt < 2; mt++)
#pragma unroll
            for (int i = 0; i < 4; i++) c_[mt][i] = 0.f;

#pragma unroll
        for (int kt = 0; kt < 8; kt++) {
            mma_bf16(c_[0], wh[0][kt], bh[kt]);
            mma_bf16(c_[1], wh[1][kt], bh[kt]);
        }
#pragma unroll
        for (int kt = 0; kt < 8; kt++) {
            mma_bf16(c_[0], wh[0][kt], bl[kt]);
            mma_bf16(c_[1], wh[1][kt], bl[kt]);
        }
#pragma unroll
        for (int mt = 0; mt < 2; mt++) {
            int r0 = wid * 32 + mt * 16 + (lane >> 2);
#pragma unroll
            for (int kt = 0; kt < 8; kt++) {
                uint32_t wl[4];
                int base = r0 * 68 + kt * 8 + (lane & 3);
                wl[0] = Wl32[base];
                wl[1] = Wl32[base + 8 * 68];
                wl[2] = Wl32[base + 4];
                wl[3] = Wl32[base + 8 * 68 + 4];
                mma_bf16(c_[mt], wl, bh[kt]);
            }
        }

#pragma unroll
        for (int mt = 0; mt < 2; mt++) {
            int gg = wid * 32 + mt * 16 + (lane >> 2);
            *(float2*)(gh_s + gg * 8 + (lane & 3) * 2) = make_float2(c_[mt][0], c_[mt][1]);
            *(float2*)(gh_s + (gg + 8) * 8 + (lane & 3) * 2) = make_float2(c_[mt][2], c_[mt][3]);
        }
        __syncwarp();

        float4 ga = *(const float4*)(gh_s + tid * 8);
        float4 gb = *(const float4*)(gh_s + tid * 8 + 4);
        float ghv[8] = {ga.x + bhh_g, ga.y + bhh_g, ga.z + bhh_g, ga.w + bhh_g,
                        gb.x + bhh_g, gb.y + bhh_g, gb.z + bhh_g, gb.w + bhh_g};

        if (gate < 2) {
#pragma unroll
            for (int b = 0; b < 8; b++)
                rz_s[b * 264 + gate * 132 + e] = sigmoidf_(xw_cur[b] + ghv[b]);
        } else {
#pragma unroll
            for (int b = 0; b < 8; b++) {
                xn_s[b * 132 + e] = xw_cur[b];
                gn_s[b * 132 + e] = ghv[b];
            }
        }
        __syncthreads();

        // balanced h-update: 1024 (b,e) pairs over 384 threads
        const size_t ybase = ((size_t)(gru * BATCH + i0) * NN + j) * DD;
#pragma unroll
        for (int pp = 0; pp < 3; pp++) {
            int p = tid + pp * 384;
            if (p < 1024) {
                int b = p >> 7, e2 = p & 127;
                float r   = rz_s[b * 264 + e2];
                float z   = rz_s[b * 264 + 132 + e2];
                float xn  = xn_s[b * 132 + e2];
                float ghn = gn_s[b * 132 + e2];
                float hp  = Hs[b * 136 + e2];
                float nn = tanhf_(xn + r * ghn);
                float hnew = (1.f - z) * nn + z * hp;
                Hs[b * 136 + e2] = hnew;
                float hhv = __bfloat162float(__float2bfloat16(hnew));
                HHb[b * 136 + e2] = __float2bfloat16(hnew);
                HLb[b * 136 + e2] = __float2bfloat16(hnew - hhv);
                g_ys[ybase + (size_t)b * (NN * DD) + e2] = hnew;
            }
        }
        __syncthreads();

#pragma unroll
        for (int b = 0; b < 8; b++) xw_cur[b] = xw_nxt[b];
    }
}

// ========================================================================
// Attention: 5 (b,n) pairs per block, 480 threads.
// Bias head index = (5*b + n) mod 8.
// ========================================================================
#define ATT_SMEM (5 * TT * DD * 2 * 4)   // 61,440 B

__global__ void __launch_bounds__(480)
attn_kernel(const float* __restrict__ rel)
{
    extern __shared__ float att_sm[];
    float* ks = att_sm;                // [5][TT*DD]
    float* vs = att_sm + 5 * TT * DD;

    int b  = blockIdx.x / 65;
    int nb = blockIdx.x % 65;
    int tid = threadIdx.x;
    const size_t GS = (size_t)MTOT * DD;

    for (int u = tid; u < 5 * TT * DD / 4; u += 480) {
        int sub = u / 384;
        int v = u - sub * 384;
        int s = v >> 5, c4 = v & 31;
        int n = nb * 5 + sub;
        size_t base = ((size_t)(b * TT + s) * NN + n) * DD + c4 * 4;
        ((float4*)ks)[u] = *(const float4*)(g_ys + GS + base);
        ((float4*)vs)[u] = *(const float4*)(g_ys + 2 * GS + base);
    }
    __syncthreads();

    int sub = tid / 96;
    int st  = tid % 96;
    int h = st / TT, t = st % TT;
    int n = nb * 5 + sub;
    const float* ksub = ks + sub * TT * DD;
    const float* vsub = vs + sub * TT * DD;

    float q[HD];
    size_t qb = ((size_t)(b * TT + t) * NN + n) * DD + h * HD;
#pragma unroll
    for (int i = 0; i < 4; i++) ((float4*)q)[i] = *(const float4*)(g_ys + qb + i * 4);

    int hbias = (5 * b + n) & 7;
    const float* rp = rel + hbias * TT * TT + t * TT;

    float srow[TT];
#pragma unroll
    for (int s = 0; s < TT; s++) {
        float a = 0.f;
#pragma unroll
        for (int d = 0; d < HD; d++) a += q[d] * ksub[s * DD + h * HD + d];
        srow[s] = a * 0.25f + __ldg(&rp[s]);
    }

    float m = srow[0];
#pragma unroll
    for (int s = 1; s < TT; s++) m = fmaxf(m, srow[s]);
    float sum = 0.f;
#pragma unroll
    for (int s = 0; s < TT; s++) { srow[s] = __expf(srow[s] - m); sum += srow[s]; }
    float inv = __fdividef(1.f, sum);

    float o[HD];
#pragma unroll
    for (int d = 0; d < HD; d++) o[d] = 0.f;
#pragma unroll
    for (int s = 0; s < TT; s++) {
        float p = srow[s] * inv;
#pragma unroll
        for (int d = 0; d < HD; d++) o[d] += p * vsub[s * DD + h * HD + d];
    }

    size_t ob = ((size_t)(b * NN + n) * TT + t) * DD + h * HD;
#pragma unroll
    for (int i = 0; i < 4; i++) *(float4*)(g_ao + ob + i * 4) = ((float4*)o)[i];
}

// ========================================================================
extern "C" void kernel_launch(void* const* d_in, const int* in_sizes, int n_in,
                              void* d_out, int out_size)
{
    const float* query = (const float*)d_in[0];
    const float* key   = (const float*)d_in[1];
    const float* value = (const float*)d_in[2];
    const float* Wih_q = (const float*)d_in[3];
    const float* Whh_q = (const float*)d_in[4];
    const float* bih_q = (const float*)d_in[5];
    const float* bhh_q = (const float*)d_in[6];
    const float* Wih_k = (const float*)d_in[7];
    const float* Whh_k = (const float*)d_in[8];
    const float* bih_k = (const float*)d_in[9];
    const float* bhh_k = (const float*)d_in[10];
    const float* Wih_v = (const float*)d_in[11];
    const float* Whh_v = (const float*)d_in[12];
    const float* bih_v = (const float*)d_in[13];
    const float* bhh_v = (const float*)d_in[14];
    const float* rel   = (const float*)d_in[15];
    const float* Wout  = (const float*)d_in[16];
    const float* bout  = (const float*)d_in[17];

    cudaFuncSetAttribute(gemm_in,     cudaFuncAttributeMaxDynamicSharedMemorySize, GIN_SMEM);
    cudaFuncSetAttribute(gemm_out,    cudaFuncAttributeMaxDynamicSharedMemorySize, GBF_SMEM);
    cudaFuncSetAttribute(gru_scan_tc, cudaFuncAttributeMaxDynamicSharedMemorySize, SC_SMEM);
    cudaFuncSetAttribute(attn_kernel, cudaFuncAttributeMaxDynamicSharedMemorySize, ATT_SMEM);

    // 1) input projections (full-N per CTA, double-buffered B)
    gemm_in<<<dim3(MTOT / 128, 3), 512, GIN_SMEM>>>(query, key, value,
                                                    Wih_q, Wih_k, Wih_v,
                                                    bih_q, bih_k, bih_v);

    // 2) GRU scans — recurrence on tensor cores
    gru_scan_tc<<<144, 384, SC_SMEM>>>(Whh_q, Whh_k, Whh_v, bhh_q, bhh_k, bhh_v);

    // 3) attentions (5 per block)
    attn_kernel<<<B32 * 65, 480, ATT_SMEM>>>(rel);

    // 4) output projection
    gemm_out<<<MTOT / 128, 512, GBF_SMEM>>>(Wout, bout, (float*)d_out);
}

// round 10
// speedup vs baseline: 2.5609x; 1.0274x over previous
#include <cuda_runtime.h>
#include <cuda_bf16.h>
#include <cstdint>

// ---------------- problem constants ----------------
#define B32   32
#define NN    325
#define TT    12
#define DD    128
#define G3    384
#define BATCH 384
#define MTOT  124800
#define HH    8
#define HD    16

// ---------------- scratch ----------
__device__ float g_xw[(size_t)3 * MTOT * G3];
__device__ float g_ys[(size_t)3 * MTOT * DD];
__device__ float g_ao[(size_t)MTOT * DD];

__device__ __forceinline__ unsigned smem_u32(const void* p) {
    return (unsigned)__cvta_generic_to_shared(p);
}
__device__ __forceinline__ float sigmoidf_(float x) {
    return __fdividef(1.f, 1.f + __expf(-x));
}
__device__ __forceinline__ float tanhf_(float x) {
    return __fdividef(2.f, 1.f + __expf(-2.f * x)) - 1.f;
}

// ---------------- warp-level tensor core helpers ----------
__device__ __forceinline__ void ldsm4(uint32_t* r, unsigned a) {
    asm volatile("ldmatrix.sync.aligned.m8n8.x4.shared.b16 {%0,%1,%2,%3}, [%4];"
        : "=r"(r[0]), "=r"(r[1]), "=r"(r[2]), "=r"(r[3]) : "r"(a));
}
__device__ __forceinline__ void mma_bf16(float* c, const uint32_t* a, const uint32_t* b) {
    asm volatile("mma.sync.aligned.m16n8k16.row.col.f32.bf16.bf16.f32 "
        "{%0,%1,%2,%3}, {%4,%5,%6,%7}, {%8,%9}, {%0,%1,%2,%3};"
        : "+f"(c[0]), "+f"(c[1]), "+f"(c[2]), "+f"(c[3])
        : "r"(a[0]), "r"(a[1]), "r"(a[2]), "r"(a[3]), "r"(b[0]), "r"(b[1]));
}
__device__ __forceinline__ uint32_t bf16x2_pack(float lo, float hi) {
    uint32_t r;
    asm("cvt.rn.bf16x2.f32 %0, %2, %1;" : "=r"(r) : "f"(lo), "f"(hi));
    return r;
}

#define TILE_A64  (64 * 136 * 2)      // 17408 B
#define TILE_B128 (128 * 136 * 2)     // 34816 B

// convert `rows` x128 fp32 -> bf16 hi/lo tiles (stride 136)
__device__ __forceinline__ void convert_rows(const float* __restrict__ S, size_t lds,
                                             int r0, int rows,
                                             uint32_t* H32, uint32_t* L32, int nthr)
{
    int tid = threadIdx.x;
    for (int u = tid; u < rows * 32; u += nthr) {
        int r = u >> 5, c4 = (u & 31) << 2;
        int o = r * 68 + (c4 >> 1);
        float4 f = *(const float4*)(S + (size_t)(r0 + r) * lds + c4);
        float h0 = __bfloat162float(__float2bfloat16(f.x));
        float h1 = __bfloat162float(__float2bfloat16(f.y));
        float h2 = __bfloat162float(__float2bfloat16(f.z));
        float h3 = __bfloat162float(__float2bfloat16(f.w));
        H32[o]     = bf16x2_pack(h0, h1);
        H32[o + 1] = bf16x2_pack(h2, h3);
        L32[o]     = bf16x2_pack(f.x - h0, f.y - h1);
        L32[o + 1] = bf16x2_pack(f.z - h2, f.w - h3);
    }
}

// ========================================================================
// GEMM tile: 64 rows x 128 cols x K=128, 256 threads (8 warps, 32x32 each),
// bf16 3-pass split.  smem 104,448 B -> 2 CTAs/SM.
// ========================================================================
#define G64_SMEM (2 * TILE_A64 + 2 * TILE_B128)   // 104448

__device__ __forceinline__ void mma_tile_64(
    unsigned sA, unsigned sBh, unsigned sBl,
    int m0, int ncol0,
    const float* __restrict__ bias,
    float* __restrict__ C, int ldc)
{
    int tid = threadIdx.x;
    int wid = tid >> 5, lane = tid & 31;
    int m0w = (wid & 1) * 32;
    int n0w = (wid >> 1) * 32;

    unsigned aoff[2], boff[2];
#pragma unroll
    for (int mt = 0; mt < 2; mt++)
        aoff[mt] = sA + (m0w + mt * 16 + (lane & 15)) * 272 + ((lane >> 4) << 4);
#pragma unroll
    for (int np = 0; np < 2; np++)
        boff[np] = (n0w + np * 16 + ((lane >> 4) << 3) + (lane & 7)) * 272
                 + (((lane >> 3) & 1) << 4);

    float acc[2][4][4];
#pragma unroll
    for (int mt = 0; mt < 2; mt++)
#pragma unroll
        for (int q = 0; q < 4; q++)
#pragma unroll
            for (int i = 0; i < 4; i++) acc[mt][q][i] = 0.f;

#pragma unroll
    for (int pass = 0; pass < 3; pass++) {
        unsigned ab = (pass == 2) ? (aoff[0] + TILE_A64) : aoff[0];
        unsigned ab1 = (pass == 2) ? (aoff[1] + TILE_A64) : aoff[1];
        unsigned bb = (pass == 1) ? sBl : sBh;
#pragma unroll
        for (int ks = 0; ks < 8; ks++) {
            uint32_t a[2][4], b[2][4];
            ldsm4(a[0], ab + ks * 32);
            ldsm4(a[1], ab1 + ks * 32);
            ldsm4(b[0], bb + boff[0] + ks * 32);
            ldsm4(b[1], bb + boff[1] + ks * 32);
#pragma unroll
            for (int mt = 0; mt < 2; mt++) {
                mma_bf16(acc[mt][0], a[mt], &b[0][0]);
                mma_bf16(acc[mt][1], a[mt], &b[0][2]);
                mma_bf16(acc[mt][2], a[mt], &b[1][0]);
                mma_bf16(acc[mt][3], a[mt], &b[1][2]);
            }
        }
    }

    int crow = lane >> 2;
    int ccol = (lane & 3) * 2;
#pragma unroll
    for (int mt = 0; mt < 2; mt++) {
        int row = m0 + m0w + mt * 16 + crow;
#pragma unroll
        for (int q = 0; q < 4; q++) {
            int col = ncol0 + n0w + q * 8 + ccol;
            float2 bv = *(const float2*)(bias + col);
            float2 v0 = make_float2(acc[mt][q][0] + bv.x, acc[mt][q][1] + bv.y);
            float2 v1 = make_float2(acc[mt][q][2] + bv.x, acc[mt][q][3] + bv.y);
            *(float2*)(C + (size_t)row * ldc + col) = v0;
            *(float2*)(C + (size_t)(row + 8) * ldc + col) = v1;
        }
    }
}

// input projections: grid (1950 m-tiles, 3 gru); loop over 3 n-tiles.
__global__ void __launch_bounds__(256, 2)
gemm_in(const float* __restrict__ Xq, const float* __restrict__ Xk, const float* __restrict__ Xv,
        const float* __restrict__ Wq, const float* __restrict__ Wk, const float* __restrict__ Wv,
        const float* __restrict__ bq, const float* __restrict__ bk, const float* __restrict__ bv)
{
    extern __shared__ char smc[];
    unsigned sA  = smem_u32(smc);
    unsigned sBh = sA + 2 * TILE_A64;
    unsigned sBl = sBh + TILE_B128;

    int gru = blockIdx.y;
    int m0  = blockIdx.x * 64;

    const float* X = (gru == 0) ? Xq : (gru == 1) ? Xk : Xv;
    const float* W = (gru == 0) ? Wq : (gru == 1) ? Wk : Wv;
    const float* bias = (gru == 0) ? bq : (gru == 1) ? bk : bv;
    float* C = g_xw + (size_t)gru * MTOT * G3;

    convert_rows(X, 128, m0, 64, (uint32_t*)smc, (uint32_t*)(smc + TILE_A64), 256);

    for (int nt = 0; nt < 3; nt++) {
        convert_rows(W, 128, nt * 128, 128,
                     (uint32_t*)(smc + 2 * TILE_A64),
                     (uint32_t*)(smc + 2 * TILE_A64 + TILE_B128), 256);
        __syncthreads();
        mma_tile_64(sA, sBh, sBl, m0, nt * 128, bias, C, G3);
        __syncthreads();
    }
}

// output projection: grid (1950)
__global__ void __launch_bounds__(256, 2)
gemm_out(const float* __restrict__ Wout, const float* __restrict__ bout,
         float* __restrict__ out)
{
    extern __shared__ char smc[];
    unsigned sA  = smem_u32(smc);
    unsigned sBh = sA + 2 * TILE_A64;
    unsigned sBl = sBh + TILE_B128;
    int m0 = blockIdx.x * 64;

    convert_rows(g_ao, 128, m0, 64, (uint32_t*)smc, (uint32_t*)(smc + TILE_A64), 256);
    convert_rows(Wout, 128, 0, 128,
                 (uint32_t*)(smc + 2 * TILE_A64),
                 (uint32_t*)(smc + 2 * TILE_A64 + TILE_B128), 256);
    __syncthreads();
    mma_tile_64(sA, sBh, sBl, m0, 0, bout, out, 128);
}

// ========================================================================
// GRU scan v10 — tensor-core recurrence, 4-way accumulator ILP.
// ========================================================================
#define SC_WLB   (G3 * 136 * 2)
#define SC_HH    SC_WLB
#define SC_HL    (SC_HH + 8 * 136 * 2)
#define SC_HS    (SC_HL + 8 * 136 * 2)
#define SC_GH    (SC_HS + 8 * 136 * 4)
#define SC_RZ    (SC_GH + G3 * 8 * 4)
#define SC_XN    (SC_RZ + 8 * 264 * 4)
#define SC_GN    (SC_XN + 8 * 132 * 4)
#define SC_SMEM  (SC_GN + 8 * 132 * 4)

__global__ void __launch_bounds__(384, 1)
gru_scan_tc(const float* __restrict__ Whh_q, const float* __restrict__ Whh_k,
            const float* __restrict__ Whh_v,
            const float* __restrict__ bhh_q, const float* __restrict__ bhh_k,
            const float* __restrict__ bhh_v)
{
    extern __shared__ char smc[];
    __nv_bfloat16* Wl  = (__nv_bfloat16*)smc;
    uint32_t*      Wl32 = (uint32_t*)smc;
    __nv_bfloat16* HHb = (__nv_bfloat16*)(smc + SC_HH);
    __nv_bfloat16* HLb = (__nv_bfloat16*)(smc + SC_HL);
    uint32_t*      HH32 = (uint32_t*)(smc + SC_HH);
    uint32_t*      HL32 = (uint32_t*)(smc + SC_HL);
    float*         Hs   = (float*)(smc + SC_HS);
    float*         gh_s = (float*)(smc + SC_GH);
    float*         rz_s = (float*)(smc + SC_RZ);
    float*         xn_s = (float*)(smc + SC_XN);
    float*         gn_s = (float*)(smc + SC_GN);

    int gru = blockIdx.x / 48;
    int bb  = blockIdx.x % 48;
    int i0  = bb * 8;

    const float* Whh = (gru == 0) ? Whh_q : (gru == 1) ? Whh_k : Whh_v;
    const float* bhh = (gru == 0) ? bhh_q : (gru == 1) ? bhh_k : bhh_v;

    int tid = threadIdx.x;
    int wid = tid >> 5;
    int lane = tid & 31;
    int gate = tid >> 7;
    int e    = tid & 127;

    for (int idx = tid; idx < G3 * DD; idx += 384) {
        int g = idx >> 7, k = idx & 127;
        float w = Whh[idx];
        float wh = __bfloat162float(__float2bfloat16(w));
        Wl[g * 136 + k] = __float2bfloat16(w - wh);
    }
    for (int idx = tid; idx < 8 * 136; idx += 384) {
        HHb[idx] = __float2bfloat16(0.f);
        HLb[idx] = __float2bfloat16(0.f);
        Hs[idx] = 0.f;
    }

    uint32_t wh[2][8][4];
    {
        const float2* W2 = (const float2*)Whh;
        int rb = wid * 32 + (lane >> 2);
#pragma unroll
        for (int mt = 0; mt < 2; mt++) {
            int r0 = rb + mt * 16;
#pragma unroll
            for (int kt = 0; kt < 8; kt++) {
                int c = kt * 16 + (lane & 3) * 2;
                float2 w00 = W2[(r0 * 128 + c) >> 1];
                float2 w10 = W2[((r0 + 8) * 128 + c) >> 1];
                float2 w01 = W2[(r0 * 128 + c + 8) >> 1];
                float2 w11 = W2[((r0 + 8) * 128 + c + 8) >> 1];
                wh[mt][kt][0] = bf16x2_pack(w00.x, w00.y);
                wh[mt][kt][1] = bf16x2_pack(w10.x, w10.y);
                wh[mt][kt][2] = bf16x2_pack(w01.x, w01.y);
                wh[mt][kt][3] = bf16x2_pack(w11.x, w11.y);
            }
        }
    }

    float bhh_g = bhh[tid];
    const float* xwp = g_xw + (size_t)(gru * BATCH + i0) * NN * G3 + tid;
    const size_t bstride = (size_t)NN * G3;

    float xw_cur[8], xw_nxt[8];
#pragma unroll
    for (int b = 0; b < 8; b++) xw_cur[b] = __ldg(xwp + (size_t)b * bstride);

    __syncthreads();

    for (int j = 0; j < NN; j++) {
        bool has_next = (j + 1 < NN);
        if (has_next) {
            const float* xp = xwp + (size_t)(j + 1) * G3;
#pragma unroll
            for (int b = 0; b < 8; b++) xw_nxt[b] = __ldg(xp + (size_t)b * bstride);
        }

        int hb = (lane >> 2) * 68 + (lane & 3);
        uint32_t bh[8][2], bl[8][2];
#pragma unroll
        for (int kt = 0; kt < 8; kt++) {
            bh[kt][0] = HH32[hb + kt * 8];
            bh[kt][1] = HH32[hb + kt * 8 + 4];
            bl[kt][0] = HL32[hb + kt * 8];
            bl[kt][1] = HL32[hb + kt * 8 + 4];
        }

        // 4 independent accumulator chains: P (pass0 + even pass2),
        // Q (pass1 + odd pass2), each x2 mt.
        float cP[2][4], cQ[2][4];
#pragma unroll
        for (int mt = 0; mt < 2; mt++)
#pragma unroll
            for (int i = 0; i < 4; i++) { cP[mt][i] = 0.f; cQ[mt][i] = 0.f; }

#pragma unroll
        for (int kt = 0; kt < 8; kt++) {
            mma_bf16(cP[0], wh[0][kt], bh[kt]);
            mma_bf16(cP[1], wh[1][kt], bh[kt]);
            mma_bf16(cQ[0], wh[0][kt], bl[kt]);
            mma_bf16(cQ[1], wh[1][kt], bl[kt]);
        }
#pragma unroll
        for (int mt = 0; mt < 2; mt++) {
            int r0 = wid * 32 + mt * 16 + (lane >> 2);
#pragma unroll
            for (int kt = 0; kt < 8; kt++) {
                uint32_t wl[4];
                int base = r0 * 68 + kt * 8 + (lane & 3);
                wl[0] = Wl32[base];
                wl[1] = Wl32[base + 8 * 68];
                wl[2] = Wl32[base + 4];
                wl[3] = Wl32[base + 8 * 68 + 4];
                mma_bf16((kt & 1) ? cQ[mt] : cP[mt], wl, bh[kt]);
            }
        }

#pragma unroll
        for (int mt = 0; mt < 2; mt++) {
            int gg = wid * 32 + mt * 16 + (lane >> 2);
            *(float2*)(gh_s + gg * 8 + (lane & 3) * 2) =
                make_float2(cP[mt][0] + cQ[mt][0], cP[mt][1] + cQ[mt][1]);
            *(float2*)(gh_s + (gg + 8) * 8 + (lane & 3) * 2) =
                make_float2(cP[mt][2] + cQ[mt][2], cP[mt][3] + cQ[mt][3]);
        }
        __syncwarp();

        float4 ga = *(const float4*)(gh_s + tid * 8);
        float4 gb = *(const float4*)(gh_s + tid * 8 + 4);
        float ghv[8] = {ga.x + bhh_g, ga.y + bhh_g, ga.z + bhh_g, ga.w + bhh_g,
                        gb.x + bhh_g, gb.y + bhh_g, gb.z + bhh_g, gb.w + bhh_g};

        if (gate < 2) {
#pragma unroll
            for (int b = 0; b < 8; b++)
                rz_s[b * 264 + gate * 132 + e] = sigmoidf_(xw_cur[b] + ghv[b]);
        } else {
#pragma unroll
            for (int b = 0; b < 8; b++) {
                xn_s[b * 132 + e] = xw_cur[b];
                gn_s[b * 132 + e] = ghv[b];
            }
        }
        __syncthreads();

        const size_t ybase = ((size_t)(gru * BATCH + i0) * NN + j) * DD;
#pragma unroll
        for (int pp = 0; pp < 3; pp++) {
            int p = tid + pp * 384;
            if (p < 1024) {
                int b = p >> 7, e2 = p & 127;
                float r   = rz_s[b * 264 + e2];
                float z   = rz_s[b * 264 + 132 + e2];
                float xn  = xn_s[b * 132 + e2];
                float ghn = gn_s[b * 132 + e2];
                float hp  = Hs[b * 136 + e2];
                float nn = tanhf_(xn + r * ghn);
                float hnew = (1.f - z) * nn + z * hp;
                Hs[b * 136 + e2] = hnew;
                float hhv = __bfloat162float(__float2bfloat16(hnew));
                HHb[b * 136 + e2] = __float2bfloat16(hnew);
                HLb[b * 136 + e2] = __float2bfloat16(hnew - hhv);
                g_ys[ybase + (size_t)b * (NN * DD) + e2] = hnew;
            }
        }
        __syncthreads();

#pragma unroll
        for (int b = 0; b < 8; b++) xw_cur[b] = xw_nxt[b];
    }
}

// ========================================================================
// Attention: 5 (b,n) pairs per block, 480 threads.
// ========================================================================
#define ATT_SMEM (5 * TT * DD * 2 * 4)

__global__ void __launch_bounds__(480)
attn_kernel(const float* __restrict__ rel)
{
    extern __shared__ float att_sm[];
    float* ks = att_sm;
    float* vs = att_sm + 5 * TT * DD;

    int b  = blockIdx.x / 65;
    int nb = blockIdx.x % 65;
    int tid = threadIdx.x;
    const size_t GS = (size_t)MTOT * DD;

    for (int u = tid; u < 5 * TT * DD / 4; u += 480) {
        int sub = u / 384;
        int v = u - sub * 384;
        int s = v >> 5, c4 = v & 31;
        int n = nb * 5 + sub;
        size_t base = ((size_t)(b * TT + s) * NN + n) * DD + c4 * 4;
        ((float4*)ks)[u] = *(const float4*)(g_ys + GS + base);
        ((float4*)vs)[u] = *(const float4*)(g_ys + 2 * GS + base);
    }
    __syncthreads();

    int sub = tid / 96;
    int st  = tid % 96;
    int h = st / TT, t = st % TT;
    int n = nb * 5 + sub;
    const float* ksub = ks + sub * TT * DD;
    const float* vsub = vs + sub * TT * DD;

    float q[HD];
    size_t qb = ((size_t)(b * TT + t) * NN + n) * DD + h * HD;
#pragma unroll
    for (int i = 0; i < 4; i++) ((float4*)q)[i] = *(const float4*)(g_ys + qb + i * 4);

    int hbias = (5 * b + n) & 7;
    const float* rp = rel + hbias * TT * TT + t * TT;

    float srow[TT];
#pragma unroll
    for (int s = 0; s < TT; s++) {
        float a = 0.f;
#pragma unroll
        for (int d = 0; d < HD; d++) a += q[d] * ksub[s * DD + h * HD + d];
        srow[s] = a * 0.25f + __ldg(&rp[s]);
    }

    float m = srow[0];
#pragma unroll
    for (int s = 1; s < TT; s++) m = fmaxf(m, srow[s]);
    float sum = 0.f;
#pragma unroll
    for (int s = 0; s < TT; s++) { srow[s] = __expf(srow[s] - m); sum += srow[s]; }
    float inv = __fdividef(1.f, sum);

    float o[HD];
#pragma unroll
    for (int d = 0; d < HD; d++) o[d] = 0.f;
#pragma unroll
    for (int s = 0; s < TT; s++) {
        float p = srow[s] * inv;
#pragma unroll
        for (int d = 0; d < HD; d++) o[d] += p * vsub[s * DD + h * HD + d];
    }

    size_t ob = ((size_t)(b * NN + n) * TT + t) * DD + h * HD;
#pragma unroll
    for (int i = 0; i < 4; i++) *(float4*)(g_ao + ob + i * 4) = ((float4*)o)[i];
}

// ========================================================================
extern "C" void kernel_launch(void* const* d_in, const int* in_sizes, int n_in,
                              void* d_out, int out_size)
{
    const float* query = (const float*)d_in[0];
    const float* key   = (const float*)d_in[1];
    const float* value = (const float*)d_in[2];
    const float* Wih_q = (const float*)d_in[3];
    const float* Whh_q = (const float*)d_in[4];
    const float* bih_q = (const float*)d_in[5];
    const float* bhh_q = (const float*)d_in[6];
    const float* Wih_k = (const float*)d_in[7];
    const float* Whh_k = (const float*)d_in[8];
    const float* bih_k = (const float*)d_in[9];
    const float* bhh_k = (const float*)d_in[10];
    const float* Wih_v = (const float*)d_in[11];
    const float* Whh_v = (const float*)d_in[12];
    const float* bih_v = (const float*)d_in[13];
    const float* bhh_v = (const float*)d_in[14];
    const float* rel   = (const float*)d_in[15];
    const float* Wout  = (const float*)d_in[16];
    const float* bout  = (const float*)d_in[17];

    cudaFuncSetAttribute(gemm_in,     cudaFuncAttributeMaxDynamicSharedMemorySize, G64_SMEM);
    cudaFuncSetAttribute(gemm_out,    cudaFuncAttributeMaxDynamicSharedMemorySize, G64_SMEM);
    cudaFuncSetAttribute(gru_scan_tc, cudaFuncAttributeMaxDynamicSharedMemorySize, SC_SMEM);
    cudaFuncSetAttribute(attn_kernel, cudaFuncAttributeMaxDynamicSharedMemorySize, ATT_SMEM);

    // 1) input projections (64-row tiles, 2 CTAs/SM)
    gemm_in<<<dim3(MTOT / 64, 3), 256, G64_SMEM>>>(query, key, value,
                                                   Wih_q, Wih_k, Wih_v,
                                                   bih_q, bih_k, bih_v);

    // 2) GRU scans — recurrence on tensor cores (4-way acc ILP)
    gru_scan_tc<<<144, 384, SC_SMEM>>>(Whh_q, Whh_k, Whh_v, bhh_q, bhh_k, bhh_v);

    // 3) attentions (5 per block)
    attn_kernel<<<B32 * 65, 480, ATT_SMEM>>>(rel);

    // 4) output projection (64-row tiles, 2 CTAs/SM)
    gemm_out<<<MTOT / 64, 256, G64_SMEM>>>(Wout, bout, (float*)d_out);
}

// round 11
// speedup vs baseline: 2.7309x; 1.0664x over previous
#include <cuda_runtime.h>
#include <cuda_bf16.h>
#include <cstdint>

// ---------------- problem constants ----------------
#define B32   32
#define NN    325
#define TT    12
#define DD    128
#define G3    384
#define BATCH 384
#define MTOT  124800
#define HH    8
#define HD    16

// ---------------- scratch ----------
__device__ float g_xw[(size_t)3 * MTOT * G3];
__device__ float g_ys[(size_t)3 * MTOT * DD];
__device__ float g_ao[(size_t)MTOT * DD];
// preconverted weights: 10 tiles (gru*3+nt for Wih, 9 = Wout), hi+lo, 128x136 bf16
__device__ __nv_bfloat16 g_wb[10][2][128 * 136];

__device__ __forceinline__ unsigned smem_u32(const void* p) {
    return (unsigned)__cvta_generic_to_shared(p);
}
__device__ __forceinline__ float sigmoidf_(float x) {
    return __fdividef(1.f, 1.f + __expf(-x));
}
__device__ __forceinline__ float tanhf_(float x) {
    return __fdividef(2.f, 1.f + __expf(-2.f * x)) - 1.f;
}
__device__ __forceinline__ void cp_async16(unsigned dst_smem, const void* src_gmem) {
    asm volatile("cp.async.cg.shared.global [%0], [%1], 16;" :: "r"(dst_smem), "l"(src_gmem) : "memory");
}
__device__ __forceinline__ void cp_wait_all() {
    asm volatile("cp.async.commit_group;\ncp.async.wait_group 0;" ::: "memory");
}

// ---------------- warp-level tensor core helpers ----------
__device__ __forceinline__ void ldsm4(uint32_t* r, unsigned a) {
    asm volatile("ldmatrix.sync.aligned.m8n8.x4.shared.b16 {%0,%1,%2,%3}, [%4];"
        : "=r"(r[0]), "=r"(r[1]), "=r"(r[2]), "=r"(r[3]) : "r"(a));
}
__device__ __forceinline__ void mma_bf16(float* c, const uint32_t* a, const uint32_t* b) {
    asm volatile("mma.sync.aligned.m16n8k16.row.col.f32.bf16.bf16.f32 "
        "{%0,%1,%2,%3}, {%4,%5,%6,%7}, {%8,%9}, {%0,%1,%2,%3};"
        : "+f"(c[0]), "+f"(c[1]), "+f"(c[2]), "+f"(c[3])
        : "r"(a[0]), "r"(a[1]), "r"(a[2]), "r"(a[3]), "r"(b[0]), "r"(b[1]));
}
__device__ __forceinline__ uint32_t bf16x2_pack(float lo, float hi) {
    uint32_t r;
    asm("cvt.rn.bf16x2.f32 %0, %2, %1;" : "=r"(r) : "f"(lo), "f"(hi));
    return r;
}

#define TILE_A64  (64 * 136 * 2)      // 17408 B
#define TILE_B128 (128 * 136 * 2)     // 34816 B

// convert `rows` x128 fp32 -> bf16 hi/lo tiles (stride 136), generic dst
__device__ __forceinline__ void convert_rows(const float* __restrict__ S, size_t lds,
                                             int r0, int rows,
                                             uint32_t* H32, uint32_t* L32, int nthr)
{
    int tid = threadIdx.x;
    for (int u = tid; u < rows * 32; u += nthr) {
        int r = u >> 5, c4 = (u & 31) << 2;
        int o = r * 68 + (c4 >> 1);
        float4 f = *(const float4*)(S + (size_t)(r0 + r) * lds + c4);
        float h0 = __bfloat162float(__float2bfloat16(f.x));
        float h1 = __bfloat162float(__float2bfloat16(f.y));
        float h2 = __bfloat162float(__float2bfloat16(f.z));
        float h3 = __bfloat162float(__float2bfloat16(f.w));
        H32[o]     = bf16x2_pack(h0, h1);
        H32[o + 1] = bf16x2_pack(h2, h3);
        L32[o]     = bf16x2_pack(f.x - h0, f.y - h1);
        L32[o + 1] = bf16x2_pack(f.z - h2, f.w - h3);
    }
}

// ========================================================================
// Weight preconvert: 10 blocks, each converts one 128x128 tile.
// ========================================================================
__global__ void __launch_bounds__(256)
preconv_w(const float* __restrict__ Wq, const float* __restrict__ Wk,
          const float* __restrict__ Wv, const float* __restrict__ Wout)
{
    int t = blockIdx.x;
    const float* src;
    if (t < 9) {
        int gru = t / 3, nt = t % 3;
        const float* W = (gru == 0) ? Wq : (gru == 1) ? Wk : Wv;
        src = W + (size_t)nt * 128 * 128;
    } else {
        src = Wout;
    }
    convert_rows(src, 128, 0, 128, (uint32_t*)g_wb[t][0], (uint32_t*)g_wb[t][1], 256);
}

// ========================================================================
// GEMM tile: 64 rows x 128 cols x K=128, 256 threads, 2 CTAs/SM.
// B tiles pre-converted in gmem; loaded via cp.async.
// ========================================================================
#define G64_SMEM (2 * TILE_A64 + 2 * TILE_B128)   // 104448

__device__ __forceinline__ void load_b_tiles(unsigned sB, int tile)
{
    const char* src = (const char*)g_wb[tile][0];    // hi then lo contiguous (69632 B)
    int tid = threadIdx.x;
#pragma unroll
    for (int i = 0; i < 17; i++) {
        int u = tid + i * 256;                       // 4352 x 16B chunks
        cp_async16(sB + u * 16, src + (size_t)u * 16);
    }
}

__device__ __forceinline__ void mma_tile_64(
    unsigned sA, unsigned sBh, unsigned sBl,
    int m0, int ncol0,
    const float* __restrict__ bias,
    float* __restrict__ C, int ldc)
{
    int tid = threadIdx.x;
    int wid = tid >> 5, lane = tid & 31;
    int m0w = (wid & 1) * 32;
    int n0w = (wid >> 1) * 32;

    unsigned aoff[2], boff[2];
#pragma unroll
    for (int mt = 0; mt < 2; mt++)
        aoff[mt] = sA + (m0w + mt * 16 + (lane & 15)) * 272 + ((lane >> 4) << 4);
#pragma unroll
    for (int np = 0; np < 2; np++)
        boff[np] = (n0w + np * 16 + ((lane >> 4) << 3) + (lane & 7)) * 272
                 + (((lane >> 3) & 1) << 4);

    float acc[2][4][4];
#pragma unroll
    for (int mt = 0; mt < 2; mt++)
#pragma unroll
        for (int q = 0; q < 4; q++)
#pragma unroll
            for (int i = 0; i < 4; i++) acc[mt][q][i] = 0.f;

#pragma unroll
    for (int pass = 0; pass < 3; pass++) {
        unsigned ab  = (pass == 2) ? (aoff[0] + TILE_A64) : aoff[0];
        unsigned ab1 = (pass == 2) ? (aoff[1] + TILE_A64) : aoff[1];
        unsigned bb  = (pass == 1) ? sBl : sBh;
#pragma unroll
        for (int ks = 0; ks < 8; ks++) {
            uint32_t a[2][4], b[2][4];
            ldsm4(a[0], ab + ks * 32);
            ldsm4(a[1], ab1 + ks * 32);
            ldsm4(b[0], bb + boff[0] + ks * 32);
            ldsm4(b[1], bb + boff[1] + ks * 32);
#pragma unroll
            for (int mt = 0; mt < 2; mt++) {
                mma_bf16(acc[mt][0], a[mt], &b[0][0]);
                mma_bf16(acc[mt][1], a[mt], &b[0][2]);
                mma_bf16(acc[mt][2], a[mt], &b[1][0]);
                mma_bf16(acc[mt][3], a[mt], &b[1][2]);
            }
        }
    }

    int crow = lane >> 2;
    int ccol = (lane & 3) * 2;
#pragma unroll
    for (int mt = 0; mt < 2; mt++) {
        int row = m0 + m0w + mt * 16 + crow;
#pragma unroll
        for (int q = 0; q < 4; q++) {
            int col = ncol0 + n0w + q * 8 + ccol;
            float2 bv = *(const float2*)(bias + col);
            float2 v0 = make_float2(acc[mt][q][0] + bv.x, acc[mt][q][1] + bv.y);
            float2 v1 = make_float2(acc[mt][q][2] + bv.x, acc[mt][q][3] + bv.y);
            *(float2*)(C + (size_t)row * ldc + col) = v0;
            *(float2*)(C + (size_t)(row + 8) * ldc + col) = v1;
        }
    }
}

// input projections: grid (1950 m-tiles, 3 gru); loop over 3 n-tiles.
__global__ void __launch_bounds__(256, 2)
gemm_in(const float* __restrict__ Xq, const float* __restrict__ Xk, const float* __restrict__ Xv,
        const float* __restrict__ bq, const float* __restrict__ bk, const float* __restrict__ bv)
{
    extern __shared__ char smc[];
    unsigned sA  = smem_u32(smc);
    unsigned sBh = sA + 2 * TILE_A64;
    unsigned sBl = sBh + TILE_B128;

    int gru = blockIdx.y;
    int m0  = blockIdx.x * 64;

    const float* X = (gru == 0) ? Xq : (gru == 1) ? Xk : Xv;
    const float* bias = (gru == 0) ? bq : (gru == 1) ? bk : bv;
    float* C = g_xw + (size_t)gru * MTOT * G3;

    // kick off B tile 0 load, then convert A while it flies
    load_b_tiles(sBh, gru * 3);
    convert_rows(X, 128, m0, 64, (uint32_t*)smc, (uint32_t*)(smc + TILE_A64), 256);

    for (int nt = 0; nt < 3; nt++) {
        cp_wait_all();
        __syncthreads();
        mma_tile_64(sA, sBh, sBl, m0, nt * 128, bias, C, G3);
        __syncthreads();
        if (nt < 2) load_b_tiles(sBh, gru * 3 + nt + 1);
    }
}

// output projection: grid (1950)
__global__ void __launch_bounds__(256, 2)
gemm_out(const float* __restrict__ bout, float* __restrict__ out)
{
    extern __shared__ char smc[];
    unsigned sA  = smem_u32(smc);
    unsigned sBh = sA + 2 * TILE_A64;
    unsigned sBl = sBh + TILE_B128;
    int m0 = blockIdx.x * 64;

    load_b_tiles(sBh, 9);
    convert_rows(g_ao, 128, m0, 64, (uint32_t*)smc, (uint32_t*)(smc + TILE_A64), 256);
    cp_wait_all();
    __syncthreads();
    mma_tile_64(sA, sBh, sBl, m0, 0, bout, out, 128);
}

// ========================================================================
// GRU scan v11 — tensor-core recurrence, ldmatrix for Wl and h frags.
// ========================================================================
#define SC_WLB   (G3 * 136 * 2)
#define SC_HH    SC_WLB
#define SC_HL    (SC_HH + 8 * 136 * 2)
#define SC_HS    (SC_HL + 8 * 136 * 2)
#define SC_GH    (SC_HS + 8 * 136 * 4)
#define SC_RZ    (SC_GH + G3 * 8 * 4)
#define SC_XN    (SC_RZ + 8 * 264 * 4)
#define SC_GN    (SC_XN + 8 * 132 * 4)
#define SC_SMEM  (SC_GN + 8 * 132 * 4)

__global__ void __launch_bounds__(384, 1)
gru_scan_tc(const float* __restrict__ Whh_q, const float* __restrict__ Whh_k,
            const float* __restrict__ Whh_v,
            const float* __restrict__ bhh_q, const float* __restrict__ bhh_k,
            const float* __restrict__ bhh_v)
{
    extern __shared__ char smc[];
    __nv_bfloat16* Wl  = (__nv_bfloat16*)smc;
    __nv_bfloat16* HHb = (__nv_bfloat16*)(smc + SC_HH);
    __nv_bfloat16* HLb = (__nv_bfloat16*)(smc + SC_HL);
    float*         Hs   = (float*)(smc + SC_HS);
    float*         gh_s = (float*)(smc + SC_GH);
    float*         rz_s = (float*)(smc + SC_RZ);
    float*         xn_s = (float*)(smc + SC_XN);
    float*         gn_s = (float*)(smc + SC_GN);

    unsigned sWl = smem_u32(smc);
    unsigned sHH = smem_u32(smc + SC_HH);
    unsigned sHL = smem_u32(smc + SC_HL);

    int gru = blockIdx.x / 48;
    int bb  = blockIdx.x % 48;
    int i0  = bb * 8;

    const float* Whh = (gru == 0) ? Whh_q : (gru == 1) ? Whh_k : Whh_v;
    const float* bhh = (gru == 0) ? bhh_q : (gru == 1) ? bhh_k : bhh_v;

    int tid = threadIdx.x;
    int wid = tid >> 5;
    int lane = tid & 31;
    int gate = tid >> 7;
    int e    = tid & 127;

    for (int idx = tid; idx < G3 * DD; idx += 384) {
        int g = idx >> 7, k = idx & 127;
        float w = Whh[idx];
        float wh = __bfloat162float(__float2bfloat16(w));
        Wl[g * 136 + k] = __float2bfloat16(w - wh);
    }
    for (int idx = tid; idx < 8 * 136; idx += 384) {
        HHb[idx] = __float2bfloat16(0.f);
        HLb[idx] = __float2bfloat16(0.f);
        Hs[idx] = 0.f;
    }

    // Wh a-frags pinned in registers
    uint32_t wh[2][8][4];
    {
        const float2* W2 = (const float2*)Whh;
        int rb = wid * 32 + (lane >> 2);
#pragma unroll
        for (int mt = 0; mt < 2; mt++) {
            int r0 = rb + mt * 16;
#pragma unroll
            for (int kt = 0; kt < 8; kt++) {
                int c = kt * 16 + (lane & 3) * 2;
                float2 w00 = W2[(r0 * 128 + c) >> 1];
                float2 w10 = W2[((r0 + 8) * 128 + c) >> 1];
                float2 w01 = W2[(r0 * 128 + c + 8) >> 1];
                float2 w11 = W2[((r0 + 8) * 128 + c + 8) >> 1];
                wh[mt][kt][0] = bf16x2_pack(w00.x, w00.y);
                wh[mt][kt][1] = bf16x2_pack(w10.x, w10.y);
                wh[mt][kt][2] = bf16x2_pack(w01.x, w01.y);
                wh[mt][kt][3] = bf16x2_pack(w11.x, w11.y);
            }
        }
    }

    // ldmatrix lane offsets
    unsigned aW[2];
#pragma unroll
    for (int mt = 0; mt < 2; mt++)
        aW[mt] = sWl + (wid * 32 + mt * 16 + (lane & 15)) * 272 + ((lane >> 4) << 4);
    // b-frag x4 covers two k-tiles: lanes[0:8)=kt rows, [8:16)=kt k8-15,
    // [16:24)=kt+1 rows, [24:32)=kt+1 k8-15
    unsigned bO = (lane & 7) * 272 + (((lane >> 3) & 1) << 4) + ((lane >> 4) << 5);

    float bhh_g = bhh[tid];
    const float* xwp = g_xw + (size_t)(gru * BATCH + i0) * NN * G3 + tid;
    const size_t bstride = (size_t)NN * G3;

    float xw_cur[8], xw_nxt[8];
#pragma unroll
    for (int b = 0; b < 8; b++) xw_cur[b] = __ldg(xwp + (size_t)b * bstride);

    __syncthreads();

    for (int j = 0; j < NN; j++) {
        bool has_next = (j + 1 < NN);
        if (has_next) {
            const float* xp = xwp + (size_t)(j + 1) * G3;
#pragma unroll
            for (int b = 0; b < 8; b++) xw_nxt[b] = __ldg(xp + (size_t)b * bstride);
        }

        // h b-frags via ldmatrix (4 + 4 ldsm4)
        uint32_t bh[8][2], bl[8][2];
#pragma unroll
        for (int kp = 0; kp < 4; kp++) {
            uint32_t r[4];
            ldsm4(r, sHH + bO + kp * 64);
            bh[2 * kp][0] = r[0]; bh[2 * kp][1] = r[1];
            bh[2 * kp + 1][0] = r[2]; bh[2 * kp + 1][1] = r[3];
            ldsm4(r, sHL + bO + kp * 64);
            bl[2 * kp][0] = r[0]; bl[2 * kp][1] = r[1];
            bl[2 * kp + 1][0] = r[2]; bl[2 * kp + 1][1] = r[3];
        }

        float cP[2][4], cQ[2][4];
#pragma unroll
        for (int mt = 0; mt < 2; mt++)
#pragma unroll
            for (int i = 0; i < 4; i++) { cP[mt][i] = 0.f; cQ[mt][i] = 0.f; }

#pragma unroll
        for (int kt = 0; kt < 8; kt++) {
            mma_bf16(cP[0], wh[0][kt], bh[kt]);
            mma_bf16(cP[1], wh[1][kt], bh[kt]);
            mma_bf16(cQ[0], wh[0][kt], bl[kt]);
            mma_bf16(cQ[1], wh[1][kt], bl[kt]);
        }
        // pass 2: Wl * hh, a-frags via ldmatrix
#pragma unroll
        for (int mt = 0; mt < 2; mt++) {
#pragma unroll
            for (int kt = 0; kt < 8; kt++) {
                uint32_t wl[4];
                ldsm4(wl, aW[mt] + kt * 32);
                mma_bf16((kt & 1) ? cQ[mt] : cP[mt], wl, bh[kt]);
            }
        }

#pragma unroll
        for (int mt = 0; mt < 2; mt++) {
            int gg = wid * 32 + mt * 16 + (lane >> 2);
            *(float2*)(gh_s + gg * 8 + (lane & 3) * 2) =
                make_float2(cP[mt][0] + cQ[mt][0], cP[mt][1] + cQ[mt][1]);
            *(float2*)(gh_s + (gg + 8) * 8 + (lane & 3) * 2) =
                make_float2(cP[mt][2] + cQ[mt][2], cP[mt][3] + cQ[mt][3]);
        }
        __syncwarp();

        float4 ga = *(const float4*)(gh_s + tid * 8);
        float4 gb = *(const float4*)(gh_s + tid * 8 + 4);
        float ghv[8] = {ga.x + bhh_g, ga.y + bhh_g, ga.z + bhh_g, ga.w + bhh_g,
                        gb.x + bhh_g, gb.y + bhh_g, gb.z + bhh_g, gb.w + bhh_g};

        if (gate < 2) {
#pragma unroll
            for (int b = 0; b < 8; b++)
                rz_s[b * 264 + gate * 132 + e] = sigmoidf_(xw_cur[b] + ghv[b]);
        } else {
#pragma unroll
            for (int b = 0; b < 8; b++) {
                xn_s[b * 132 + e] = xw_cur[b];
                gn_s[b * 132 + e] = ghv[b];
            }
        }
        __syncthreads();

        const size_t ybase = ((size_t)(gru * BATCH + i0) * NN + j) * DD;
#pragma unroll
        for (int pp = 0; pp < 3; pp++) {
            int p = tid + pp * 384;
            if (p < 1024) {
                int b = p >> 7, e2 = p & 127;
                float r   = rz_s[b * 264 + e2];
                float z   = rz_s[b * 264 + 132 + e2];
                float xn  = xn_s[b * 132 + e2];
                float ghn = gn_s[b * 132 + e2];
                float hp  = Hs[b * 136 + e2];
                float nn = tanhf_(xn + r * ghn);
                float hnew = (1.f - z) * nn + z * hp;
                Hs[b * 136 + e2] = hnew;
                float hhv = __bfloat162float(__float2bfloat16(hnew));
                HHb[b * 136 + e2] = __float2bfloat16(hnew);
                HLb[b * 136 + e2] = __float2bfloat16(hnew - hhv);
                g_ys[ybase + (size_t)b * (NN * DD) + e2] = hnew;
            }
        }
        __syncthreads();

#pragma unroll
        for (int b = 0; b < 8; b++) xw_cur[b] = xw_nxt[b];
    }
}

// ========================================================================
// Attention: 5 (b,n) pairs per block, 480 threads.
// ========================================================================
#define ATT_SMEM (5 * TT * DD * 2 * 4)

__global__ void __launch_bounds__(480)
attn_kernel(const float* __restrict__ rel)
{
    extern __shared__ float att_sm[];
    float* ks = att_sm;
    float* vs = att_sm + 5 * TT * DD;

    int b  = blockIdx.x / 65;
    int nb = blockIdx.x % 65;
    int tid = threadIdx.x;
    const size_t GS = (size_t)MTOT * DD;

    for (int u = tid; u < 5 * TT * DD / 4; u += 480) {
        int sub = u / 384;
        int v = u - sub * 384;
        int s = v >> 5, c4 = v & 31;
        int n = nb * 5 + sub;
        size_t base = ((size_t)(b * TT + s) * NN + n) * DD + c4 * 4;
        ((float4*)ks)[u] = *(const float4*)(g_ys + GS + base);
        ((float4*)vs)[u] = *(const float4*)(g_ys + 2 * GS + base);
    }
    __syncthreads();

    int sub = tid / 96;
    int st  = tid % 96;
    int h = st / TT, t = st % TT;
    int n = nb * 5 + sub;
    const float* ksub = ks + sub * TT * DD;
    const float* vsub = vs + sub * TT * DD;

    float q[HD];
    size_t qb = ((size_t)(b * TT + t) * NN + n) * DD + h * HD;
#pragma unroll
    for (int i = 0; i < 4; i++) ((float4*)q)[i] = *(const float4*)(g_ys + qb + i * 4);

    int hbias = (5 * b + n) & 7;
    const float* rp = rel + hbias * TT * TT + t * TT;

    float srow[TT];
#pragma unroll
    for (int s = 0; s < TT; s++) {
        float a = 0.f;
#pragma unroll
        for (int d = 0; d < HD; d++) a += q[d] * ksub[s * DD + h * HD + d];
        srow[s] = a * 0.25f + __ldg(&rp[s]);
    }

    float m = srow[0];
#pragma unroll
    for (int s = 1; s < TT; s++) m = fmaxf(m, srow[s]);
    float sum = 0.f;
#pragma unroll
    for (int s = 0; s < TT; s++) { srow[s] = __expf(srow[s] - m); sum += srow[s]; }
    float inv = __fdividef(1.f, sum);

    float o[HD];
#pragma unroll
    for (int d = 0; d < HD; d++) o[d] = 0.f;
#pragma unroll
    for (int s = 0; s < TT; s++) {
        float p = srow[s] * inv;
#pragma unroll
        for (int d = 0; d < HD; d++) o[d] += p * vsub[s * DD + h * HD + d];
    }

    size_t ob = ((size_t)(b * NN + n) * TT + t) * DD + h * HD;
#pragma unroll
    for (int i = 0; i < 4; i++) *(float4*)(g_ao + ob + i * 4) = ((float4*)o)[i];
}

// ========================================================================
extern "C" void kernel_launch(void* const* d_in, const int* in_sizes, int n_in,
                              void* d_out, int out_size)
{
    const float* query = (const float*)d_in[0];
    const float* key   = (const float*)d_in[1];
    const float* value = (const float*)d_in[2];
    const float* Wih_q = (const float*)d_in[3];
    const float* Whh_q = (const float*)d_in[4];
    const float* bih_q = (const float*)d_in[5];
    const float* bhh_q = (const float*)d_in[6];
    const float* Wih_k = (const float*)d_in[7];
    const float* Whh_k = (const float*)d_in[8];
    const float* bih_k = (const float*)d_in[9];
    const float* bhh_k = (const float*)d_in[10];
    const float* Wih_v = (const float*)d_in[11];
    const float* Whh_v = (const float*)d_in[12];
    const float* bih_v = (const float*)d_in[13];
    const float* bhh_v = (const float*)d_in[14];
    const float* rel   = (const float*)d_in[15];
    const float* Wout  = (const float*)d_in[16];
    const float* bout  = (const float*)d_in[17];

    cudaFuncSetAttribute(gemm_in,     cudaFuncAttributeMaxDynamicSharedMemorySize, G64_SMEM);
    cudaFuncSetAttribute(gemm_out,    cudaFuncAttributeMaxDynamicSharedMemorySize, G64_SMEM);
    cudaFuncSetAttribute(gru_scan_tc, cudaFuncAttributeMaxDynamicSharedMemorySize, SC_SMEM);
    cudaFuncSetAttribute(attn_kernel, cudaFuncAttributeMaxDynamicSharedMemorySize, ATT_SMEM);

    // 0) preconvert all weight matrices to bf16 hi/lo tiles
    preconv_w<<<10, 256>>>(Wih_q, Wih_k, Wih_v, Wout);

    // 1) input projections (64-row tiles, 2 CTAs/SM, preconverted B)
    gemm_in<<<dim3(MTOT / 64, 3), 256, G64_SMEM>>>(query, key, value,
                                                   bih_q, bih_k, bih_v);

    // 2) GRU scans — recurrence on tensor cores (ldmatrix frags)
    gru_scan_tc<<<144, 384, SC_SMEM>>>(Whh_q, Whh_k, Whh_v, bhh_q, bhh_k, bhh_v);

    // 3) attentions (5 per block)
    attn_kernel<<<B32 * 65, 480, ATT_SMEM>>>(rel);

    // 4) output projection (preconverted B)
    gemm_out<<<MTOT / 64, 256, G64_SMEM>>>(bout, (float*)d_out);
}

// round 12
// speedup vs baseline: 2.8747x; 1.0526x over previous
#include <cuda_runtime.h>
#include <cuda_bf16.h>
#include <cstdint>

// ---------------- problem constants ----------------
#define B32   32
#define NN    325
#define TT    12
#define DD    128
#define G3    384
#define BATCH 384
#define MTOT  124800
#define HH    8
#define HD    16

// ---------------- scratch ----------
__device__ float g_xw[(size_t)3 * MTOT * G3];
__device__ float g_ys[(size_t)3 * MTOT * DD];
__device__ float g_ao[(size_t)MTOT * DD];
// preconverted weights: 10 tiles (gru*3+nt for Wih, 9 = Wout), hi+lo, 128x136 bf16
__device__ __nv_bfloat16 g_wb[10][2][128 * 136];

__device__ __forceinline__ unsigned smem_u32(const void* p) {
    return (unsigned)__cvta_generic_to_shared(p);
}
__device__ __forceinline__ float sigmoidf_(float x) {
    return __fdividef(1.f, 1.f + __expf(-x));
}
__device__ __forceinline__ float tanhf_(float x) {
    return __fdividef(2.f, 1.f + __expf(-2.f * x)) - 1.f;
}
__device__ __forceinline__ void cp_async16(unsigned dst_smem, const void* src_gmem) {
    asm volatile("cp.async.cg.shared.global [%0], [%1], 16;" :: "r"(dst_smem), "l"(src_gmem) : "memory");
}
__device__ __forceinline__ void cp_commit() {
    asm volatile("cp.async.commit_group;" ::: "memory");
}
__device__ __forceinline__ void cp_wait0() {
    asm volatile("cp.async.wait_group 0;" ::: "memory");
}

// ---------------- warp-level tensor core helpers ----------
__device__ __forceinline__ void ldsm4(uint32_t* r, unsigned a) {
    asm volatile("ldmatrix.sync.aligned.m8n8.x4.shared.b16 {%0,%1,%2,%3}, [%4];"
        : "=r"(r[0]), "=r"(r[1]), "=r"(r[2]), "=r"(r[3]) : "r"(a));
}
__device__ __forceinline__ void mma_bf16(float* c, const uint32_t* a, const uint32_t* b) {
    asm volatile("mma.sync.aligned.m16n8k16.row.col.f32.bf16.bf16.f32 "
        "{%0,%1,%2,%3}, {%4,%5,%6,%7}, {%8,%9}, {%0,%1,%2,%3};"
        : "+f"(c[0]), "+f"(c[1]), "+f"(c[2]), "+f"(c[3])
        : "r"(a[0]), "r"(a[1]), "r"(a[2]), "r"(a[3]), "r"(b[0]), "r"(b[1]));
}
__device__ __forceinline__ uint32_t bf16x2_pack(float lo, float hi) {
    uint32_t r;
    asm("cvt.rn.bf16x2.f32 %0, %2, %1;" : "=r"(r) : "f"(lo), "f"(hi));
    return r;
}

#define TILE_A64  (64 * 136 * 2)
#define TILE_B128 (128 * 136 * 2)

__device__ __forceinline__ void convert_rows(const float* __restrict__ S, size_t lds,
                                             int r0, int rows,
                                             uint32_t* H32, uint32_t* L32, int nthr)
{
    int tid = threadIdx.x;
    for (int u = tid; u < rows * 32; u += nthr) {
        int r = u >> 5, c4 = (u & 31) << 2;
        int o = r * 68 + (c4 >> 1);
        float4 f = *(const float4*)(S + (size_t)(r0 + r) * lds + c4);
        float h0 = __bfloat162float(__float2bfloat16(f.x));
        float h1 = __bfloat162float(__float2bfloat16(f.y));
        float h2 = __bfloat162float(__float2bfloat16(f.z));
        float h3 = __bfloat162float(__float2bfloat16(f.w));
        H32[o]     = bf16x2_pack(h0, h1);
        H32[o + 1] = bf16x2_pack(h2, h3);
        L32[o]     = bf16x2_pack(f.x - h0, f.y - h1);
        L32[o + 1] = bf16x2_pack(f.z - h2, f.w - h3);
    }
}

// ========================================================================
// Weight preconvert (unchanged)
// ========================================================================
__global__ void __launch_bounds__(256)
preconv_w(const float* __restrict__ Wq, const float* __restrict__ Wk,
          const float* __restrict__ Wv, const float* __restrict__ Wout)
{
    int t = blockIdx.x;
    const float* src;
    if (t < 9) {
        int gru = t / 3, nt = t % 3;
        const float* W = (gru == 0) ? Wq : (gru == 1) ? Wk : Wv;
        src = W + (size_t)nt * 128 * 128;
    } else {
        src = Wout;
    }
    convert_rows(src, 128, 0, 128, (uint32_t*)g_wb[t][0], (uint32_t*)g_wb[t][1], 256);
}

// ========================================================================
// GEMMs (R11, unchanged)
// ========================================================================
#define G64_SMEM (2 * TILE_A64 + 2 * TILE_B128)

__device__ __forceinline__ void load_b_tiles(unsigned sB, int tile)
{
    const char* src = (const char*)g_wb[tile][0];
    int tid = threadIdx.x;
#pragma unroll
    for (int i = 0; i < 17; i++) {
        int u = tid + i * 256;
        cp_async16(sB + u * 16, src + (size_t)u * 16);
    }
}

__device__ __forceinline__ void mma_tile_64(
    unsigned sA, unsigned sBh, unsigned sBl,
    int m0, int ncol0,
    const float* __restrict__ bias,
    float* __restrict__ C, int ldc)
{
    int tid = threadIdx.x;
    int wid = tid >> 5, lane = tid & 31;
    int m0w = (wid & 1) * 32;
    int n0w = (wid >> 1) * 32;

    unsigned aoff[2], boff[2];
#pragma unroll
    for (int mt = 0; mt < 2; mt++)
        aoff[mt] = sA + (m0w + mt * 16 + (lane & 15)) * 272 + ((lane >> 4) << 4);
#pragma unroll
    for (int np = 0; np < 2; np++)
        boff[np] = (n0w + np * 16 + ((lane >> 4) << 3) + (lane & 7)) * 272
                 + (((lane >> 3) & 1) << 4);

    float acc[2][4][4];
#pragma unroll
    for (int mt = 0; mt < 2; mt++)
#pragma unroll
        for (int q = 0; q < 4; q++)
#pragma unroll
            for (int i = 0; i < 4; i++) acc[mt][q][i] = 0.f;

#pragma unroll
    for (int pass = 0; pass < 3; pass++) {
        unsigned ab  = (pass == 2) ? (aoff[0] + TILE_A64) : aoff[0];
        unsigned ab1 = (pass == 2) ? (aoff[1] + TILE_A64) : aoff[1];
        unsigned bb  = (pass == 1) ? sBl : sBh;
#pragma unroll
        for (int ks = 0; ks < 8; ks++) {
            uint32_t a[2][4], b[2][4];
            ldsm4(a[0], ab + ks * 32);
            ldsm4(a[1], ab1 + ks * 32);
            ldsm4(b[0], bb + boff[0] + ks * 32);
            ldsm4(b[1], bb + boff[1] + ks * 32);
#pragma unroll
            for (int mt = 0; mt < 2; mt++) {
                mma_bf16(acc[mt][0], a[mt], &b[0][0]);
                mma_bf16(acc[mt][1], a[mt], &b[0][2]);
                mma_bf16(acc[mt][2], a[mt], &b[1][0]);
                mma_bf16(acc[mt][3], a[mt], &b[1][2]);
            }
        }
    }

    int crow = lane >> 2;
    int ccol = (lane & 3) * 2;
#pragma unroll
    for (int mt = 0; mt < 2; mt++) {
        int row = m0 + m0w + mt * 16 + crow;
#pragma unroll
        for (int q = 0; q < 4; q++) {
            int col = ncol0 + n0w + q * 8 + ccol;
            float2 bv = *(const float2*)(bias + col);
            float2 v0 = make_float2(acc[mt][q][0] + bv.x, acc[mt][q][1] + bv.y);
            float2 v1 = make_float2(acc[mt][q][2] + bv.x, acc[mt][q][3] + bv.y);
            *(float2*)(C + (size_t)row * ldc + col) = v0;
            *(float2*)(C + (size_t)(row + 8) * ldc + col) = v1;
        }
    }
}

__global__ void __launch_bounds__(256, 2)
gemm_in(const float* __restrict__ Xq, const float* __restrict__ Xk, const float* __restrict__ Xv,
        const float* __restrict__ bq, const float* __restrict__ bk, const float* __restrict__ bv)
{
    extern __shared__ char smc[];
    unsigned sA  = smem_u32(smc);
    unsigned sBh = sA + 2 * TILE_A64;
    unsigned sBl = sBh + TILE_B128;

    int gru = blockIdx.y;
    int m0  = blockIdx.x * 64;

    const float* X = (gru == 0) ? Xq : (gru == 1) ? Xk : Xv;
    const float* bias = (gru == 0) ? bq : (gru == 1) ? bk : bv;
    float* C = g_xw + (size_t)gru * MTOT * G3;

    load_b_tiles(sBh, gru * 3);
    convert_rows(X, 128, m0, 64, (uint32_t*)smc, (uint32_t*)(smc + TILE_A64), 256);

    for (int nt = 0; nt < 3; nt++) {
        cp_commit(); cp_wait0();
        __syncthreads();
        mma_tile_64(sA, sBh, sBl, m0, nt * 128, bias, C, G3);
        __syncthreads();
        if (nt < 2) load_b_tiles(sBh, gru * 3 + nt + 1);
    }
}

__global__ void __launch_bounds__(256, 2)
gemm_out(const float* __restrict__ bout, float* __restrict__ out)
{
    extern __shared__ char smc[];
    unsigned sA  = smem_u32(smc);
    unsigned sBh = sA + 2 * TILE_A64;
    unsigned sBl = sBh + TILE_B128;
    int m0 = blockIdx.x * 64;

    load_b_tiles(sBh, 9);
    convert_rows(g_ao, 128, m0, 64, (uint32_t*)smc, (uint32_t*)(smc + TILE_A64), 256);
    cp_commit(); cp_wait0();
    __syncthreads();
    mma_tile_64(sA, sBh, sBl, m0, 0, bout, out, 128);
}

// ========================================================================
// GRU scan v12 — frag-owner epilogue + smem-staged xw (cp.async double buf).
// smem layout (bytes):
//   Wl   [384][136] bf16        @ 0        (104448)
//   HH   [8][136] bf16          @ 104448   (2176)
//   HL   [8][136] bf16          @ 106624   (2176)
//   Hs   [8][136] f32           @ 108800   (4352)
//   r_s  [8][132] f32           @ 113152   (4224)
//   z_s  [8][132] f32           @ 117376   (4224)
//   gn_s [8][132] f32           @ 121600   (4224)
//   xw_s [2][8][388] f32        @ 125824   (24832)
// ========================================================================
#define SC_HH    104448
#define SC_HL    106624
#define SC_HS    108800
#define SC_RS    113152
#define SC_ZS    117376
#define SC_GN    121600
#define SC_XW    125824
#define SC_SMEM  150656
#define XW_STG   (8 * 388)          // floats per stage

__global__ void __launch_bounds__(384, 1)
gru_scan_tc(const float* __restrict__ Whh_q, const float* __restrict__ Whh_k,
            const float* __restrict__ Whh_v,
            const float* __restrict__ bhh_q, const float* __restrict__ bhh_k,
            const float* __restrict__ bhh_v)
{
    extern __shared__ char smc[];
    __nv_bfloat16* Wl  = (__nv_bfloat16*)smc;
    __nv_bfloat16* HHb = (__nv_bfloat16*)(smc + SC_HH);
    __nv_bfloat16* HLb = (__nv_bfloat16*)(smc + SC_HL);
    float*         Hs   = (float*)(smc + SC_HS);
    float*         r_s  = (float*)(smc + SC_RS);
    float*         z_s  = (float*)(smc + SC_ZS);
    float*         gn_s = (float*)(smc + SC_GN);
    float*         xw_s = (float*)(smc + SC_XW);

    unsigned sWl = smem_u32(smc);
    unsigned sHH = smem_u32(smc + SC_HH);
    unsigned sHL = smem_u32(smc + SC_HL);
    unsigned sXW = smem_u32(smc + SC_XW);

    int gru = blockIdx.x / 48;
    int bb  = blockIdx.x % 48;
    int i0  = bb * 8;

    const float* Whh = (gru == 0) ? Whh_q : (gru == 1) ? Whh_k : Whh_v;
    const float* bhh = (gru == 0) ? bhh_q : (gru == 1) ? bhh_k : bhh_v;

    int tid = threadIdx.x;
    int wid = tid >> 5;
    int lane = tid & 31;
    int gatew = wid >> 2;      // per-warp gate type: 0=r 1=z 2=n

    for (int idx = tid; idx < G3 * DD; idx += 384) {
        int g = idx >> 7, k = idx & 127;
        float w = Whh[idx];
        float wh = __bfloat162float(__float2bfloat16(w));
        Wl[g * 136 + k] = __float2bfloat16(w - wh);
    }
    for (int idx = tid; idx < 8 * 136; idx += 384) {
        HHb[idx] = __float2bfloat16(0.f);
        HLb[idx] = __float2bfloat16(0.f);
        Hs[idx] = 0.f;
    }

    // Wh a-frags pinned in registers
    uint32_t wh[2][8][4];
    {
        const float2* W2 = (const float2*)Whh;
        int rb = wid * 32 + (lane >> 2);
#pragma unroll
        for (int mt = 0; mt < 2; mt++) {
            int r0 = rb + mt * 16;
#pragma unroll
            for (int kt = 0; kt < 8; kt++) {
                int c = kt * 16 + (lane & 3) * 2;
                float2 w00 = W2[(r0 * 128 + c) >> 1];
                float2 w10 = W2[((r0 + 8) * 128 + c) >> 1];
                float2 w01 = W2[(r0 * 128 + c + 8) >> 1];
                float2 w11 = W2[((r0 + 8) * 128 + c + 8) >> 1];
                wh[mt][kt][0] = bf16x2_pack(w00.x, w00.y);
                wh[mt][kt][1] = bf16x2_pack(w10.x, w10.y);
                wh[mt][kt][2] = bf16x2_pack(w01.x, w01.y);
                wh[mt][kt][3] = bf16x2_pack(w11.x, w11.y);
            }
        }
    }

    // bhh for owned frag rows: gg0 + 8k, gg0 = 32wid + lane>>2
    float bhh_r[4];
#pragma unroll
    for (int k = 0; k < 4; k++) bhh_r[k] = bhh[wid * 32 + (lane >> 2) + 8 * k];

    // ldmatrix lane offsets
    unsigned aW[2];
#pragma unroll
    for (int mt = 0; mt < 2; mt++)
        aW[mt] = sWl + (wid * 32 + mt * 16 + (lane & 15)) * 272 + ((lane >> 4) << 4);
    unsigned bO = (lane & 7) * 272 + (((lane >> 3) & 1) << 4) + ((lane >> 4) << 5);

    const size_t xwbase = (size_t)(gru * BATCH + i0) * NN * G3;   // floats
    const size_t bstride = (size_t)NN * G3;

    // prefetch step 0 into stage 0
    {
#pragma unroll
        for (int w2 = 0; w2 < 2; w2++) {
            int c = tid + w2 * 384;
            int b = c / 96, q = c % 96;
            cp_async16(sXW + b * 1552 + q * 16,
                       g_xw + xwbase + (size_t)b * bstride + q * 4);
        }
        cp_commit(); cp_wait0();
    }
    __syncthreads();

    for (int j = 0; j < NN; j++) {
        bool has_next = (j + 1 < NN);
        if (has_next) {
            unsigned dst = sXW + ((j + 1) & 1) * (XW_STG * 4);
#pragma unroll
            for (int w2 = 0; w2 < 2; w2++) {
                int c = tid + w2 * 384;
                int b = c / 96, q = c % 96;
                cp_async16(dst + b * 1552 + q * 16,
                           g_xw + xwbase + (size_t)b * bstride + (size_t)(j + 1) * G3 + q * 4);
            }
            cp_commit();
        }

        // h b-frags via ldmatrix
        uint32_t bh[8][2], bl[8][2];
#pragma unroll
        for (int kp = 0; kp < 4; kp++) {
            uint32_t r[4];
            ldsm4(r, sHH + bO + kp * 64);
            bh[2 * kp][0] = r[0]; bh[2 * kp][1] = r[1];
            bh[2 * kp + 1][0] = r[2]; bh[2 * kp + 1][1] = r[3];
            ldsm4(r, sHL + bO + kp * 64);
            bl[2 * kp][0] = r[0]; bl[2 * kp][1] = r[1];
            bl[2 * kp + 1][0] = r[2]; bl[2 * kp + 1][1] = r[3];
        }

        float cP[2][4], cQ[2][4];
#pragma unroll
        for (int mt = 0; mt < 2; mt++)
#pragma unroll
            for (int i = 0; i < 4; i++) { cP[mt][i] = 0.f; cQ[mt][i] = 0.f; }

#pragma unroll
        for (int kt = 0; kt < 8; kt++) {
            mma_bf16(cP[0], wh[0][kt], bh[kt]);
            mma_bf16(cP[1], wh[1][kt], bh[kt]);
            mma_bf16(cQ[0], wh[0][kt], bl[kt]);
            mma_bf16(cQ[1], wh[1][kt], bl[kt]);
        }
#pragma unroll
        for (int mt = 0; mt < 2; mt++) {
#pragma unroll
            for (int kt = 0; kt < 8; kt++) {
                uint32_t wl[4];
                ldsm4(wl, aW[mt] + kt * 32);
                mma_bf16((kt & 1) ? cQ[mt] : cP[mt], wl, bh[kt]);
            }
        }

        // ---- frag-owner epilogue (per-warp uniform gate type)
        const float* xwc = xw_s + (j & 1) * XW_STG;
        int b0 = 2 * (lane & 3);
#pragma unroll
        for (int mt = 0; mt < 2; mt++) {
            int gg = wid * 32 + mt * 16 + (lane >> 2);
            int e  = gg & 127;
            float s0 = cP[mt][0] + cQ[mt][0];
            float s1 = cP[mt][1] + cQ[mt][1];
            float s2 = cP[mt][2] + cQ[mt][2];
            float s3 = cP[mt][3] + cQ[mt][3];
            if (gatew < 2) {
                float* dst = (gatew == 0) ? r_s : z_s;
                float p00 = xwc[b0 * 388 + gg]           + s0 + bhh_r[2 * mt];
                float p01 = xwc[(b0 + 1) * 388 + gg]     + s1 + bhh_r[2 * mt];
                float p10 = xwc[b0 * 388 + gg + 8]       + s2 + bhh_r[2 * mt + 1];
                float p11 = xwc[(b0 + 1) * 388 + gg + 8] + s3 + bhh_r[2 * mt + 1];
                dst[b0 * 132 + e]           = sigmoidf_(p00);
                dst[(b0 + 1) * 132 + e]     = sigmoidf_(p01);
                dst[b0 * 132 + e + 8]       = sigmoidf_(p10);
                dst[(b0 + 1) * 132 + e + 8] = sigmoidf_(p11);
            } else {
                gn_s[b0 * 132 + e]           = s0 + bhh_r[2 * mt];
                gn_s[(b0 + 1) * 132 + e]     = s1 + bhh_r[2 * mt];
                gn_s[b0 * 132 + e + 8]       = s2 + bhh_r[2 * mt + 1];
                gn_s[(b0 + 1) * 132 + e + 8] = s3 + bhh_r[2 * mt + 1];
            }
        }

        cp_wait0();           // retire xw[j+1] before the barrier
        __syncthreads();

        // ---- balanced h-update: 1024 (b,e) pairs over 384 threads
        const size_t ybase = ((size_t)(gru * BATCH + i0) * NN + j) * DD;
#pragma unroll
        for (int pp = 0; pp < 3; pp++) {
            int p = tid + pp * 384;
            if (p < 1024) {
                int b = p >> 7, e2 = p & 127;
                float r   = r_s[b * 132 + e2];
                float z   = z_s[b * 132 + e2];
                float ghn = gn_s[b * 132 + e2];
                float xn  = xwc[b * 388 + 256 + e2];
                float hp  = Hs[b * 136 + e2];
                float nn = tanhf_(xn + r * ghn);
                float hnew = (1.f - z) * nn + z * hp;
                Hs[b * 136 + e2] = hnew;
                float hhv = __bfloat162float(__float2bfloat16(hnew));
                HHb[b * 136 + e2] = __float2bfloat16(hnew);
                HLb[b * 136 + e2] = __float2bfloat16(hnew - hhv);
                g_ys[ybase + (size_t)b * (NN * DD) + e2] = hnew;
            }
        }
        __syncthreads();
    }
}

// ========================================================================
// Attention v12: lane-pair head split; 960 threads, 5 (b,n) per block.
// ========================================================================
#define ATT_SMEM (5 * TT * DD * 2 * 4)

__global__ void __launch_bounds__(960)
attn_kernel(const float* __restrict__ rel)
{
    extern __shared__ float att_sm[];
    float* ks = att_sm;
    float* vs = att_sm + 5 * TT * DD;

    int b  = blockIdx.x / 65;
    int nb = blockIdx.x % 65;
    int tid = threadIdx.x;
    const size_t GS = (size_t)MTOT * DD;

    for (int u = tid; u < 5 * TT * DD / 4; u += 960) {
        int sub = u / 384;
        int v = u - sub * 384;
        int s = v >> 5, c4 = v & 31;
        int n = nb * 5 + sub;
        size_t base = ((size_t)(b * TT + s) * NN + n) * DD + c4 * 4;
        ((float4*)ks)[u] = *(const float4*)(g_ys + GS + base);
        ((float4*)vs)[u] = *(const float4*)(g_ys + 2 * GS + base);
    }
    __syncthreads();

    int half = tid & 1;
    int k  = tid >> 1;          // 0..479
    int sub = k / 96;
    int st  = k % 96;
    int h = st / TT, t = st % TT;
    int n = nb * 5 + sub;
    int d0 = h * HD + half * 8;
    const float* ksub = ks + sub * TT * DD;
    const float* vsub = vs + sub * TT * DD;

    float q[8];
    size_t qb = ((size_t)(b * TT + t) * NN + n) * DD + d0;
    ((float4*)q)[0] = *(const float4*)(g_ys + qb);
    ((float4*)q)[1] = *(const float4*)(g_ys + qb + 4);

    int hbias = (5 * b + n) & 7;
    const float* rp = rel + hbias * TT * TT + t * TT;

    float srow[TT];
#pragma unroll
    for (int s = 0; s < TT; s++) {
        float a = 0.f;
#pragma unroll
        for (int d = 0; d < 8; d++) a += q[d] * ksub[s * DD + d0 + d];
        float full = a + __shfl_xor_sync(0xffffffffu, a, 1);
        srow[s] = full * 0.25f + __ldg(&rp[s]);
    }

    float m = srow[0];
#pragma unroll
    for (int s = 1; s < TT; s++) m = fmaxf(m, srow[s]);
    float sum = 0.f;
#pragma unroll
    for (int s = 0; s < TT; s++) { srow[s] = __expf(srow[s] - m); sum += srow[s]; }
    float inv = __fdividef(1.f, sum);

    float o[8];
#pragma unroll
    for (int d = 0; d < 8; d++) o[d] = 0.f;
#pragma unroll
    for (int s = 0; s < TT; s++) {
        float p = srow[s] * inv;
#pragma unroll
        for (int d = 0; d < 8; d++) o[d] += p * vsub[s * DD + d0 + d];
    }

    size_t ob = ((size_t)(b * NN + n) * TT + t) * DD + d0;
    *(float4*)(g_ao + ob)     = ((float4*)o)[0];
    *(float4*)(g_ao + ob + 4) = ((float4*)o)[1];
}

// ========================================================================
extern "C" void kernel_launch(void* const* d_in, const int* in_sizes, int n_in,
                              void* d_out, int out_size)
{
    const float* query = (const float*)d_in[0];
    const float* key   = (const float*)d_in[1];
    const float* value = (const float*)d_in[2];
    const float* Wih_q = (const float*)d_in[3];
    const float* Whh_q = (const float*)d_in[4];
    const float* bih_q = (const float*)d_in[5];
    const float* bhh_q = (const float*)d_in[6];
    const float* Wih_k = (const float*)d_in[7];
    const float* Whh_k = (const float*)d_in[8];
    const float* bih_k = (const float*)d_in[9];
    const float* bhh_k = (const float*)d_in[10];
    const float* Wih_v = (const float*)d_in[11];
    const float* Whh_v = (const float*)d_in[12];
    const float* bih_v = (const float*)d_in[13];
    const float* bhh_v = (const float*)d_in[14];
    const float* rel   = (const float*)d_in[15];
    const float* Wout  = (const float*)d_in[16];
    const float* bout  = (const float*)d_in[17];

    cudaFuncSetAttribute(gemm_in,     cudaFuncAttributeMaxDynamicSharedMemorySize, G64_SMEM);
    cudaFuncSetAttribute(gemm_out,    cudaFuncAttributeMaxDynamicSharedMemorySize, G64_SMEM);
    cudaFuncSetAttribute(gru_scan_tc, cudaFuncAttributeMaxDynamicSharedMemorySize, SC_SMEM);
    cudaFuncSetAttribute(attn_kernel, cudaFuncAttributeMaxDynamicSharedMemorySize, ATT_SMEM);

    // 0) preconvert all weight matrices to bf16 hi/lo tiles
    preconv_w<<<10, 256>>>(Wih_q, Wih_k, Wih_v, Wout);

    // 1) input projections
    gemm_in<<<dim3(MTOT / 64, 3), 256, G64_SMEM>>>(query, key, value,
                                                   bih_q, bih_k, bih_v);

    // 2) GRU scans — frag-owner epilogue
    gru_scan_tc<<<144, 384, SC_SMEM>>>(Whh_q, Whh_k, Whh_v, bhh_q, bhh_k, bhh_v);

    // 3) attentions (lane-pair head split)
    attn_kernel<<<B32 * 65, 960, ATT_SMEM>>>(rel);

    // 4) output projection
    gemm_out<<<MTOT / 64, 256, G64_SMEM>>>(bout, (float*)d_out);
}

// round 13
// speedup vs baseline: 3.0024x; 1.0445x over previous
#include <cuda_runtime.h>
#include <cuda_bf16.h>
#include <cstdint>

// ---------------- problem constants ----------------
#define B32   32
#define NN    325
#define TT    12
#define DD    128
#define G3    384
#define BATCH 384
#define MTOT  124800
#define HH    8
#define HD    16

// ---------------- scratch ----------
__device__ float g_xw[(size_t)3 * MTOT * G3];
__device__ float g_ys[(size_t)3 * MTOT * DD];
// attention output, preconverted to bf16 hi/lo tiles (ldmatrix layout):
// [m-tile][hi/lo][64*136]
__device__ __nv_bfloat16 g_ab[MTOT / 64][2][64 * 136];
// preconverted weights: 10 tiles (gru*3+nt for Wih, 9 = Wout), hi+lo, 128x136 bf16
__device__ __nv_bfloat16 g_wb[10][2][128 * 136];

__device__ __forceinline__ unsigned smem_u32(const void* p) {
    return (unsigned)__cvta_generic_to_shared(p);
}
__device__ __forceinline__ float sigmoidf_(float x) {
    return __fdividef(1.f, 1.f + __expf(-x));
}
__device__ __forceinline__ float tanhf_(float x) {
    return __fdividef(2.f, 1.f + __expf(-2.f * x)) - 1.f;
}
__device__ __forceinline__ void cp_async16(unsigned dst_smem, const void* src_gmem) {
    asm volatile("cp.async.cg.shared.global [%0], [%1], 16;" :: "r"(dst_smem), "l"(src_gmem) : "memory");
}
__device__ __forceinline__ void cp_commit() {
    asm volatile("cp.async.commit_group;" ::: "memory");
}
__device__ __forceinline__ void cp_wait0() {
    asm volatile("cp.async.wait_group 0;" ::: "memory");
}

// ---------------- warp-level tensor core helpers ----------
__device__ __forceinline__ void ldsm4(uint32_t* r, unsigned a) {
    asm volatile("ldmatrix.sync.aligned.m8n8.x4.shared.b16 {%0,%1,%2,%3}, [%4];"
        : "=r"(r[0]), "=r"(r[1]), "=r"(r[2]), "=r"(r[3]) : "r"(a));
}
__device__ __forceinline__ void mma_bf16(float* c, const uint32_t* a, const uint32_t* b) {
    asm volatile("mma.sync.aligned.m16n8k16.row.col.f32.bf16.bf16.f32 "
        "{%0,%1,%2,%3}, {%4,%5,%6,%7}, {%8,%9}, {%0,%1,%2,%3};"
        : "+f"(c[0]), "+f"(c[1]), "+f"(c[2]), "+f"(c[3])
        : "r"(a[0]), "r"(a[1]), "r"(a[2]), "r"(a[3]), "r"(b[0]), "r"(b[1]));
}
__device__ __forceinline__ uint32_t bf16x2_pack(float lo, float hi) {
    uint32_t r;
    asm("cvt.rn.bf16x2.f32 %0, %2, %1;" : "=r"(r) : "f"(lo), "f"(hi));
    return r;
}

#define TILE_A64  (64 * 136 * 2)
#define TILE_B128 (128 * 136 * 2)

__device__ __forceinline__ void convert_rows(const float* __restrict__ S, size_t lds,
                                             int r0, int rows,
                                             uint32_t* H32, uint32_t* L32, int nthr)
{
    int tid = threadIdx.x;
    for (int u = tid; u < rows * 32; u += nthr) {
        int r = u >> 5, c4 = (u & 31) << 2;
        int o = r * 68 + (c4 >> 1);
        float4 f = *(const float4*)(S + (size_t)(r0 + r) * lds + c4);
        float h0 = __bfloat162float(__float2bfloat16(f.x));
        float h1 = __bfloat162float(__float2bfloat16(f.y));
        float h2 = __bfloat162float(__float2bfloat16(f.z));
        float h3 = __bfloat162float(__float2bfloat16(f.w));
        H32[o]     = bf16x2_pack(h0, h1);
        H32[o + 1] = bf16x2_pack(h2, h3);
        L32[o]     = bf16x2_pack(f.x - h0, f.y - h1);
        L32[o + 1] = bf16x2_pack(f.z - h2, f.w - h3);
    }
}

// ========================================================================
// Weight preconvert (unchanged)
// ========================================================================
__global__ void __launch_bounds__(256)
preconv_w(const float* __restrict__ Wq, const float* __restrict__ Wk,
          const float* __restrict__ Wv, const float* __restrict__ Wout)
{
    int t = blockIdx.x;
    const float* src;
    if (t < 9) {
        int gru = t / 3, nt = t % 3;
        const float* W = (gru == 0) ? Wq : (gru == 1) ? Wk : Wv;
        src = W + (size_t)nt * 128 * 128;
    } else {
        src = Wout;
    }
    convert_rows(src, 128, 0, 128, (uint32_t*)g_wb[t][0], (uint32_t*)g_wb[t][1], 256);
}

// ========================================================================
// GEMM core (R11/R12, unchanged)
// ========================================================================
#define G64_SMEM (2 * TILE_A64 + 2 * TILE_B128)

__device__ __forceinline__ void load_b_tiles(unsigned sB, int tile)
{
    const char* src = (const char*)g_wb[tile][0];
    int tid = threadIdx.x;
#pragma unroll
    for (int i = 0; i < 17; i++) {
        int u = tid + i * 256;
        cp_async16(sB + u * 16, src + (size_t)u * 16);
    }
}

__device__ __forceinline__ void mma_tile_64(
    unsigned sA, unsigned sBh, unsigned sBl,
    int m0, int ncol0,
    const float* __restrict__ bias,
    float* __restrict__ C, int ldc)
{
    int tid = threadIdx.x;
    int wid = tid >> 5, lane = tid & 31;
    int m0w = (wid & 1) * 32;
    int n0w = (wid >> 1) * 32;

    unsigned aoff[2], boff[2];
#pragma unroll
    for (int mt = 0; mt < 2; mt++)
        aoff[mt] = sA + (m0w + mt * 16 + (lane & 15)) * 272 + ((lane >> 4) << 4);
#pragma unroll
    for (int np = 0; np < 2; np++)
        boff[np] = (n0w + np * 16 + ((lane >> 4) << 3) + (lane & 7)) * 272
                 + (((lane >> 3) & 1) << 4);

    float acc[2][4][4];
#pragma unroll
    for (int mt = 0; mt < 2; mt++)
#pragma unroll
        for (int q = 0; q < 4; q++)
#pragma unroll
            for (int i = 0; i < 4; i++) acc[mt][q][i] = 0.f;

#pragma unroll
    for (int pass = 0; pass < 3; pass++) {
        unsigned ab  = (pass == 2) ? (aoff[0] + TILE_A64) : aoff[0];
        unsigned ab1 = (pass == 2) ? (aoff[1] + TILE_A64) : aoff[1];
        unsigned bb  = (pass == 1) ? sBl : sBh;
#pragma unroll
        for (int ks = 0; ks < 8; ks++) {
            uint32_t a[2][4], b[2][4];
            ldsm4(a[0], ab + ks * 32);
            ldsm4(a[1], ab1 + ks * 32);
            ldsm4(b[0], bb + boff[0] + ks * 32);
            ldsm4(b[1], bb + boff[1] + ks * 32);
#pragma unroll
            for (int mt = 0; mt < 2; mt++) {
                mma_bf16(acc[mt][0], a[mt], &b[0][0]);
                mma_bf16(acc[mt][1], a[mt], &b[0][2]);
                mma_bf16(acc[mt][2], a[mt], &b[1][0]);
                mma_bf16(acc[mt][3], a[mt], &b[1][2]);
            }
        }
    }

    int crow = lane >> 2;
    int ccol = (lane & 3) * 2;
#pragma unroll
    for (int mt = 0; mt < 2; mt++) {
        int row = m0 + m0w + mt * 16 + crow;
#pragma unroll
        for (int q = 0; q < 4; q++) {
            int col = ncol0 + n0w + q * 8 + ccol;
            float2 bv = *(const float2*)(bias + col);
            float2 v0 = make_float2(acc[mt][q][0] + bv.x, acc[mt][q][1] + bv.y);
            float2 v1 = make_float2(acc[mt][q][2] + bv.x, acc[mt][q][3] + bv.y);
            *(float2*)(C + (size_t)row * ldc + col) = v0;
            *(float2*)(C + (size_t)(row + 8) * ldc + col) = v1;
        }
    }
}

__global__ void __launch_bounds__(256, 2)
gemm_in(const float* __restrict__ Xq, const float* __restrict__ Xk, const float* __restrict__ Xv,
        const float* __restrict__ bq, const float* __restrict__ bk, const float* __restrict__ bv)
{
    extern __shared__ char smc[];
    unsigned sA  = smem_u32(smc);
    unsigned sBh = sA + 2 * TILE_A64;
    unsigned sBl = sBh + TILE_B128;

    int gru = blockIdx.y;
    int m0  = blockIdx.x * 64;

    const float* X = (gru == 0) ? Xq : (gru == 1) ? Xk : Xv;
    const float* bias = (gru == 0) ? bq : (gru == 1) ? bk : bv;
    float* C = g_xw + (size_t)gru * MTOT * G3;

    load_b_tiles(sBh, gru * 3);
    convert_rows(X, 128, m0, 64, (uint32_t*)smc, (uint32_t*)(smc + TILE_A64), 256);

    for (int nt = 0; nt < 3; nt++) {
        cp_commit(); cp_wait0();
        __syncthreads();
        mma_tile_64(sA, sBh, sBl, m0, nt * 128, bias, C, G3);
        __syncthreads();
        if (nt < 2) load_b_tiles(sBh, gru * 3 + nt + 1);
    }
}

// output projection: A tiles preconverted by attention (g_ab) -> pure cp.async + mma
__global__ void __launch_bounds__(256, 2)
gemm_out(const float* __restrict__ bout, float* __restrict__ out)
{
    extern __shared__ char smc[];
    unsigned sA  = smem_u32(smc);
    unsigned sBh = sA + 2 * TILE_A64;
    unsigned sBl = sBh + TILE_B128;
    int tile = blockIdx.x;
    int m0 = tile * 64;
    int tid = threadIdx.x;

    // A: 2176 x 16B chunks (hi then lo contiguous)
    const char* asrc = (const char*)g_ab[tile][0];
#pragma unroll
    for (int i = 0; i < 9; i++) {
        int u = tid + i * 256;
        if (u < 2176) cp_async16(sA + u * 16, asrc + (size_t)u * 16);
    }
    load_b_tiles(sBh, 9);
    cp_commit(); cp_wait0();
    __syncthreads();
    mma_tile_64(sA, sBh, sBl, m0, 0, bout, out, 128);
}

// ========================================================================
// GRU scan v12 (unchanged from R12)
// ========================================================================
#define SC_HH    104448
#define SC_HL    106624
#define SC_HS    108800
#define SC_RS    113152
#define SC_ZS    117376
#define SC_GN    121600
#define SC_XW    125824
#define SC_SMEM  150656
#define XW_STG   (8 * 388)

__global__ void __launch_bounds__(384, 1)
gru_scan_tc(const float* __restrict__ Whh_q, const float* __restrict__ Whh_k,
            const float* __restrict__ Whh_v,
            const float* __restrict__ bhh_q, const float* __restrict__ bhh_k,
            const float* __restrict__ bhh_v)
{
    extern __shared__ char smc[];
    __nv_bfloat16* Wl  = (__nv_bfloat16*)smc;
    __nv_bfloat16* HHb = (__nv_bfloat16*)(smc + SC_HH);
    __nv_bfloat16* HLb = (__nv_bfloat16*)(smc + SC_HL);
    float*         Hs   = (float*)(smc + SC_HS);
    float*         r_s  = (float*)(smc + SC_RS);
    float*         z_s  = (float*)(smc + SC_ZS);
    float*         gn_s = (float*)(smc + SC_GN);
    float*         xw_s = (float*)(smc + SC_XW);

    unsigned sWl = smem_u32(smc);
    unsigned sHH = smem_u32(smc + SC_HH);
    unsigned sHL = smem_u32(smc + SC_HL);
    unsigned sXW = smem_u32(smc + SC_XW);

    int gru = blockIdx.x / 48;
    int bb  = blockIdx.x % 48;
    int i0  = bb * 8;

    const float* Whh = (gru == 0) ? Whh_q : (gru == 1) ? Whh_k : Whh_v;
    const float* bhh = (gru == 0) ? bhh_q : (gru == 1) ? bhh_k : bhh_v;

    int tid = threadIdx.x;
    int wid = tid >> 5;
    int lane = tid & 31;
    int gatew = wid >> 2;

    for (int idx = tid; idx < G3 * DD; idx += 384) {
        int g = idx >> 7, k = idx & 127;
        float w = Whh[idx];
        float wh = __bfloat162float(__float2bfloat16(w));
        Wl[g * 136 + k] = __float2bfloat16(w - wh);
    }
    for (int idx = tid; idx < 8 * 136; idx += 384) {
        HHb[idx] = __float2bfloat16(0.f);
        HLb[idx] = __float2bfloat16(0.f);
        Hs[idx] = 0.f;
    }

    uint32_t wh[2][8][4];
    {
        const float2* W2 = (const float2*)Whh;
        int rb = wid * 32 + (lane >> 2);
#pragma unroll
        for (int mt = 0; mt < 2; mt++) {
            int r0 = rb + mt * 16;
#pragma unroll
            for (int kt = 0; kt < 8; kt++) {
                int c = kt * 16 + (lane & 3) * 2;
                float2 w00 = W2[(r0 * 128 + c) >> 1];
                float2 w10 = W2[((r0 + 8) * 128 + c) >> 1];
                float2 w01 = W2[(r0 * 128 + c + 8) >> 1];
                float2 w11 = W2[((r0 + 8) * 128 + c + 8) >> 1];
                wh[mt][kt][0] = bf16x2_pack(w00.x, w00.y);
                wh[mt][kt][1] = bf16x2_pack(w10.x, w10.y);
                wh[mt][kt][2] = bf16x2_pack(w01.x, w01.y);
                wh[mt][kt][3] = bf16x2_pack(w11.x, w11.y);
            }
        }
    }

    float bhh_r[4];
#pragma unroll
    for (int k = 0; k < 4; k++) bhh_r[k] = bhh[wid * 32 + (lane >> 2) + 8 * k];

    unsigned aW[2];
#pragma unroll
    for (int mt = 0; mt < 2; mt++)
        aW[mt] = sWl + (wid * 32 + mt * 16 + (lane & 15)) * 272 + ((lane >> 4) << 4);
    unsigned bO = (lane & 7) * 272 + (((lane >> 3) & 1) << 4) + ((lane >> 4) << 5);

    const size_t xwbase = (size_t)(gru * BATCH + i0) * NN * G3;
    const size_t bstride = (size_t)NN * G3;

    {
#pragma unroll
        for (int w2 = 0; w2 < 2; w2++) {
            int c = tid + w2 * 384;
            int b = c / 96, q = c % 96;
            cp_async16(sXW + b * 1552 + q * 16,
                       g_xw + xwbase + (size_t)b * bstride + q * 4);
        }
        cp_commit(); cp_wait0();
    }
    __syncthreads();

    for (int j = 0; j < NN; j++) {
        bool has_next = (j + 1 < NN);
        if (has_next) {
            unsigned dst = sXW + ((j + 1) & 1) * (XW_STG * 4);
#pragma unroll
            for (int w2 = 0; w2 < 2; w2++) {
                int c = tid + w2 * 384;
                int b = c / 96, q = c % 96;
                cp_async16(dst + b * 1552 + q * 16,
                           g_xw + xwbase + (size_t)b * bstride + (size_t)(j + 1) * G3 + q * 4);
            }
            cp_commit();
        }

        uint32_t bh[8][2], bl[8][2];
#pragma unroll
        for (int kp = 0; kp < 4; kp++) {
            uint32_t r[4];
            ldsm4(r, sHH + bO + kp * 64);
            bh[2 * kp][0] = r[0]; bh[2 * kp][1] = r[1];
            bh[2 * kp + 1][0] = r[2]; bh[2 * kp + 1][1] = r[3];
            ldsm4(r, sHL + bO + kp * 64);
            bl[2 * kp][0] = r[0]; bl[2 * kp][1] = r[1];
            bl[2 * kp + 1][0] = r[2]; bl[2 * kp + 1][1] = r[3];
        }

        float cP[2][4], cQ[2][4];
#pragma unroll
        for (int mt = 0; mt < 2; mt++)
#pragma unroll
            for (int i = 0; i < 4; i++) { cP[mt][i] = 0.f; cQ[mt][i] = 0.f; }

#pragma unroll
        for (int kt = 0; kt < 8; kt++) {
            mma_bf16(cP[0], wh[0][kt], bh[kt]);
            mma_bf16(cP[1], wh[1][kt], bh[kt]);
            mma_bf16(cQ[0], wh[0][kt], bl[kt]);
            mma_bf16(cQ[1], wh[1][kt], bl[kt]);
        }
#pragma unroll
        for (int mt = 0; mt < 2; mt++) {
#pragma unroll
            for (int kt = 0; kt < 8; kt++) {
                uint32_t wl[4];
                ldsm4(wl, aW[mt] + kt * 32);
                mma_bf16((kt & 1) ? cQ[mt] : cP[mt], wl, bh[kt]);
            }
        }

        const float* xwc = xw_s + (j & 1) * XW_STG;
        int b0 = 2 * (lane & 3);
#pragma unroll
        for (int mt = 0; mt < 2; mt++) {
            int gg = wid * 32 + mt * 16 + (lane >> 2);
            int e  = gg & 127;
            float s0 = cP[mt][0] + cQ[mt][0];
            float s1 = cP[mt][1] + cQ[mt][1];
            float s2 = cP[mt][2] + cQ[mt][2];
            float s3 = cP[mt][3] + cQ[mt][3];
            if (gatew < 2) {
                float* dst = (gatew == 0) ? r_s : z_s;
                float p00 = xwc[b0 * 388 + gg]           + s0 + bhh_r[2 * mt];
                float p01 = xwc[(b0 + 1) * 388 + gg]     + s1 + bhh_r[2 * mt];
                float p10 = xwc[b0 * 388 + gg + 8]       + s2 + bhh_r[2 * mt + 1];
                float p11 = xwc[(b0 + 1) * 388 + gg + 8] + s3 + bhh_r[2 * mt + 1];
                dst[b0 * 132 + e]           = sigmoidf_(p00);
                dst[(b0 + 1) * 132 + e]     = sigmoidf_(p01);
                dst[b0 * 132 + e + 8]       = sigmoidf_(p10);
                dst[(b0 + 1) * 132 + e + 8] = sigmoidf_(p11);
            } else {
                gn_s[b0 * 132 + e]           = s0 + bhh_r[2 * mt];
                gn_s[(b0 + 1) * 132 + e]     = s1 + bhh_r[2 * mt];
                gn_s[b0 * 132 + e + 8]       = s2 + bhh_r[2 * mt + 1];
                gn_s[(b0 + 1) * 132 + e + 8] = s3 + bhh_r[2 * mt + 1];
            }
        }

        cp_wait0();
        __syncthreads();

        const size_t ybase = ((size_t)(gru * BATCH + i0) * NN + j) * DD;
#pragma unroll
        for (int pp = 0; pp < 3; pp++) {
            int p = tid + pp * 384;
            if (p < 1024) {
                int b = p >> 7, e2 = p & 127;
                float r   = r_s[b * 132 + e2];
                float z   = z_s[b * 132 + e2];
                float ghn = gn_s[b * 132 + e2];
                float xn  = xwc[b * 388 + 256 + e2];
                float hp  = Hs[b * 136 + e2];
                float nn = tanhf_(xn + r * ghn);
                float hnew = (1.f - z) * nn + z * hp;
                Hs[b * 136 + e2] = hnew;
                float hhv = __bfloat162float(__float2bfloat16(hnew));
                HHb[b * 136 + e2] = __float2bfloat16(hnew);
                HLb[b * 136 + e2] = __float2bfloat16(hnew - hhv);
                g_ys[ybase + (size_t)b * (NN * DD) + e2] = hnew;
            }
        }
        __syncthreads();
    }
}

// ========================================================================
// Attention v13: one (b,n) pair per 192-thread block (lane-pair head split),
// output written directly as bf16 hi/lo tiles for gemm_out.
// ========================================================================
__global__ void __launch_bounds__(192)
attn_kernel(const float* __restrict__ rel)
{
    __shared__ float ks[TT * DD];
    __shared__ float vs[TT * DD];

    int b = blockIdx.x / NN;
    int n = blockIdx.x % NN;
    int tid = threadIdx.x;
    const size_t GS = (size_t)MTOT * DD;

    for (int u = tid; u < TT * DD / 4; u += 192) {
        int s = u >> 5, c4 = u & 31;
        size_t base = ((size_t)(b * TT + s) * NN + n) * DD + c4 * 4;
        ((float4*)ks)[u] = *(const float4*)(g_ys + GS + base);
        ((float4*)vs)[u] = *(const float4*)(g_ys + 2 * GS + base);
    }
    __syncthreads();

    int half = tid & 1;
    int k  = tid >> 1;          // 0..95
    int h = k / TT, t = k % TT;
    int d0 = h * HD + half * 8;

    float q[8];
    size_t qb = ((size_t)(b * TT + t) * NN + n) * DD + d0;
    ((float4*)q)[0] = *(const float4*)(g_ys + qb);
    ((float4*)q)[1] = *(const float4*)(g_ys + qb + 4);

    int hbias = (5 * b + n) & 7;
    const float* rp = rel + hbias * TT * TT + t * TT;

    float srow[TT];
#pragma unroll
    for (int s = 0; s < TT; s++) {
        float a = 0.f;
#pragma unroll
        for (int d = 0; d < 8; d++) a += q[d] * ks[s * DD + d0 + d];
        float full = a + __shfl_xor_sync(0xffffffffu, a, 1);
        srow[s] = full * 0.25f + __ldg(&rp[s]);
    }

    float m = srow[0];
#pragma unroll
    for (int s = 1; s < TT; s++) m = fmaxf(m, srow[s]);
    float sum = 0.f;
#pragma unroll
    for (int s = 0; s < TT; s++) { srow[s] = __expf(srow[s] - m); sum += srow[s]; }
    float inv = __fdividef(1.f, sum);

    float o[8];
#pragma unroll
    for (int d = 0; d < 8; d++) o[d] = 0.f;
#pragma unroll
    for (int s = 0; s < TT; s++) {
        float p = srow[s] * inv;
#pragma unroll
        for (int d = 0; d < 8; d++) o[d] += p * vs[s * DD + d0 + d];
    }

    // write bf16 hi/lo tile pair directly (gemm_out's A layout)
    int mrow = (b * NN + n) * TT + t;
    int tile = mrow >> 6;
    int r = mrow & 63;
    uint32_t hi4[4], lo4[4];
#pragma unroll
    for (int i = 0; i < 4; i++) {
        float h0 = __bfloat162float(__float2bfloat16(o[2 * i]));
        float h1 = __bfloat162float(__float2bfloat16(o[2 * i + 1]));
        hi4[i] = bf16x2_pack(h0, h1);
        lo4[i] = bf16x2_pack(o[2 * i] - h0, o[2 * i + 1] - h1);
    }
    int off = r * 136 + d0;   // elements
    *(uint4*)((char*)g_ab[tile][0] + off * 2) = make_uint4(hi4[0], hi4[1], hi4[2], hi4[3]);
    *(uint4*)((char*)g_ab[tile][1] + off * 2) = make_uint4(lo4[0], lo4[1], lo4[2], lo4[3]);
}

// ========================================================================
extern "C" void kernel_launch(void* const* d_in, const int* in_sizes, int n_in,
                              void* d_out, int out_size)
{
    const float* query = (const float*)d_in[0];
    const float* key   = (const float*)d_in[1];
    const float* value = (const float*)d_in[2];
    const float* Wih_q = (const float*)d_in[3];
    const float* Whh_q = (const float*)d_in[4];
    const float* bih_q = (const float*)d_in[5];
    const float* bhh_q = (const float*)d_in[6];
    const float* Wih_k = (const float*)d_in[7];
    const float* Whh_k = (const float*)d_in[8];
    const float* bih_k = (const float*)d_in[9];
    const float* bhh_k = (const float*)d_in[10];
    const float* Wih_v = (const float*)d_in[11];
    const float* Whh_v = (const float*)d_in[12];
    const float* bih_v = (const float*)d_in[13];
    const float* bhh_v = (const float*)d_in[14];
    const float* rel   = (const float*)d_in[15];
    const float* Wout  = (const float*)d_in[16];
    const float* bout  = (const float*)d_in[17];

    cudaFuncSetAttribute(gemm_in,     cudaFuncAttributeMaxDynamicSharedMemorySize, G64_SMEM);
    cudaFuncSetAttribute(gemm_out,    cudaFuncAttributeMaxDynamicSharedMemorySize, G64_SMEM);
    cudaFuncSetAttribute(gru_scan_tc, cudaFuncAttributeMaxDynamicSharedMemorySize, SC_SMEM);

    // 0) preconvert all weight matrices
    preconv_w<<<10, 256>>>(Wih_q, Wih_k, Wih_v, Wout);

    // 1) input projections
    gemm_in<<<dim3(MTOT / 64, 3), 256, G64_SMEM>>>(query, key, value,
                                                   bih_q, bih_k, bih_v);

    // 2) GRU scans
    gru_scan_tc<<<144, 384, SC_SMEM>>>(Whh_q, Whh_k, Whh_v, bhh_q, bhh_k, bhh_v);

    // 3) attentions (one pair per 192-thread block; writes bf16 tiles)
    attn_kernel<<<B32 * NN, 192>>>(rel);

    // 4) output projection (pure cp.async + mma)
    gemm_out<<<MTOT / 64, 256, G64_SMEM>>>(bout, (float*)d_out);
}